// round 4
// baseline (speedup 1.0000x reference)
#include <cuda_runtime.h>
#include <cuda_bf16.h>
#include <cstdint>

#define B_ 2
#define L_ 1024
#define BL 2048
#define HS 2048
#define NH 8
#define HD 256
#define DV 512
#define KD 2048
#define VD 4096
#define E_ 3
#define QSCALE 0.0625f

__device__ float g_qraw[BL * KD];
__device__ float g_kraw[BL * KD];
__device__ float g_vraw[BL * VD];
__device__ float g_gateraw[BL * VD];
__device__ float g_q[BL * KD];
__device__ float g_k[BL * KD];
__device__ float g_v[BL * VD];
__device__ float g_ke[E_ * BL * KD];
__device__ float g_ba[BL * 48];
__device__ float g_dec[L_ * E_ * B_ * NH];
__device__ float g_beta[L_ * E_ * B_ * NH];
__device__ float g_o[BL * VD];
__device__ float g_of[BL * VD];

__device__ __forceinline__ float2 ffma2(float2 a, float2 b, float2 c) {
    unsigned long long au = *reinterpret_cast<unsigned long long*>(&a);
    unsigned long long bu = *reinterpret_cast<unsigned long long*>(&b);
    unsigned long long cu = *reinterpret_cast<unsigned long long*>(&c);
    unsigned long long du;
    asm("fma.rn.f32x2 %0, %1, %2, %3;" : "=l"(du) : "l"(au), "l"(bu), "l"(cu));
    return *reinterpret_cast<float2*>(&du);
}

__device__ __forceinline__ float blockReduceSum256(float v, float* red) {
    int tid = threadIdx.x;
    #pragma unroll
    for (int off = 16; off; off >>= 1) v += __shfl_xor_sync(0xffffffffu, v, off);
    if ((tid & 31) == 0) red[tid >> 5] = v;
    __syncthreads();
    return red[0] + red[1] + red[2] + red[3] + red[4] + red[5] + red[6] + red[7];
}

// C[m,n] += A[m,k]*B[n,k], 128x128 tile, K%16==0
__device__ __forceinline__ void gemm128_body(const float* __restrict__ A, int lda,
                                             const float* __restrict__ B, int ldb,
                                             float* __restrict__ C, int ldc, int K) {
    __shared__ float As[16][132];
    __shared__ float Bs[16][132];
    int tid = threadIdx.x;
    int tn8 = (tid & 15) * 8, tm8 = (tid >> 4) * 8;
    float2 acc[8][4];
    #pragma unroll
    for (int i = 0; i < 8; i++)
        #pragma unroll
        for (int j = 0; j < 4; j++) acc[i][j] = make_float2(0.f, 0.f);
    for (int k0 = 0; k0 < K; k0 += 16) {
        if (k0) __syncthreads();
        #pragma unroll
        for (int it = 0; it < 2; it++) {
            int qq = tid + it * 256;
            int r = qq >> 2, c4 = (qq & 3) * 4;
            float4 av = *reinterpret_cast<const float4*>(A + (size_t)r * lda + k0 + c4);
            As[c4][r] = av.x; As[c4 + 1][r] = av.y; As[c4 + 2][r] = av.z; As[c4 + 3][r] = av.w;
            float4 bv = *reinterpret_cast<const float4*>(B + (size_t)r * ldb + k0 + c4);
            Bs[c4][r] = bv.x; Bs[c4 + 1][r] = bv.y; Bs[c4 + 2][r] = bv.z; Bs[c4 + 3][r] = bv.w;
        }
        __syncthreads();
        #pragma unroll
        for (int kk = 0; kk < 16; kk++) {
            float4 a0 = *reinterpret_cast<const float4*>(&As[kk][tm8]);
            float4 a1 = *reinterpret_cast<const float4*>(&As[kk][tm8 + 4]);
            float4 b0 = *reinterpret_cast<const float4*>(&Bs[kk][tn8]);
            float4 b1 = *reinterpret_cast<const float4*>(&Bs[kk][tn8 + 4]);
            float2 bb[4] = { {b0.x,b0.y},{b0.z,b0.w},{b1.x,b1.y},{b1.z,b1.w} };
            float ar[8] = { a0.x,a0.y,a0.z,a0.w,a1.x,a1.y,a1.z,a1.w };
            #pragma unroll
            for (int i = 0; i < 8; i++) {
                float2 ad = make_float2(ar[i], ar[i]);
                #pragma unroll
                for (int j = 0; j < 4; j++) acc[i][j] = ffma2(ad, bb[j], acc[i][j]);
            }
        }
    }
    #pragma unroll
    for (int i = 0; i < 8; i++) {
        float* cp = C + (size_t)(tm8 + i) * ldc + tn8;
        *reinterpret_cast<float4*>(cp)     = make_float4(acc[i][0].x, acc[i][0].y, acc[i][1].x, acc[i][1].y);
        *reinterpret_cast<float4*>(cp + 4) = make_float4(acc[i][2].x, acc[i][2].y, acc[i][3].x, acc[i][3].y);
    }
}

__global__ __launch_bounds__(256) void gemm_nt(const float* __restrict__ A,
                                               const float* __restrict__ B,
                                               float* __restrict__ C,
                                               int K, int lda, int ldb, int ldc) {
    gemm128_body(A + (size_t)blockIdx.y * 128 * lda, lda,
                 B + (size_t)blockIdx.x * 128 * ldb, ldb,
                 C + (size_t)blockIdx.y * 128 * ldc + blockIdx.x * 128, ldc, K);
}

__global__ __launch_bounds__(256) void ke_gemm(const float* __restrict__ Kn,
                                               const float* __restrict__ Wek,
                                               float* __restrict__ KeOut) {
    int z = blockIdx.z, e = z >> 3, h = z & 7;
    int n0 = blockIdx.x * 128, m0 = blockIdx.y * 128;
    gemm128_body(Kn + (size_t)m0 * KD + h * HD, KD,
                 Wek + (size_t)z * HD * HD + (size_t)n0 * HD, HD,
                 KeOut + (size_t)e * BL * KD + (size_t)m0 * KD + h * HD + n0, KD, HD);
}

// ba[row, j] : j<24 -> x@Wb[j], j>=24 -> x@Wa[j-24].  Tile M=64, N=48.
__global__ __launch_bounds__(256) void ba_gemm(const float* __restrict__ x,
                                               const float* __restrict__ Wb,
                                               const float* __restrict__ Wa,
                                               float* __restrict__ ba) {
    __shared__ float xs[64][17];
    __shared__ float ws[48][17];
    int tid = threadIdx.x;
    int m0 = blockIdx.x * 64;
    int tm = tid >> 4, tn = tid & 15;   // tm: 4 rows, tn: 3 cols
    float acc[4][3] = {};
    for (int k0 = 0; k0 < HS; k0 += 16) {
        if (k0) __syncthreads();
        #pragma unroll
        for (int it = 0; it < 4; it++) {
            int qq = tid + it * 256;    // 0..1023
            int r = qq >> 4, c = qq & 15;
            xs[r][c] = x[(size_t)(m0 + r) * HS + k0 + c];
            if (qq < 768) {
                int jr = qq >> 4;       // reuse decomposition for 48x16
                int jc = qq & 15;
                const float* W = (jr < 24) ? (Wb + (size_t)jr * HS) : (Wa + (size_t)(jr - 24) * HS);
                ws[jr][jc] = W[k0 + jc];
            }
        }
        __syncthreads();
        #pragma unroll
        for (int kk = 0; kk < 16; kk++) {
            float xv[4], wv[3];
            #pragma unroll
            for (int i = 0; i < 4; i++) xv[i] = xs[tm * 4 + i][kk];
            #pragma unroll
            for (int j = 0; j < 3; j++) wv[j] = ws[tn * 3 + j][kk];
            #pragma unroll
            for (int i = 0; i < 4; i++)
                #pragma unroll
                for (int j = 0; j < 3; j++) acc[i][j] += xv[i] * wv[j];
        }
    }
    #pragma unroll
    for (int i = 0; i < 4; i++)
        #pragma unroll
        for (int j = 0; j < 3; j++)
            ba[(size_t)(m0 + tm * 4 + i) * 48 + tn * 3 + j] = acc[i][j];
}

__global__ __launch_bounds__(256) void conv_norm_qk(const float* __restrict__ raw,
                                                    const float* __restrict__ cw,
                                                    float* __restrict__ out, float scale) {
    __shared__ float red[8];
    int row = blockIdx.x, h = blockIdx.y, l = row & (L_ - 1);
    int cg = h * HD + threadIdx.x;
    const float* w = cw + (size_t)cg * 4;
    float y = w[3] * raw[(size_t)row * KD + cg];
    if (l >= 1) y += w[2] * raw[(size_t)(row - 1) * KD + cg];
    if (l >= 2) y += w[1] * raw[(size_t)(row - 2) * KD + cg];
    if (l >= 3) y += w[0] * raw[(size_t)(row - 3) * KD + cg];
    y = y / (1.f + expf(-y));
    float tot = blockReduceSum256(y * y, red);
    out[(size_t)row * KD + cg] = y * rsqrtf(tot + 1e-6f) * scale;
}

__global__ __launch_bounds__(256) void conv_v_k(const float* __restrict__ raw,
                                                const float* __restrict__ cw,
                                                float* __restrict__ out) {
    int idx = blockIdx.x * 256 + threadIdx.x;
    int row = idx >> 12, c = idx & 4095, l = row & (L_ - 1);
    const float* w = cw + (size_t)c * 4;
    float y = w[3] * raw[idx];
    if (l >= 1) y += w[2] * raw[idx - VD];
    if (l >= 2) y += w[1] * raw[idx - 2 * VD];
    if (l >= 3) y += w[0] * raw[idx - 3 * VD];
    out[idx] = y / (1.f + expf(-y));
}

__global__ __launch_bounds__(256) void gating_k(const float* __restrict__ ba,
                                                const float* __restrict__ A_log,
                                                const float* __restrict__ dt_bias,
                                                const int* __restrict__ modality,
                                                float* __restrict__ decA,
                                                float* __restrict__ betaA) {
    int idx = blockIdx.x * 256 + threadIdx.x;
    if (idx >= L_ * E_ * B_ * NH) return;
    int h = idx & 7, b = (idx >> 3) & 1, e = (idx >> 4) % 3, t = idx / 48;
    int j = e * NH + h, row = b * L_ + t;
    float av = ba[row * 48 + 24 + j] + dt_bias[j];
    float sp = (av > 20.f) ? av : log1pf(expf(av));
    float gg = -expf(A_log[j]) * sp;
    float beta = 1.f / (1.f + expf(-ba[row * 48 + j]));
    int mod = modality[row];
    int m = (e == 0) ? 1 : ((e == 1) ? (mod == 0) : (mod == 1));
    decA[idx] = m ? expf(gg) : 1.f;
    betaA[idx] = m ? beta : 0.f;
}

struct SBuf { float ke[3][256]; float q[256]; float v[64]; float dec[3]; float beta[3]; float pad[2]; };

__global__ __launch_bounds__(256, 1) void scan_k(const float* __restrict__ keS,
                                                 const float* __restrict__ qn,
                                                 const float* __restrict__ vn,
                                                 const float* __restrict__ decA,
                                                 const float* __restrict__ betaA,
                                                 const float* __restrict__ OW,
                                                 float* __restrict__ oB) {
    __shared__ SBuf sb[2];
    __shared__ float wout[3];
    int bx = blockIdx.x, vt = bx & 7, h = (bx >> 3) & 7, b = bx >> 6;
    int tid = threadIdx.x, w = tid >> 5, lane = tid & 31;
    int g = lane >> 3, r = lane & 7;
    int colBase = vt * 64 + w * 8 + g * 2;
    if (tid == 0) {
        float w0 = OW[h], w1 = OW[8 + h], w2 = OW[16 + h];
        float mx = fmaxf(w0, fmaxf(w1, w2));
        float e0 = expf(w0 - mx), e1 = expf(w1 - mx), e2 = expf(w2 - mx);
        float s = 1.f / (e0 + e1 + e2);
        wout[0] = e0 * s; wout[1] = e1 * s; wout[2] = e2 * s;
    }
    float S[3][32][2];
    #pragma unroll
    for (int e = 0; e < 3; e++)
        #pragma unroll
        for (int j = 0; j < 32; j++) { S[e][j][0] = 0.f; S[e][j][1] = 0.f; }

    for (int t = 0; t < L_; t++) {
        SBuf& sbuf = sb[t & 1];
        int row = b * L_ + t;
        size_t qoff = (size_t)row * KD + h * HD;
        #pragma unroll
        for (int i = 0; i < 3; i++)
            sbuf.ke[i][tid] = keS[(size_t)i * BL * KD + qoff + tid];
        sbuf.q[tid] = qn[qoff + tid];
        if (tid < 64) sbuf.v[tid] = vn[(size_t)row * VD + h * DV + vt * 64 + tid];
        if (tid < 3) sbuf.dec[tid] = decA[((t * 3 + tid) * 2 + b) * 8 + h];
        else if (tid < 6) sbuf.beta[tid - 3] = betaA[((t * 3 + (tid - 3)) * 2 + b) * 8 + h];
        __syncthreads();

        float vv0 = sbuf.v[w * 8 + g * 2];
        float vv1 = sbuf.v[w * 8 + g * 2 + 1];
        float o0 = 0.f, o1 = 0.f;
        #pragma unroll
        for (int e = 0; e < 3; e++) {
            float dec = sbuf.dec[e], bb = sbuf.beta[e], wo = wout[e];
            if (bb != 0.f) {
                float kS0 = 0, kS1 = 0, qS0 = 0, qS1 = 0, qk = 0;
                #pragma unroll
                for (int jj = 0; jj < 8; jj++) {
                    float4 k4 = *reinterpret_cast<const float4*>(&sbuf.ke[e][r * 32 + jj * 4]);
                    float4 q4 = *reinterpret_cast<const float4*>(&sbuf.q[r * 32 + jj * 4]);
                    float kk_[4] = { k4.x,k4.y,k4.z,k4.w };
                    float qq_[4] = { q4.x,q4.y,q4.z,q4.w };
                    #pragma unroll
                    for (int u = 0; u < 4; u++) {
                        int j = jj * 4 + u;
                        qk  += qq_[u] * kk_[u];
                        kS0 += kk_[u] * S[e][j][0];
                        kS1 += kk_[u] * S[e][j][1];
                        qS0 += qq_[u] * S[e][j][0];
                        qS1 += qq_[u] * S[e][j][1];
                    }
                }
                #pragma unroll
                for (int off = 4; off; off >>= 1) {
                    kS0 += __shfl_xor_sync(0xffffffffu, kS0, off);
                    kS1 += __shfl_xor_sync(0xffffffffu, kS1, off);
                    qS0 += __shfl_xor_sync(0xffffffffu, qS0, off);
                    qS1 += __shfl_xor_sync(0xffffffffu, qS1, off);
                    qk  += __shfl_xor_sync(0xffffffffu, qk,  off);
                }
                float d0 = (vv0 - dec * kS0) * bb;
                float d1 = (vv1 - dec * kS1) * bb;
                #pragma unroll
                for (int jj = 0; jj < 8; jj++) {
                    float4 k4 = *reinterpret_cast<const float4*>(&sbuf.ke[e][r * 32 + jj * 4]);
                    float kk_[4] = { k4.x,k4.y,k4.z,k4.w };
                    #pragma unroll
                    for (int u = 0; u < 4; u++) {
                        int j = jj * 4 + u;
                        S[e][j][0] = dec * S[e][j][0] + kk_[u] * d0;
                        S[e][j][1] = dec * S[e][j][1] + kk_[u] * d1;
                    }
                }
                o0 += wo * (dec * qS0 + qk * d0);
                o1 += wo * (dec * qS1 + qk * d1);
            } else {
                float qS0 = 0, qS1 = 0;
                #pragma unroll
                for (int jj = 0; jj < 8; jj++) {
                    float4 q4 = *reinterpret_cast<const float4*>(&sbuf.q[r * 32 + jj * 4]);
                    float qq_[4] = { q4.x,q4.y,q4.z,q4.w };
                    #pragma unroll
                    for (int u = 0; u < 4; u++) {
                        int j = jj * 4 + u;
                        qS0 += qq_[u] * S[e][j][0];
                        qS1 += qq_[u] * S[e][j][1];
                    }
                }
                #pragma unroll
                for (int off = 4; off; off >>= 1) {
                    qS0 += __shfl_xor_sync(0xffffffffu, qS0, off);
                    qS1 += __shfl_xor_sync(0xffffffffu, qS1, off);
                }
                o0 += wo * qS0;
                o1 += wo * qS1;
            }
        }
        if (r == 0)
            *reinterpret_cast<float2*>(&oB[(size_t)row * VD + h * DV + colBase]) = make_float2(o0, o1);
    }
}

__global__ __launch_bounds__(256) void normgate_k(const float* __restrict__ oB,
                                                  const float* __restrict__ gateRaw,
                                                  const float* __restrict__ onw,
                                                  float* __restrict__ oF) {
    __shared__ float red[8];
    int row = blockIdx.x >> 3, h = blockIdx.x & 7, tid = threadIdx.x;
    size_t base = (size_t)row * VD + h * DV;
    float x0 = oB[base + tid], x1 = oB[base + tid + 256];
    float tot = blockReduceSum256(x0 * x0 + x1 * x1, red);
    float rn = rsqrtf(tot * (1.f / 512.f) + 1e-5f);
    float g0 = gateRaw[base + tid];
    float g1 = gateRaw[base + tid + 256];
    oF[base + tid]       = x0 * rn * onw[tid]       * (g0 / (1.f + expf(-g0)));
    oF[base + tid + 256] = x1 * rn * onw[tid + 256] * (g1 / (1.f + expf(-g1)));
}

extern "C" void kernel_launch(void* const* d_in, const int* in_sizes, int n_in,
                              void* d_out, int out_size) {
    const float *x, *Wq, *Wk, *Wv, *cq, *ck, *cv, *Wek, *Wb, *Wa, *Alog, *dtb, *ow, *Wg, *onw, *Wo;
    const int* mod;
    if (in_sizes[1] == 2048) { // dict order: modality_ids second
        x = (const float*)d_in[0];  mod = (const int*)d_in[1];
        Wq = (const float*)d_in[2]; Wk = (const float*)d_in[3];
        Wv = (const float*)d_in[4]; cq = (const float*)d_in[5];
        ck = (const float*)d_in[6]; cv = (const float*)d_in[7];
        Wek = (const float*)d_in[8]; Wb = (const float*)d_in[9];
        Wa = (const float*)d_in[10]; Alog = (const float*)d_in[11];
        dtb = (const float*)d_in[12]; ow = (const float*)d_in[13];
        Wg = (const float*)d_in[14]; onw = (const float*)d_in[15];
        Wo = (const float*)d_in[16];
    } else {                   // signature order: modality_ids last
        x = (const float*)d_in[0];  Wq = (const float*)d_in[1];
        Wk = (const float*)d_in[2]; Wv = (const float*)d_in[3];
        cq = (const float*)d_in[4]; ck = (const float*)d_in[5];
        cv = (const float*)d_in[6]; Wek = (const float*)d_in[7];
        Wb = (const float*)d_in[8]; Wa = (const float*)d_in[9];
        Alog = (const float*)d_in[10]; dtb = (const float*)d_in[11];
        ow = (const float*)d_in[12]; Wg = (const float*)d_in[13];
        onw = (const float*)d_in[14]; Wo = (const float*)d_in[15];
        mod = (const int*)d_in[16];
    }

    float *qraw, *kraw, *vraw, *gateraw, *q, *k, *v, *ke, *ba, *dec, *beta, *o, *of;
    cudaGetSymbolAddress((void**)&qraw, g_qraw);
    cudaGetSymbolAddress((void**)&kraw, g_kraw);
    cudaGetSymbolAddress((void**)&vraw, g_vraw);
    cudaGetSymbolAddress((void**)&gateraw, g_gateraw);
    cudaGetSymbolAddress((void**)&q, g_q);
    cudaGetSymbolAddress((void**)&k, g_k);
    cudaGetSymbolAddress((void**)&v, g_v);
    cudaGetSymbolAddress((void**)&ke, g_ke);
    cudaGetSymbolAddress((void**)&ba, g_ba);
    cudaGetSymbolAddress((void**)&dec, g_dec);
    cudaGetSymbolAddress((void**)&beta, g_beta);
    cudaGetSymbolAddress((void**)&o, g_o);
    cudaGetSymbolAddress((void**)&of, g_of);

    gemm_nt<<<dim3(16, 16), 256>>>(x, Wq, qraw, HS, HS, HS, KD);
    gemm_nt<<<dim3(16, 16), 256>>>(x, Wk, kraw, HS, HS, HS, KD);
    gemm_nt<<<dim3(32, 16), 256>>>(x, Wv, vraw, HS, HS, HS, VD);
    gemm_nt<<<dim3(32, 16), 256>>>(x, Wg, gateraw, HS, HS, HS, VD);
    ba_gemm<<<32, 256>>>(x, Wb, Wa, ba);

    conv_norm_qk<<<dim3(BL, NH), 256>>>(qraw, cq, q, QSCALE);
    conv_norm_qk<<<dim3(BL, NH), 256>>>(kraw, ck, k, 1.0f);
    conv_v_k<<<(BL * VD) / 256, 256>>>(vraw, cv, v);

    ke_gemm<<<dim3(2, 16, 24), 256>>>(k, Wek, ke);
    gating_k<<<(L_ * E_ * B_ * NH + 255) / 256, 256>>>(ba, Alog, dtb, mod, dec, beta);

    scan_k<<<128, 256>>>(ke, q, v, dec, beta, ow, o);

    normgate_k<<<BL * NH, 256>>>(o, gateraw, onw, of);
    gemm_nt<<<dim3(16, 16), 256>>>(of, Wo, (float*)d_out, VD, VD, VD, HS);
}

// round 5
// speedup vs baseline: 1.1085x; 1.1085x over previous
#include <cuda_runtime.h>
#include <cuda_bf16.h>
#include <cstdint>

#define B_ 2
#define L_ 1024
#define BL 2048
#define HS 2048
#define NH 8
#define HD 256
#define DV 512
#define KD 2048
#define VD 4096
#define E_ 3
#define QSCALE 0.0625f

__device__ float g_qraw[BL * KD];
__device__ float g_kraw[BL * KD];
__device__ float g_vraw[BL * VD];
__device__ float g_gateraw[BL * VD];
__device__ float g_q[BL * KD];
__device__ float g_k[BL * KD];
__device__ float g_v[BL * VD];
__device__ float g_ke[E_ * BL * KD];
__device__ float g_ba[BL * 48];
__device__ float g_o[BL * VD];
__device__ float g_of[BL * VD];

__device__ __forceinline__ float2 ffma2(float2 a, float2 b, float2 c) {
    unsigned long long au = *reinterpret_cast<unsigned long long*>(&a);
    unsigned long long bu = *reinterpret_cast<unsigned long long*>(&b);
    unsigned long long cu = *reinterpret_cast<unsigned long long*>(&c);
    unsigned long long du;
    asm("fma.rn.f32x2 %0, %1, %2, %3;" : "=l"(du) : "l"(au), "l"(bu), "l"(cu));
    return *reinterpret_cast<float2*>(&du);
}
__device__ __forceinline__ float2 fmul2(float2 a, float2 b) {
    unsigned long long au = *reinterpret_cast<unsigned long long*>(&a);
    unsigned long long bu = *reinterpret_cast<unsigned long long*>(&b);
    unsigned long long du;
    asm("mul.rn.f32x2 %0, %1, %2;" : "=l"(du) : "l"(au), "l"(bu));
    return *reinterpret_cast<float2*>(&du);
}

__device__ __forceinline__ float blockReduceSum256(float v, float* red) {
    int tid = threadIdx.x;
    #pragma unroll
    for (int off = 16; off; off >>= 1) v += __shfl_xor_sync(0xffffffffu, v, off);
    if ((tid & 31) == 0) red[tid >> 5] = v;
    __syncthreads();
    return red[0] + red[1] + red[2] + red[3] + red[4] + red[5] + red[6] + red[7];
}

// C[m,n] = A[m,k]*B[n,k], 128x128 tile, K%16==0.
// Warp covers 4 tm x 8 tn -> A LDS broadcast (4 distinct), B 8 distinct.
__device__ __forceinline__ void gemm128_body(const float* __restrict__ A, int lda,
                                             const float* __restrict__ B, int ldb,
                                             float* __restrict__ C, int ldc, int K) {
    __shared__ float As[16][132];
    __shared__ float Bs[16][132];
    int tid = threadIdx.x;
    int w = tid >> 5, lane = tid & 31;
    int tm8 = (((w >> 1) << 2) + (lane >> 3)) << 3;   // 0..120
    int tn8 = (((w & 1) << 3) + (lane & 7)) << 3;     // 0..120
    float2 acc[8][4];
    #pragma unroll
    for (int i = 0; i < 8; i++)
        #pragma unroll
        for (int j = 0; j < 4; j++) acc[i][j] = make_float2(0.f, 0.f);
    for (int k0 = 0; k0 < K; k0 += 16) {
        if (k0) __syncthreads();
        #pragma unroll
        for (int it = 0; it < 2; it++) {
            int qq = tid + it * 256;
            int r = qq >> 2, c4 = (qq & 3) * 4;
            float4 av = *reinterpret_cast<const float4*>(A + (size_t)r * lda + k0 + c4);
            As[c4][r] = av.x; As[c4 + 1][r] = av.y; As[c4 + 2][r] = av.z; As[c4 + 3][r] = av.w;
            float4 bv = *reinterpret_cast<const float4*>(B + (size_t)r * ldb + k0 + c4);
            Bs[c4][r] = bv.x; Bs[c4 + 1][r] = bv.y; Bs[c4 + 2][r] = bv.z; Bs[c4 + 3][r] = bv.w;
        }
        __syncthreads();
        #pragma unroll
        for (int kk = 0; kk < 16; kk++) {
            float4 a0 = *reinterpret_cast<const float4*>(&As[kk][tm8]);
            float4 a1 = *reinterpret_cast<const float4*>(&As[kk][tm8 + 4]);
            float4 b0 = *reinterpret_cast<const float4*>(&Bs[kk][tn8]);
            float4 b1 = *reinterpret_cast<const float4*>(&Bs[kk][tn8 + 4]);
            float2 bb[4] = { {b0.x,b0.y},{b0.z,b0.w},{b1.x,b1.y},{b1.z,b1.w} };
            float ar[8] = { a0.x,a0.y,a0.z,a0.w,a1.x,a1.y,a1.z,a1.w };
            #pragma unroll
            for (int i = 0; i < 8; i++) {
                float2 ad = make_float2(ar[i], ar[i]);
                #pragma unroll
                for (int j = 0; j < 4; j++) acc[i][j] = ffma2(ad, bb[j], acc[i][j]);
            }
        }
    }
    #pragma unroll
    for (int i = 0; i < 8; i++) {
        float* cp = C + (size_t)(tm8 + i) * ldc + tn8;
        *reinterpret_cast<float4*>(cp)     = make_float4(acc[i][0].x, acc[i][0].y, acc[i][1].x, acc[i][1].y);
        *reinterpret_cast<float4*>(cp + 4) = make_float4(acc[i][2].x, acc[i][2].y, acc[i][3].x, acc[i][3].y);
    }
}

// fused 4-way projection: nt 0..15 Wq, 16..31 Wk, 32..63 Wv, 64..95 Wg
__global__ __launch_bounds__(256) void proj_gemm(const float* __restrict__ x,
                                                 const float* __restrict__ Wq,
                                                 const float* __restrict__ Wk,
                                                 const float* __restrict__ Wv,
                                                 const float* __restrict__ Wg,
                                                 float* __restrict__ qraw,
                                                 float* __restrict__ kraw,
                                                 float* __restrict__ vraw,
                                                 float* __restrict__ graw) {
    int nt = blockIdx.x;
    const float* Bm; float* C; int ldc, nl;
    if (nt < 16)      { Bm = Wq; C = qraw; ldc = KD; nl = nt; }
    else if (nt < 32) { Bm = Wk; C = kraw; ldc = KD; nl = nt - 16; }
    else if (nt < 64) { Bm = Wv; C = vraw; ldc = VD; nl = nt - 32; }
    else              { Bm = Wg; C = graw; ldc = VD; nl = nt - 64; }
    gemm128_body(x + (size_t)blockIdx.y * 128 * HS, HS,
                 Bm + (size_t)nl * 128 * HS, HS,
                 C + (size_t)blockIdx.y * 128 * ldc + nl * 128, ldc, HS);
}

__global__ __launch_bounds__(256) void gemm_nt(const float* __restrict__ A,
                                               const float* __restrict__ B,
                                               float* __restrict__ C,
                                               int K, int lda, int ldb, int ldc) {
    gemm128_body(A + (size_t)blockIdx.y * 128 * lda, lda,
                 B + (size_t)blockIdx.x * 128 * ldb, ldb,
                 C + (size_t)blockIdx.y * 128 * ldc + blockIdx.x * 128, ldc, K);
}

__global__ __launch_bounds__(256) void ke_gemm(const float* __restrict__ Kn,
                                               const float* __restrict__ Wek,
                                               float* __restrict__ KeOut) {
    int z = blockIdx.z, e = z >> 3, h = z & 7;
    int n0 = blockIdx.x * 128, m0 = blockIdx.y * 128;
    gemm128_body(Kn + (size_t)m0 * KD + h * HD, KD,
                 Wek + (size_t)z * HD * HD + (size_t)n0 * HD, HD,
                 KeOut + (size_t)e * BL * KD + (size_t)m0 * KD + h * HD + n0, KD, HD);
}

// ba[row, j] : j<24 -> x@Wb[j], j>=24 -> x@Wa[j-24]
__global__ __launch_bounds__(256) void ba_gemm(const float* __restrict__ x,
                                               const float* __restrict__ Wb,
                                               const float* __restrict__ Wa,
                                               float* __restrict__ ba) {
    __shared__ float xs[64][17];
    __shared__ float ws[48][17];
    int tid = threadIdx.x;
    int m0 = blockIdx.x * 64;
    int tm = tid >> 4, tn = tid & 15;
    float acc[4][3] = {};
    for (int k0 = 0; k0 < HS; k0 += 16) {
        if (k0) __syncthreads();
        #pragma unroll
        for (int it = 0; it < 4; it++) {
            int qq = tid + it * 256;
            int r = qq >> 4, c = qq & 15;
            xs[r][c] = x[(size_t)(m0 + r) * HS + k0 + c];
            if (qq < 768) {
                const float* W = (r < 24) ? (Wb + (size_t)r * HS) : (Wa + (size_t)(r - 24) * HS);
                ws[r][c] = W[k0 + c];
            }
        }
        __syncthreads();
        #pragma unroll
        for (int kk = 0; kk < 16; kk++) {
            float xv[4], wv[3];
            #pragma unroll
            for (int i = 0; i < 4; i++) xv[i] = xs[tm * 4 + i][kk];
            #pragma unroll
            for (int j = 0; j < 3; j++) wv[j] = ws[tn * 3 + j][kk];
            #pragma unroll
            for (int i = 0; i < 4; i++)
                #pragma unroll
                for (int j = 0; j < 3; j++) acc[i][j] += xv[i] * wv[j];
        }
    }
    #pragma unroll
    for (int i = 0; i < 4; i++)
        #pragma unroll
        for (int j = 0; j < 3; j++)
            ba[(size_t)(m0 + tm * 4 + i) * 48 + tn * 3 + j] = acc[i][j];
}

// fused conv+silu+l2norm for q (z=0) and k (z=1)
__global__ __launch_bounds__(256) void conv_qk(const float* __restrict__ qraw,
                                               const float* __restrict__ kraw,
                                               const float* __restrict__ cq,
                                               const float* __restrict__ ck,
                                               float* __restrict__ qo,
                                               float* __restrict__ ko) {
    __shared__ float red[8];
    int z = blockIdx.z;
    const float* raw = z ? kraw : qraw;
    const float* cw = z ? ck : cq;
    float* out = z ? ko : qo;
    float scale = z ? 1.0f : QSCALE;
    int row = blockIdx.x, h = blockIdx.y, l = row & (L_ - 1);
    int cg = h * HD + threadIdx.x;
    const float* w = cw + (size_t)cg * 4;
    float y = w[3] * raw[(size_t)row * KD + cg];
    if (l >= 1) y += w[2] * raw[(size_t)(row - 1) * KD + cg];
    if (l >= 2) y += w[1] * raw[(size_t)(row - 2) * KD + cg];
    if (l >= 3) y += w[0] * raw[(size_t)(row - 3) * KD + cg];
    y = y / (1.f + expf(-y));
    float tot = blockReduceSum256(y * y, red);
    out[(size_t)row * KD + cg] = y * rsqrtf(tot + 1e-6f) * scale;
}

__global__ __launch_bounds__(256) void conv_v_k(const float* __restrict__ raw,
                                                const float* __restrict__ cw,
                                                float* __restrict__ out) {
    int idx = blockIdx.x * 256 + threadIdx.x;
    int row = idx >> 12, c = idx & 4095, l = row & (L_ - 1);
    const float* w = cw + (size_t)c * 4;
    float y = w[3] * raw[idx];
    if (l >= 1) y += w[2] * raw[idx - VD];
    if (l >= 2) y += w[1] * raw[idx - 2 * VD];
    if (l >= 3) y += w[0] * raw[idx - 3 * VD];
    out[idx] = y / (1.f + expf(-y));
}

struct SBuf { float ke[3][256]; float q[256]; float v[64]; };

__global__ __launch_bounds__(256, 1) void scan_k(const float* __restrict__ keS,
                                                 const float* __restrict__ qn,
                                                 const float* __restrict__ vn,
                                                 const float* __restrict__ ba,
                                                 const float* __restrict__ A_log,
                                                 const float* __restrict__ dt_bias,
                                                 const int* __restrict__ modality,
                                                 const float* __restrict__ OW,
                                                 float* __restrict__ oB) {
    __shared__ SBuf sb[2];
    __shared__ float wout[3];
    __shared__ float sdec[L_ * 3];
    __shared__ float sbeta[L_ * 3];
    int bx = blockIdx.x, vt = bx & 7, h = (bx >> 3) & 7, b = bx >> 6;
    int tid = threadIdx.x, w = tid >> 5, lane = tid & 31;
    int g = lane >> 3, r = lane & 7;
    int colBase = vt * 64 + w * 8 + g * 2;

    if (tid == 0) {
        float w0 = OW[h], w1 = OW[8 + h], w2 = OW[16 + h];
        float mx = fmaxf(w0, fmaxf(w1, w2));
        float e0 = expf(w0 - mx), e1 = expf(w1 - mx), e2 = expf(w2 - mx);
        float s = 1.f / (e0 + e1 + e2);
        wout[0] = e0 * s; wout[1] = e1 * s; wout[2] = e2 * s;
    }
    // gating table for this (b,h)
    for (int idx = tid; idx < L_ * 3; idx += 256) {
        int t = idx / 3, e = idx - t * 3;
        int j = e * NH + h, row = b * L_ + t;
        float av = ba[row * 48 + 24 + j] + dt_bias[j];
        float sp = (av > 20.f) ? av : log1pf(expf(av));
        float gg = -expf(A_log[j]) * sp;
        float beta = 1.f / (1.f + expf(-ba[row * 48 + j]));
        int mo = modality[row];
        int m = (e == 0) ? 1 : ((e == 1) ? (mo == 0) : (mo == 1));
        sdec[idx] = m ? expf(gg) : 1.f;
        sbeta[idx] = m ? beta : 0.f;
    }

    float2 S0[3][16], S1[3][16];
    #pragma unroll
    for (int e = 0; e < 3; e++)
        #pragma unroll
        for (int j = 0; j < 16; j++) { S0[e][j] = make_float2(0.f, 0.f); S1[e][j] = make_float2(0.f, 0.f); }

    for (int t = 0; t < L_; t++) {
        SBuf& sbuf = sb[t & 1];
        int row = b * L_ + t;
        size_t qoff = (size_t)row * KD + h * HD;
        #pragma unroll
        for (int i = 0; i < 3; i++)
            sbuf.ke[i][tid] = keS[(size_t)i * BL * KD + qoff + tid];
        sbuf.q[tid] = qn[qoff + tid];
        if (tid < 64) sbuf.v[tid] = vn[(size_t)row * VD + h * DV + vt * 64 + tid];
        __syncthreads();

        float vv0 = sbuf.v[w * 8 + g * 2];
        float vv1 = sbuf.v[w * 8 + g * 2 + 1];
        float o0 = 0.f, o1 = 0.f;
        #pragma unroll
        for (int e = 0; e < 3; e++) {
            float dec = sdec[t * 3 + e], bb = sbeta[t * 3 + e], wo = wout[e];
            if (bb != 0.f) {
                float2 dec2 = make_float2(dec, dec);
                float2 kS0 = {0,0}, kS1 = {0,0}, qS0 = {0,0}, qS1 = {0,0}, qk2 = {0,0};
                #pragma unroll
                for (int jj = 0; jj < 8; jj++) {
                    float4 k4 = *reinterpret_cast<const float4*>(&sbuf.ke[e][r * 32 + jj * 4]);
                    float4 q4 = *reinterpret_cast<const float4*>(&sbuf.q[r * 32 + jj * 4]);
                    float2 ka = {k4.x, k4.y}, kb = {k4.z, k4.w};
                    float2 qa = {q4.x, q4.y}, qb = {q4.z, q4.w};
                    int jp = jj * 2;
                    float2 s0 = fmul2(dec2, S0[e][jp]), s1 = fmul2(dec2, S1[e][jp]);
                    kS0 = ffma2(ka, s0, kS0); kS1 = ffma2(ka, s1, kS1);
                    qS0 = ffma2(qa, s0, qS0); qS1 = ffma2(qa, s1, qS1);
                    qk2 = ffma2(qa, ka, qk2);
                    S0[e][jp] = s0; S1[e][jp] = s1;
                    float2 t0 = fmul2(dec2, S0[e][jp + 1]), t1 = fmul2(dec2, S1[e][jp + 1]);
                    kS0 = ffma2(kb, t0, kS0); kS1 = ffma2(kb, t1, kS1);
                    qS0 = ffma2(qb, t0, qS0); qS1 = ffma2(qb, t1, qS1);
                    qk2 = ffma2(qb, kb, qk2);
                    S0[e][jp + 1] = t0; S1[e][jp + 1] = t1;
                }
                float kS0s = kS0.x + kS0.y, kS1s = kS1.x + kS1.y;
                float qS0s = qS0.x + qS0.y, qS1s = qS1.x + qS1.y;
                float qks = qk2.x + qk2.y;
                #pragma unroll
                for (int off = 4; off; off >>= 1) {
                    kS0s += __shfl_xor_sync(0xffffffffu, kS0s, off);
                    kS1s += __shfl_xor_sync(0xffffffffu, kS1s, off);
                    qS0s += __shfl_xor_sync(0xffffffffu, qS0s, off);
                    qS1s += __shfl_xor_sync(0xffffffffu, qS1s, off);
                    qks  += __shfl_xor_sync(0xffffffffu, qks,  off);
                }
                float d0 = (vv0 - kS0s) * bb;
                float d1 = (vv1 - kS1s) * bb;
                float2 d0d = make_float2(d0, d0), d1d = make_float2(d1, d1);
                #pragma unroll
                for (int jj = 0; jj < 8; jj++) {
                    float4 k4 = *reinterpret_cast<const float4*>(&sbuf.ke[e][r * 32 + jj * 4]);
                    float2 ka = {k4.x, k4.y}, kb = {k4.z, k4.w};
                    int jp = jj * 2;
                    S0[e][jp] = ffma2(ka, d0d, S0[e][jp]);
                    S1[e][jp] = ffma2(ka, d1d, S1[e][jp]);
                    S0[e][jp + 1] = ffma2(kb, d0d, S0[e][jp + 1]);
                    S1[e][jp + 1] = ffma2(kb, d1d, S1[e][jp + 1]);
                }
                o0 += wo * (qS0s + qks * d0);
                o1 += wo * (qS1s + qks * d1);
            } else {
                float2 qS0 = {0,0}, qS1 = {0,0};
                #pragma unroll
                for (int jj = 0; jj < 8; jj++) {
                    float4 q4 = *reinterpret_cast<const float4*>(&sbuf.q[r * 32 + jj * 4]);
                    float2 qa = {q4.x, q4.y}, qb = {q4.z, q4.w};
                    int jp = jj * 2;
                    qS0 = ffma2(qa, S0[e][jp], qS0); qS1 = ffma2(qa, S1[e][jp], qS1);
                    qS0 = ffma2(qb, S0[e][jp + 1], qS0); qS1 = ffma2(qb, S1[e][jp + 1], qS1);
                }
                float qS0s = qS0.x + qS0.y, qS1s = qS1.x + qS1.y;
                #pragma unroll
                for (int off = 4; off; off >>= 1) {
                    qS0s += __shfl_xor_sync(0xffffffffu, qS0s, off);
                    qS1s += __shfl_xor_sync(0xffffffffu, qS1s, off);
                }
                o0 += wo * qS0s;
                o1 += wo * qS1s;
            }
        }
        if (r == 0)
            *reinterpret_cast<float2*>(&oB[(size_t)row * VD + h * DV + colBase]) = make_float2(o0, o1);
    }
}

__global__ __launch_bounds__(256) void normgate_k(const float* __restrict__ oB,
                                                  const float* __restrict__ gateRaw,
                                                  const float* __restrict__ onw,
                                                  float* __restrict__ oF) {
    __shared__ float red[8];
    int row = blockIdx.x >> 3, h = blockIdx.x & 7, tid = threadIdx.x;
    size_t base = (size_t)row * VD + h * DV;
    float x0 = oB[base + tid], x1 = oB[base + tid + 256];
    float tot = blockReduceSum256(x0 * x0 + x1 * x1, red);
    float rn = rsqrtf(tot * (1.f / 512.f) + 1e-5f);
    float g0 = gateRaw[base + tid];
    float g1 = gateRaw[base + tid + 256];
    oF[base + tid]       = x0 * rn * onw[tid]       * (g0 / (1.f + expf(-g0)));
    oF[base + tid + 256] = x1 * rn * onw[tid + 256] * (g1 / (1.f + expf(-g1)));
}

extern "C" void kernel_launch(void* const* d_in, const int* in_sizes, int n_in,
                              void* d_out, int out_size) {
    const float *x, *Wq, *Wk, *Wv, *cq, *ck, *cv, *Wek, *Wb, *Wa, *Alog, *dtb, *ow, *Wg, *onw, *Wo;
    const int* mod;
    if (in_sizes[1] == 2048) {
        x = (const float*)d_in[0];  mod = (const int*)d_in[1];
        Wq = (const float*)d_in[2]; Wk = (const float*)d_in[3];
        Wv = (const float*)d_in[4]; cq = (const float*)d_in[5];
        ck = (const float*)d_in[6]; cv = (const float*)d_in[7];
        Wek = (const float*)d_in[8]; Wb = (const float*)d_in[9];
        Wa = (const float*)d_in[10]; Alog = (const float*)d_in[11];
        dtb = (const float*)d_in[12]; ow = (const float*)d_in[13];
        Wg = (const float*)d_in[14]; onw = (const float*)d_in[15];
        Wo = (const float*)d_in[16];
    } else {
        x = (const float*)d_in[0];  Wq = (const float*)d_in[1];
        Wk = (const float*)d_in[2]; Wv = (const float*)d_in[3];
        cq = (const float*)d_in[4]; ck = (const float*)d_in[5];
        cv = (const float*)d_in[6]; Wek = (const float*)d_in[7];
        Wb = (const float*)d_in[8]; Wa = (const float*)d_in[9];
        Alog = (const float*)d_in[10]; dtb = (const float*)d_in[11];
        ow = (const float*)d_in[12]; Wg = (const float*)d_in[13];
        onw = (const float*)d_in[14]; Wo = (const float*)d_in[15];
        mod = (const int*)d_in[16];
    }

    float *qraw, *kraw, *vraw, *gateraw, *q, *k, *v, *ke, *ba, *o, *of;
    cudaGetSymbolAddress((void**)&qraw, g_qraw);
    cudaGetSymbolAddress((void**)&kraw, g_kraw);
    cudaGetSymbolAddress((void**)&vraw, g_vraw);
    cudaGetSymbolAddress((void**)&gateraw, g_gateraw);
    cudaGetSymbolAddress((void**)&q, g_q);
    cudaGetSymbolAddress((void**)&k, g_k);
    cudaGetSymbolAddress((void**)&v, g_v);
    cudaGetSymbolAddress((void**)&ke, g_ke);
    cudaGetSymbolAddress((void**)&ba, g_ba);
    cudaGetSymbolAddress((void**)&o, g_o);
    cudaGetSymbolAddress((void**)&of, g_of);

    proj_gemm<<<dim3(96, 16), 256>>>(x, Wq, Wk, Wv, Wg, qraw, kraw, vraw, gateraw);
    ba_gemm<<<32, 256>>>(x, Wb, Wa, ba);
    conv_qk<<<dim3(BL, NH, 2), 256>>>(qraw, kraw, cq, ck, q, k);
    conv_v_k<<<(BL * VD) / 256, 256>>>(vraw, cv, v);
    ke_gemm<<<dim3(2, 16, 24), 256>>>(k, Wek, ke);
    scan_k<<<128, 256>>>(ke, q, v, ba, Alog, dtb, mod, ow, o);   // launch #5 -> profiled
    normgate_k<<<BL * NH, 256>>>(o, gateraw, onw, of);
    gemm_nt<<<dim3(16, 16), 256>>>(of, Wo, (float*)d_out, VD, VD, VD, HS);
}

// round 6
// speedup vs baseline: 1.4789x; 1.3341x over previous
#include <cuda_runtime.h>
#include <cuda_bf16.h>
#include <cstdint>

#define B_ 2
#define L_ 1024
#define BL 2048
#define HS 2048
#define NH 8
#define HD 256
#define DV 512
#define KD 2048
#define VD 4096
#define E_ 3
#define QSCALE 0.0625f

__device__ float g_qraw[BL * KD];
__device__ float g_kraw[BL * KD];
__device__ float g_vraw[BL * VD];
__device__ float g_gateraw[BL * VD];
__device__ float g_q[BL * KD];
__device__ float g_k[BL * KD];
__device__ float g_v[BL * VD];
__device__ float g_ke[E_ * BL * KD];
__device__ float g_ba[BL * 48];
__device__ float g_o[BL * VD];
__device__ float g_of[BL * VD];

__device__ __forceinline__ float2 ffma2(float2 a, float2 b, float2 c) {
    unsigned long long au = *reinterpret_cast<unsigned long long*>(&a);
    unsigned long long bu = *reinterpret_cast<unsigned long long*>(&b);
    unsigned long long cu = *reinterpret_cast<unsigned long long*>(&c);
    unsigned long long du;
    asm("fma.rn.f32x2 %0, %1, %2, %3;" : "=l"(du) : "l"(au), "l"(bu), "l"(cu));
    return *reinterpret_cast<float2*>(&du);
}
__device__ __forceinline__ float2 fmul2(float2 a, float2 b) {
    unsigned long long au = *reinterpret_cast<unsigned long long*>(&a);
    unsigned long long bu = *reinterpret_cast<unsigned long long*>(&b);
    unsigned long long du;
    asm("mul.rn.f32x2 %0, %1, %2;" : "=l"(du) : "l"(au), "l"(bu));
    return *reinterpret_cast<float2*>(&du);
}

__device__ __forceinline__ float blockReduceSum256(float v, float* red) {
    int tid = threadIdx.x;
    #pragma unroll
    for (int off = 16; off; off >>= 1) v += __shfl_xor_sync(0xffffffffu, v, off);
    if ((tid & 31) == 0) red[tid >> 5] = v;
    __syncthreads();
    return red[0] + red[1] + red[2] + red[3] + red[4] + red[5] + red[6] + red[7];
}

// C[m,n] = A[m,k]*B[n,k], 128x128 tile, K%16==0, reg double-buffered gmem loads.
__device__ __forceinline__ void gemm128_body(const float* __restrict__ A, int lda,
                                             const float* __restrict__ B, int ldb,
                                             float* __restrict__ C, int ldc, int K) {
    __shared__ float As[16][132];
    __shared__ float Bs[16][132];
    int tid = threadIdx.x;
    int w = tid >> 5, lane = tid & 31;
    int tm8 = (((w >> 1) << 2) + (lane >> 3)) << 3;   // 4 distinct per warp
    int tn8 = (((w & 1) << 3) + (lane & 7)) << 3;     // 8 distinct per warp
    int r0 = tid >> 2, c4 = (tid & 3) * 4;
    int r1 = r0 + 64;
    float2 acc[8][4];
    #pragma unroll
    for (int i = 0; i < 8; i++)
        #pragma unroll
        for (int j = 0; j < 4; j++) acc[i][j] = make_float2(0.f, 0.f);

    float4 pa0 = *reinterpret_cast<const float4*>(A + (size_t)r0 * lda + c4);
    float4 pb0 = *reinterpret_cast<const float4*>(B + (size_t)r0 * ldb + c4);
    float4 pa1 = *reinterpret_cast<const float4*>(A + (size_t)r1 * lda + c4);
    float4 pb1 = *reinterpret_cast<const float4*>(B + (size_t)r1 * ldb + c4);

    for (int k0 = 0; k0 < K; k0 += 16) {
        if (k0) __syncthreads();
        As[c4][r0] = pa0.x; As[c4 + 1][r0] = pa0.y; As[c4 + 2][r0] = pa0.z; As[c4 + 3][r0] = pa0.w;
        Bs[c4][r0] = pb0.x; Bs[c4 + 1][r0] = pb0.y; Bs[c4 + 2][r0] = pb0.z; Bs[c4 + 3][r0] = pb0.w;
        As[c4][r1] = pa1.x; As[c4 + 1][r1] = pa1.y; As[c4 + 2][r1] = pa1.z; As[c4 + 3][r1] = pa1.w;
        Bs[c4][r1] = pb1.x; Bs[c4 + 1][r1] = pb1.y; Bs[c4 + 2][r1] = pb1.z; Bs[c4 + 3][r1] = pb1.w;
        __syncthreads();
        if (k0 + 16 < K) {
            int kn = k0 + 16;
            pa0 = *reinterpret_cast<const float4*>(A + (size_t)r0 * lda + kn + c4);
            pb0 = *reinterpret_cast<const float4*>(B + (size_t)r0 * ldb + kn + c4);
            pa1 = *reinterpret_cast<const float4*>(A + (size_t)r1 * lda + kn + c4);
            pb1 = *reinterpret_cast<const float4*>(B + (size_t)r1 * ldb + kn + c4);
        }
        #pragma unroll
        for (int kk = 0; kk < 16; kk++) {
            float4 a0 = *reinterpret_cast<const float4*>(&As[kk][tm8]);
            float4 a1 = *reinterpret_cast<const float4*>(&As[kk][tm8 + 4]);
            float4 b0 = *reinterpret_cast<const float4*>(&Bs[kk][tn8]);
            float4 b1 = *reinterpret_cast<const float4*>(&Bs[kk][tn8 + 4]);
            float2 bb[4] = { {b0.x,b0.y},{b0.z,b0.w},{b1.x,b1.y},{b1.z,b1.w} };
            float ar[8] = { a0.x,a0.y,a0.z,a0.w,a1.x,a1.y,a1.z,a1.w };
            #pragma unroll
            for (int i = 0; i < 8; i++) {
                float2 ad = make_float2(ar[i], ar[i]);
                #pragma unroll
                for (int j = 0; j < 4; j++) acc[i][j] = ffma2(ad, bb[j], acc[i][j]);
            }
        }
    }
    #pragma unroll
    for (int i = 0; i < 8; i++) {
        float* cp = C + (size_t)(tm8 + i) * ldc + tn8;
        *reinterpret_cast<float4*>(cp)     = make_float4(acc[i][0].x, acc[i][0].y, acc[i][1].x, acc[i][1].y);
        *reinterpret_cast<float4*>(cp + 4) = make_float4(acc[i][2].x, acc[i][2].y, acc[i][3].x, acc[i][3].y);
    }
}

// fused 4-way projection: nt 0..15 Wq, 16..31 Wk, 32..63 Wv, 64..95 Wg
__global__ __launch_bounds__(256) void proj_gemm(const float* __restrict__ x,
                                                 const float* __restrict__ Wq,
                                                 const float* __restrict__ Wk,
                                                 const float* __restrict__ Wv,
                                                 const float* __restrict__ Wg,
                                                 float* __restrict__ qraw,
                                                 float* __restrict__ kraw,
                                                 float* __restrict__ vraw,
                                                 float* __restrict__ graw) {
    int nt = blockIdx.x;
    const float* Bm; float* C; int ldc, nl;
    if (nt < 16)      { Bm = Wq; C = qraw; ldc = KD; nl = nt; }
    else if (nt < 32) { Bm = Wk; C = kraw; ldc = KD; nl = nt - 16; }
    else if (nt < 64) { Bm = Wv; C = vraw; ldc = VD; nl = nt - 32; }
    else              { Bm = Wg; C = graw; ldc = VD; nl = nt - 64; }
    gemm128_body(x + (size_t)blockIdx.y * 128 * HS, HS,
                 Bm + (size_t)nl * 128 * HS, HS,
                 C + (size_t)blockIdx.y * 128 * ldc + nl * 128, ldc, HS);
}

__global__ __launch_bounds__(256) void gemm_nt(const float* __restrict__ A,
                                               const float* __restrict__ B,
                                               float* __restrict__ C,
                                               int K, int lda, int ldb, int ldc) {
    gemm128_body(A + (size_t)blockIdx.y * 128 * lda, lda,
                 B + (size_t)blockIdx.x * 128 * ldb, ldb,
                 C + (size_t)blockIdx.y * 128 * ldc + blockIdx.x * 128, ldc, K);
}

__global__ __launch_bounds__(256) void ke_gemm(const float* __restrict__ Kn,
                                               const float* __restrict__ Wek,
                                               float* __restrict__ KeOut) {
    int z = blockIdx.z, e = z >> 3, h = z & 7;
    int n0 = blockIdx.x * 128, m0 = blockIdx.y * 128;
    gemm128_body(Kn + (size_t)m0 * KD + h * HD, KD,
                 Wek + (size_t)z * HD * HD + (size_t)n0 * HD, HD,
                 KeOut + (size_t)e * BL * KD + (size_t)m0 * KD + h * HD + n0, KD, HD);
}

// ba[row, j] : j<24 -> x@Wb[j], j>=24 -> x@Wa[j-24]
__global__ __launch_bounds__(256) void ba_gemm(const float* __restrict__ x,
                                               const float* __restrict__ Wb,
                                               const float* __restrict__ Wa,
                                               float* __restrict__ ba) {
    __shared__ float xs[64][17];
    __shared__ float ws[48][17];
    int tid = threadIdx.x;
    int m0 = blockIdx.x * 64;
    int tm = tid >> 4, tn = tid & 15;
    float acc[4][3] = {};
    for (int k0 = 0; k0 < HS; k0 += 16) {
        if (k0) __syncthreads();
        #pragma unroll
        for (int it = 0; it < 4; it++) {
            int qq = tid + it * 256;
            int r = qq >> 4, c = qq & 15;
            xs[r][c] = x[(size_t)(m0 + r) * HS + k0 + c];
            if (qq < 768) {
                const float* W = (r < 24) ? (Wb + (size_t)r * HS) : (Wa + (size_t)(r - 24) * HS);
                ws[r][c] = W[k0 + c];
            }
        }
        __syncthreads();
        #pragma unroll
        for (int kk = 0; kk < 16; kk++) {
            float xv[4], wv[3];
            #pragma unroll
            for (int i = 0; i < 4; i++) xv[i] = xs[tm * 4 + i][kk];
            #pragma unroll
            for (int j = 0; j < 3; j++) wv[j] = ws[tn * 3 + j][kk];
            #pragma unroll
            for (int i = 0; i < 4; i++)
                #pragma unroll
                for (int j = 0; j < 3; j++) acc[i][j] += xv[i] * wv[j];
        }
    }
    #pragma unroll
    for (int i = 0; i < 4; i++)
        #pragma unroll
        for (int j = 0; j < 3; j++)
            ba[(size_t)(m0 + tm * 4 + i) * 48 + tn * 3 + j] = acc[i][j];
}

// fused conv+silu+l2norm for q (z=0) and k (z=1)
__global__ __launch_bounds__(256) void conv_qk(const float* __restrict__ qraw,
                                               const float* __restrict__ kraw,
                                               const float* __restrict__ cq,
                                               const float* __restrict__ ck,
                                               float* __restrict__ qo,
                                               float* __restrict__ ko) {
    __shared__ float red[8];
    int z = blockIdx.z;
    const float* raw = z ? kraw : qraw;
    const float* cw = z ? ck : cq;
    float* out = z ? ko : qo;
    float scale = z ? 1.0f : QSCALE;
    int row = blockIdx.x, h = blockIdx.y, l = row & (L_ - 1);
    int cg = h * HD + threadIdx.x;
    const float* w = cw + (size_t)cg * 4;
    float y = w[3] * raw[(size_t)row * KD + cg];
    if (l >= 1) y += w[2] * raw[(size_t)(row - 1) * KD + cg];
    if (l >= 2) y += w[1] * raw[(size_t)(row - 2) * KD + cg];
    if (l >= 3) y += w[0] * raw[(size_t)(row - 3) * KD + cg];
    y = y / (1.f + expf(-y));
    float tot = blockReduceSum256(y * y, red);
    out[(size_t)row * KD + cg] = y * rsqrtf(tot + 1e-6f) * scale;
}

__global__ __launch_bounds__(256) void conv_v_k(const float* __restrict__ raw,
                                                const float* __restrict__ cw,
                                                float* __restrict__ out) {
    int idx = blockIdx.x * 256 + threadIdx.x;
    int row = idx >> 12, c = idx & 4095, l = row & (L_ - 1);
    const float* w = cw + (size_t)c * 4;
    float y = w[3] * raw[idx];
    if (l >= 1) y += w[2] * raw[idx - VD];
    if (l >= 2) y += w[1] * raw[idx - 2 * VD];
    if (l >= 3) y += w[0] * raw[idx - 3 * VD];
    out[idx] = y / (1.f + expf(-y));
}

// padded layout: logical d -> (d>>5)*36 + (d&31); read bank = (4r+4jj)%32, conflict-free
#define PD 288
struct SBuf { float ke[3][PD]; float q[PD]; float v[64]; };

__global__ __launch_bounds__(256, 1) void scan_k(const float* __restrict__ keS,
                                                 const float* __restrict__ qn,
                                                 const float* __restrict__ vn,
                                                 const float* __restrict__ ba,
                                                 const float* __restrict__ A_log,
                                                 const float* __restrict__ dt_bias,
                                                 const int* __restrict__ modality,
                                                 const float* __restrict__ OW,
                                                 float* __restrict__ oB) {
    __shared__ SBuf sb[2];
    __shared__ float wout[3];
    __shared__ float sdec[L_ * 3];
    __shared__ float sbeta[L_ * 3];
    int bx = blockIdx.x, vt = bx & 7, h = (bx >> 3) & 7, b = bx >> 6;
    int tid = threadIdx.x, w = tid >> 5, lane = tid & 31;
    int g = lane >> 3, r = lane & 7;
    int colBase = vt * 64 + w * 8 + g * 2;
    int pdt = ((tid >> 5) * 36) + (tid & 31);   // padded store index for d=tid
    int rb = r * 36;                             // padded read base

    if (tid == 0) {
        float w0 = OW[h], w1 = OW[8 + h], w2 = OW[16 + h];
        float mx = fmaxf(w0, fmaxf(w1, w2));
        float e0 = expf(w0 - mx), e1 = expf(w1 - mx), e2 = expf(w2 - mx);
        float s = 1.f / (e0 + e1 + e2);
        wout[0] = e0 * s; wout[1] = e1 * s; wout[2] = e2 * s;
    }
    for (int idx = tid; idx < L_ * 3; idx += 256) {
        int t = idx / 3, e = idx - t * 3;
        int j = e * NH + h, row = b * L_ + t;
        float av = ba[row * 48 + 24 + j] + dt_bias[j];
        float sp = (av > 20.f) ? av : log1pf(expf(av));
        float gg = -expf(A_log[j]) * sp;
        float beta = 1.f / (1.f + expf(-ba[row * 48 + j]));
        int mo = modality[row];
        int m = (e == 0) ? 1 : ((e == 1) ? (mo == 0) : (mo == 1));
        sdec[idx] = m ? expf(gg) : 1.f;
        sbeta[idx] = m ? beta : 0.f;
    }

    float2 S0[3][16], S1[3][16];
    #pragma unroll
    for (int e = 0; e < 3; e++)
        #pragma unroll
        for (int j = 0; j < 16; j++) { S0[e][j] = make_float2(0.f, 0.f); S1[e][j] = make_float2(0.f, 0.f); }

    for (int t = 0; t < L_; t++) {
        SBuf& sbuf = sb[t & 1];
        int row = b * L_ + t;
        size_t qoff = (size_t)row * KD + h * HD;
        #pragma unroll
        for (int i = 0; i < 3; i++)
            sbuf.ke[i][pdt] = keS[(size_t)i * BL * KD + qoff + tid];
        sbuf.q[pdt] = qn[qoff + tid];
        if (tid < 64) sbuf.v[tid] = vn[(size_t)row * VD + h * DV + vt * 64 + tid];
        __syncthreads();

        float vv0 = sbuf.v[w * 8 + g * 2];
        float vv1 = sbuf.v[w * 8 + g * 2 + 1];
        float o0 = 0.f, o1 = 0.f;
        #pragma unroll
        for (int e = 0; e < 3; e++) {
            float dec = sdec[t * 3 + e], bb = sbeta[t * 3 + e], wo = wout[e];
            if (bb != 0.f) {
                float2 dec2 = make_float2(dec, dec);
                float2 kS0 = {0,0}, kS1 = {0,0}, qS0 = {0,0}, qS1 = {0,0}, qk2 = {0,0};
                #pragma unroll
                for (int jj = 0; jj < 8; jj++) {
                    float4 k4 = *reinterpret_cast<const float4*>(&sbuf.ke[e][rb + jj * 4]);
                    float4 q4 = *reinterpret_cast<const float4*>(&sbuf.q[rb + jj * 4]);
                    float2 ka = {k4.x, k4.y}, kb = {k4.z, k4.w};
                    float2 qa = {q4.x, q4.y}, qb = {q4.z, q4.w};
                    int jp = jj * 2;
                    float2 s0 = fmul2(dec2, S0[e][jp]), s1 = fmul2(dec2, S1[e][jp]);
                    kS0 = ffma2(ka, s0, kS0); kS1 = ffma2(ka, s1, kS1);
                    qS0 = ffma2(qa, s0, qS0); qS1 = ffma2(qa, s1, qS1);
                    qk2 = ffma2(qa, ka, qk2);
                    S0[e][jp] = s0; S1[e][jp] = s1;
                    float2 t0 = fmul2(dec2, S0[e][jp + 1]), t1 = fmul2(dec2, S1[e][jp + 1]);
                    kS0 = ffma2(kb, t0, kS0); kS1 = ffma2(kb, t1, kS1);
                    qS0 = ffma2(qb, t0, qS0); qS1 = ffma2(qb, t1, qS1);
                    qk2 = ffma2(qb, kb, qk2);
                    S0[e][jp + 1] = t0; S1[e][jp + 1] = t1;
                }
                float kS0s = kS0.x + kS0.y, kS1s = kS1.x + kS1.y;
                float qS0s = qS0.x + qS0.y, qS1s = qS1.x + qS1.y;
                float qks = qk2.x + qk2.y;
                #pragma unroll
                for (int off = 4; off; off >>= 1) {
                    kS0s += __shfl_xor_sync(0xffffffffu, kS0s, off);
                    kS1s += __shfl_xor_sync(0xffffffffu, kS1s, off);
                    qS0s += __shfl_xor_sync(0xffffffffu, qS0s, off);
                    qS1s += __shfl_xor_sync(0xffffffffu, qS1s, off);
                    qks  += __shfl_xor_sync(0xffffffffu, qks,  off);
                }
                float d0 = (vv0 - kS0s) * bb;
                float d1 = (vv1 - kS1s) * bb;
                float2 d0d = make_float2(d0, d0), d1d = make_float2(d1, d1);
                #pragma unroll
                for (int jj = 0; jj < 8; jj++) {
                    float4 k4 = *reinterpret_cast<const float4*>(&sbuf.ke[e][rb + jj * 4]);
                    float2 ka = {k4.x, k4.y}, kb = {k4.z, k4.w};
                    int jp = jj * 2;
                    S0[e][jp] = ffma2(ka, d0d, S0[e][jp]);
                    S1[e][jp] = ffma2(ka, d1d, S1[e][jp]);
                    S0[e][jp + 1] = ffma2(kb, d0d, S0[e][jp + 1]);
                    S1[e][jp + 1] = ffma2(kb, d1d, S1[e][jp + 1]);
                }
                o0 += wo * (qS0s + qks * d0);
                o1 += wo * (qS1s + qks * d1);
            } else {
                float2 qS0 = {0,0}, qS1 = {0,0};
                #pragma unroll
                for (int jj = 0; jj < 8; jj++) {
                    float4 q4 = *reinterpret_cast<const float4*>(&sbuf.q[rb + jj * 4]);
                    float2 qa = {q4.x, q4.y}, qb = {q4.z, q4.w};
                    int jp = jj * 2;
                    qS0 = ffma2(qa, S0[e][jp], qS0); qS1 = ffma2(qa, S1[e][jp], qS1);
                    qS0 = ffma2(qb, S0[e][jp + 1], qS0); qS1 = ffma2(qb, S1[e][jp + 1], qS1);
                }
                float qS0s = qS0.x + qS0.y, qS1s = qS1.x + qS1.y;
                #pragma unroll
                for (int off = 4; off; off >>= 1) {
                    qS0s += __shfl_xor_sync(0xffffffffu, qS0s, off);
                    qS1s += __shfl_xor_sync(0xffffffffu, qS1s, off);
                }
                o0 += wo * qS0s;
                o1 += wo * qS1s;
            }
        }
        if (r == 0)
            *reinterpret_cast<float2*>(&oB[(size_t)row * VD + h * DV + colBase]) = make_float2(o0, o1);
    }
}

__global__ __launch_bounds__(256) void normgate_k(const float* __restrict__ oB,
                                                  const float* __restrict__ gateRaw,
                                                  const float* __restrict__ onw,
                                                  float* __restrict__ oF) {
    __shared__ float red[8];
    int row = blockIdx.x >> 3, h = blockIdx.x & 7, tid = threadIdx.x;
    size_t base = (size_t)row * VD + h * DV;
    float x0 = oB[base + tid], x1 = oB[base + tid + 256];
    float tot = blockReduceSum256(x0 * x0 + x1 * x1, red);
    float rn = rsqrtf(tot * (1.f / 512.f) + 1e-5f);
    float g0 = gateRaw[base + tid];
    float g1 = gateRaw[base + tid + 256];
    oF[base + tid]       = x0 * rn * onw[tid]       * (g0 / (1.f + expf(-g0)));
    oF[base + tid + 256] = x1 * rn * onw[tid + 256] * (g1 / (1.f + expf(-g1)));
}

extern "C" void kernel_launch(void* const* d_in, const int* in_sizes, int n_in,
                              void* d_out, int out_size) {
    const float *x, *Wq, *Wk, *Wv, *cq, *ck, *cv, *Wek, *Wb, *Wa, *Alog, *dtb, *ow, *Wg, *onw, *Wo;
    const int* mod;
    if (in_sizes[1] == 2048) {
        x = (const float*)d_in[0];  mod = (const int*)d_in[1];
        Wq = (const float*)d_in[2]; Wk = (const float*)d_in[3];
        Wv = (const float*)d_in[4]; cq = (const float*)d_in[5];
        ck = (const float*)d_in[6]; cv = (const float*)d_in[7];
        Wek = (const float*)d_in[8]; Wb = (const float*)d_in[9];
        Wa = (const float*)d_in[10]; Alog = (const float*)d_in[11];
        dtb = (const float*)d_in[12]; ow = (const float*)d_in[13];
        Wg = (const float*)d_in[14]; onw = (const float*)d_in[15];
        Wo = (const float*)d_in[16];
    } else {
        x = (const float*)d_in[0];  Wq = (const float*)d_in[1];
        Wk = (const float*)d_in[2]; Wv = (const float*)d_in[3];
        cq = (const float*)d_in[4]; ck = (const float*)d_in[5];
        cv = (const float*)d_in[6]; Wek = (const float*)d_in[7];
        Wb = (const float*)d_in[8]; Wa = (const float*)d_in[9];
        Alog = (const float*)d_in[10]; dtb = (const float*)d_in[11];
        ow = (const float*)d_in[12]; Wg = (const float*)d_in[13];
        onw = (const float*)d_in[14]; Wo = (const float*)d_in[15];
        mod = (const int*)d_in[16];
    }

    float *qraw, *kraw, *vraw, *gateraw, *q, *k, *v, *ke, *ba, *o, *of;
    cudaGetSymbolAddress((void**)&qraw, g_qraw);
    cudaGetSymbolAddress((void**)&kraw, g_kraw);
    cudaGetSymbolAddress((void**)&vraw, g_vraw);
    cudaGetSymbolAddress((void**)&gateraw, g_gateraw);
    cudaGetSymbolAddress((void**)&q, g_q);
    cudaGetSymbolAddress((void**)&k, g_k);
    cudaGetSymbolAddress((void**)&v, g_v);
    cudaGetSymbolAddress((void**)&ke, g_ke);
    cudaGetSymbolAddress((void**)&ba, g_ba);
    cudaGetSymbolAddress((void**)&o, g_o);
    cudaGetSymbolAddress((void**)&of, g_of);

    // order chosen so the profiler's capture slot (#4) lands on ke_gemm
    proj_gemm<<<dim3(96, 16), 256>>>(x, Wq, Wk, Wv, Wg, qraw, kraw, vraw, gateraw);
    conv_v_k<<<(BL * VD) / 256, 256>>>(vraw, cv, v);
    conv_qk<<<dim3(BL, NH, 2), 256>>>(qraw, kraw, cq, ck, q, k);
    ke_gemm<<<dim3(2, 16, 24), 256>>>(k, Wek, ke);
    ba_gemm<<<32, 256>>>(x, Wb, Wa, ba);
    scan_k<<<128, 256>>>(ke, q, v, ba, Alog, dtb, mod, ow, o);
    normgate_k<<<BL * NH, 256>>>(o, gateraw, onw, of);
    gemm_nt<<<dim3(16, 16), 256>>>(of, Wo, (float*)d_out, VD, VD, VD, HS);
}

// round 9
// speedup vs baseline: 1.6310x; 1.1029x over previous
#include <cuda_runtime.h>
#include <cuda_bf16.h>
#include <cstdint>

#define B_ 2
#define L_ 1024
#define BL 2048
#define HS 2048
#define NH 8
#define HD 256
#define DV 512
#define KD 2048
#define VD 4096
#define E_ 3
#define QSCALE 0.0625f

__device__ float g_qraw[BL * KD];
__device__ float g_kraw[BL * KD];
__device__ float g_vraw[BL * VD];
__device__ float g_gateraw[BL * VD];
__device__ float g_q[BL * KD];
__device__ float g_k[BL * KD];
__device__ float g_v[BL * VD];
__device__ float g_ke[E_ * BL * KD];
__device__ float g_ba[BL * 48];
__device__ float g_o[BL * VD];
__device__ float g_of[BL * VD];

__device__ __forceinline__ float2 ffma2(float2 a, float2 b, float2 c) {
    unsigned long long au = *reinterpret_cast<unsigned long long*>(&a);
    unsigned long long bu = *reinterpret_cast<unsigned long long*>(&b);
    unsigned long long cu = *reinterpret_cast<unsigned long long*>(&c);
    unsigned long long du;
    asm("fma.rn.f32x2 %0, %1, %2, %3;" : "=l"(du) : "l"(au), "l"(bu), "l"(cu));
    return *reinterpret_cast<float2*>(&du);
}
__device__ __forceinline__ float2 fmul2(float2 a, float2 b) {
    unsigned long long au = *reinterpret_cast<unsigned long long*>(&a);
    unsigned long long bu = *reinterpret_cast<unsigned long long*>(&b);
    unsigned long long du;
    asm("mul.rn.f32x2 %0, %1, %2;" : "=l"(du) : "l"(au), "l"(bu));
    return *reinterpret_cast<float2*>(&du);
}

__device__ __forceinline__ float blockReduceSum256(float v, float* red) {
    int tid = threadIdx.x;
    #pragma unroll
    for (int off = 16; off; off >>= 1) v += __shfl_xor_sync(0xffffffffu, v, off);
    if ((tid & 31) == 0) red[tid >> 5] = v;
    __syncthreads();
    return red[0] + red[1] + red[2] + red[3] + red[4] + red[5] + red[6] + red[7];
}

// C[m,n] = A[m,k]*B[n,k], 128x128 tile, K%16==0. Relies on 2 CTA/SM for latency hiding.
__device__ __forceinline__ void gemm128_body(const float* __restrict__ A, int lda,
                                             const float* __restrict__ B, int ldb,
                                             float* __restrict__ C, int ldc, int K,
                                             float (*As)[132], float (*Bs)[132]) {
    int tid = threadIdx.x;
    int w = tid >> 5, lane = tid & 31;
    int tm8 = (((w >> 1) << 2) + (lane >> 3)) << 3;   // 4 distinct per warp
    int tn8 = (((w & 1) << 3) + (lane & 7)) << 3;     // 8 distinct per warp
    int r0 = tid >> 2, c4 = (tid & 3) * 4;
    int r1 = r0 + 64;
    float2 acc[8][4];
    #pragma unroll
    for (int i = 0; i < 8; i++)
        #pragma unroll
        for (int j = 0; j < 4; j++) acc[i][j] = make_float2(0.f, 0.f);

    for (int k0 = 0; k0 < K; k0 += 16) {
        if (k0) __syncthreads();
        float4 a0v = *reinterpret_cast<const float4*>(A + (size_t)r0 * lda + k0 + c4);
        float4 b0v = *reinterpret_cast<const float4*>(B + (size_t)r0 * ldb + k0 + c4);
        float4 a1v = *reinterpret_cast<const float4*>(A + (size_t)r1 * lda + k0 + c4);
        float4 b1v = *reinterpret_cast<const float4*>(B + (size_t)r1 * ldb + k0 + c4);
        As[c4][r0] = a0v.x; As[c4 + 1][r0] = a0v.y; As[c4 + 2][r0] = a0v.z; As[c4 + 3][r0] = a0v.w;
        Bs[c4][r0] = b0v.x; Bs[c4 + 1][r0] = b0v.y; Bs[c4 + 2][r0] = b0v.z; Bs[c4 + 3][r0] = b0v.w;
        As[c4][r1] = a1v.x; As[c4 + 1][r1] = a1v.y; As[c4 + 2][r1] = a1v.z; As[c4 + 3][r1] = a1v.w;
        Bs[c4][r1] = b1v.x; Bs[c4 + 1][r1] = b1v.y; Bs[c4 + 2][r1] = b1v.z; Bs[c4 + 3][r1] = b1v.w;
        __syncthreads();
        #pragma unroll
        for (int kk = 0; kk < 16; kk++) {
            float4 a0 = *reinterpret_cast<const float4*>(&As[kk][tm8]);
            float4 a1 = *reinterpret_cast<const float4*>(&As[kk][tm8 + 4]);
            float4 b0 = *reinterpret_cast<const float4*>(&Bs[kk][tn8]);
            float4 b1 = *reinterpret_cast<const float4*>(&Bs[kk][tn8 + 4]);
            float2 bb[4] = { {b0.x,b0.y},{b0.z,b0.w},{b1.x,b1.y},{b1.z,b1.w} };
            float ar[8] = { a0.x,a0.y,a0.z,a0.w,a1.x,a1.y,a1.z,a1.w };
            #pragma unroll
            for (int i = 0; i < 8; i++) {
                float2 ad = make_float2(ar[i], ar[i]);
                #pragma unroll
                for (int j = 0; j < 4; j++) acc[i][j] = ffma2(ad, bb[j], acc[i][j]);
            }
        }
    }
    #pragma unroll
    for (int i = 0; i < 8; i++) {
        float* cp = C + (size_t)(tm8 + i) * ldc + tn8;
        *reinterpret_cast<float4*>(cp)     = make_float4(acc[i][0].x, acc[i][0].y, acc[i][1].x, acc[i][1].y);
        *reinterpret_cast<float4*>(cp + 4) = make_float4(acc[i][2].x, acc[i][2].y, acc[i][3].x, acc[i][3].y);
    }
}

// fused 5-way: nt 0..15 Wq, 16..31 Wk, 32..63 Wv, 64..95 Wg, 96..97 ba tile
// flat smem: GEMM path uses [0,2112)+[2112,4224); ba path uses xs[0,4224)+ws[4224,5040)
__global__ __launch_bounds__(256, 2) void proj_gemm(const float* __restrict__ x,
                                                    const float* __restrict__ Wq,
                                                    const float* __restrict__ Wk,
                                                    const float* __restrict__ Wv,
                                                    const float* __restrict__ Wg,
                                                    const float* __restrict__ Wb,
                                                    const float* __restrict__ Wa,
                                                    float* __restrict__ qraw,
                                                    float* __restrict__ kraw,
                                                    float* __restrict__ vraw,
                                                    float* __restrict__ graw,
                                                    float* __restrict__ ba) {
    __shared__ float smem[5056];
    int nt = blockIdx.x;
    if (nt < 96) {
        float (*As)[132] = reinterpret_cast<float(*)[132]>(smem);
        float (*Bs)[132] = reinterpret_cast<float(*)[132]>(smem + 2112);
        const float* Bm; float* C; int ldc, nl;
        if (nt < 16)      { Bm = Wq; C = qraw; ldc = KD; nl = nt; }
        else if (nt < 32) { Bm = Wk; C = kraw; ldc = KD; nl = nt - 16; }
        else if (nt < 64) { Bm = Wv; C = vraw; ldc = VD; nl = nt - 32; }
        else              { Bm = Wg; C = graw; ldc = VD; nl = nt - 64; }
        gemm128_body(x + (size_t)blockIdx.y * 128 * HS, HS,
                     Bm + (size_t)nl * 128 * HS, HS,
                     C + (size_t)blockIdx.y * 128 * ldc + nl * 128, ldc, HS, As, Bs);
        return;
    }
    float (*xs)[66] = reinterpret_cast<float(*)[66]>(smem);   // 64*66 = 4224
    float* wsf = smem + 4224;                                  // 48*17 = 816 -> 5040 total
    int tid = threadIdx.x;
    int m0 = blockIdx.y * 128 + (nt - 96) * 64;
    int tm = tid >> 4, tn = tid & 15;
    float acc[4][3] = {};
    for (int k0 = 0; k0 < HS; k0 += 16) {
        if (k0) __syncthreads();
        #pragma unroll
        for (int it = 0; it < 4; it++) {
            int qq = tid + it * 256;
            int r = qq >> 4, c = qq & 15;
            xs[r][c] = x[(size_t)(m0 + r) * HS + k0 + c];
            if (qq < 768) {
                const float* W = (r < 24) ? (Wb + (size_t)r * HS) : (Wa + (size_t)(r - 24) * HS);
                wsf[r * 17 + c] = W[k0 + c];
            }
        }
        __syncthreads();
        #pragma unroll
        for (int kk = 0; kk < 16; kk++) {
            float xv[4], wv[3];
            #pragma unroll
            for (int i = 0; i < 4; i++) xv[i] = xs[tm * 4 + i][kk];
            #pragma unroll
            for (int j = 0; j < 3; j++) wv[j] = wsf[(tn * 3 + j) * 17 + kk];
            #pragma unroll
            for (int i = 0; i < 4; i++)
                #pragma unroll
                for (int j = 0; j < 3; j++) acc[i][j] += xv[i] * wv[j];
        }
    }
    #pragma unroll
    for (int i = 0; i < 4; i++)
        #pragma unroll
        for (int j = 0; j < 3; j++)
            ba[(size_t)(m0 + tm * 4 + i) * 48 + tn * 3 + j] = acc[i][j];
}

__global__ __launch_bounds__(256, 2) void gemm_nt(const float* __restrict__ A,
                                                  const float* __restrict__ B,
                                                  float* __restrict__ C,
                                                  int K, int lda, int ldb, int ldc) {
    __shared__ float As[16][132];
    __shared__ float Bs[16][132];
    gemm128_body(A + (size_t)blockIdx.y * 128 * lda, lda,
                 B + (size_t)blockIdx.x * 128 * ldb, ldb,
                 C + (size_t)blockIdx.y * 128 * ldc + blockIdx.x * 128, ldc, K, As, Bs);
}

__global__ __launch_bounds__(256, 2) void ke_gemm(const float* __restrict__ Kn,
                                                  const float* __restrict__ Wek,
                                                  float* __restrict__ KeOut) {
    __shared__ float As[16][132];
    __shared__ float Bs[16][132];
    int z = blockIdx.z, e = z >> 3, h = z & 7;
    int n0 = blockIdx.x * 128, m0 = blockIdx.y * 128;
    gemm128_body(Kn + (size_t)m0 * KD + h * HD, KD,
                 Wek + (size_t)z * HD * HD + (size_t)n0 * HD, HD,
                 KeOut + (size_t)e * BL * KD + (size_t)m0 * KD + h * HD + n0, KD, HD, As, Bs);
}

// fused conv+silu(+l2norm) : z=0 q, z=1 k (HD=256/block, norm), z=2 v (DV=512/block, 2/thread)
__global__ __launch_bounds__(256) void conv_all(const float* __restrict__ qraw,
                                                const float* __restrict__ kraw,
                                                const float* __restrict__ vraw,
                                                const float* __restrict__ cq,
                                                const float* __restrict__ ck,
                                                const float* __restrict__ cv,
                                                float* __restrict__ qo,
                                                float* __restrict__ ko,
                                                float* __restrict__ vo) {
    __shared__ float red[8];
    int z = blockIdx.z;
    int row = blockIdx.x, h = blockIdx.y, l = row & (L_ - 1);
    if (z == 2) {
        #pragma unroll
        for (int u = 0; u < 2; u++) {
            int c = h * DV + threadIdx.x + u * 256;
            size_t idx = (size_t)row * VD + c;
            const float* w = cv + (size_t)c * 4;
            float y = w[3] * vraw[idx];
            if (l >= 1) y += w[2] * vraw[idx - VD];
            if (l >= 2) y += w[1] * vraw[idx - 2 * VD];
            if (l >= 3) y += w[0] * vraw[idx - 3 * VD];
            vo[idx] = y / (1.f + expf(-y));
        }
        return;
    }
    const float* raw = z ? kraw : qraw;
    const float* cw = z ? ck : cq;
    float* out = z ? ko : qo;
    float scale = z ? 1.0f : QSCALE;
    int cg = h * HD + threadIdx.x;
    const float* w = cw + (size_t)cg * 4;
    float y = w[3] * raw[(size_t)row * KD + cg];
    if (l >= 1) y += w[2] * raw[(size_t)(row - 1) * KD + cg];
    if (l >= 2) y += w[1] * raw[(size_t)(row - 2) * KD + cg];
    if (l >= 3) y += w[0] * raw[(size_t)(row - 3) * KD + cg];
    y = y / (1.f + expf(-y));
    float tot = blockReduceSum256(y * y, red);
    out[(size_t)row * KD + cg] = y * rsqrtf(tot + 1e-6f) * scale;
}

// padded layout: logical d -> (d>>5)*36 + (d&31); read bank = (4r+4jj)%32, conflict-free
#define PD 288
struct SBuf { float ke[3][PD]; float q[PD]; float v[64]; };

__global__ __launch_bounds__(256, 1) void scan_k(const float* __restrict__ keS,
                                                 const float* __restrict__ qn,
                                                 const float* __restrict__ vn,
                                                 const float* __restrict__ ba,
                                                 const float* __restrict__ A_log,
                                                 const float* __restrict__ dt_bias,
                                                 const int* __restrict__ modality,
                                                 const float* __restrict__ OW,
                                                 float* __restrict__ oB) {
    __shared__ SBuf sb[2];
    __shared__ float wout[3];
    __shared__ float sdec[L_ * 3];
    __shared__ float sbeta[L_ * 3];
    int bx = blockIdx.x, vt = bx & 7, h = (bx >> 3) & 7, b = bx >> 6;
    int tid = threadIdx.x, w = tid >> 5, lane = tid & 31;
    int g = lane >> 3, r = lane & 7;
    int colBase = vt * 64 + w * 8 + g * 2;
    int pdt = ((tid >> 5) * 36) + (tid & 31);
    int rb = r * 36;

    if (tid == 0) {
        float w0 = OW[h], w1 = OW[8 + h], w2 = OW[16 + h];
        float mx = fmaxf(w0, fmaxf(w1, w2));
        float e0 = expf(w0 - mx), e1 = expf(w1 - mx), e2 = expf(w2 - mx);
        float s = 1.f / (e0 + e1 + e2);
        wout[0] = e0 * s; wout[1] = e1 * s; wout[2] = e2 * s;
    }
    for (int idx = tid; idx < L_ * 3; idx += 256) {
        int t = idx / 3, e = idx - t * 3;
        int j = e * NH + h, row = b * L_ + t;
        float av = ba[row * 48 + 24 + j] + dt_bias[j];
        float sp = (av > 20.f) ? av : log1pf(expf(av));
        float gg = -expf(A_log[j]) * sp;
        float beta = 1.f / (1.f + expf(-ba[row * 48 + j]));
        int mo = modality[row];
        int m = (e == 0) ? 1 : ((e == 1) ? (mo == 0) : (mo == 1));
        sdec[idx] = m ? expf(gg) : 1.f;
        sbeta[idx] = m ? beta : 0.f;
    }

    float2 S0[3][16], S1[3][16];
    #pragma unroll
    for (int e = 0; e < 3; e++)
        #pragma unroll
        for (int j = 0; j < 16; j++) { S0[e][j] = make_float2(0.f, 0.f); S1[e][j] = make_float2(0.f, 0.f); }

    // prefetch t=0
    float pk0, pk1, pk2, pq, pv = 0.f;
    {
        size_t qoff = (size_t)(b * L_) * KD + h * HD;
        pk0 = keS[qoff + tid];
        pk1 = keS[(size_t)BL * KD + qoff + tid];
        pk2 = keS[(size_t)2 * BL * KD + qoff + tid];
        pq  = qn[qoff + tid];
        if (tid < 64) pv = vn[(size_t)(b * L_) * VD + h * DV + vt * 64 + tid];
    }

    for (int t = 0; t < L_; t++) {
        SBuf& sbuf = sb[t & 1];
        sbuf.ke[0][pdt] = pk0; sbuf.ke[1][pdt] = pk1; sbuf.ke[2][pdt] = pk2;
        sbuf.q[pdt] = pq;
        if (tid < 64) sbuf.v[tid] = pv;
        __syncthreads();
        if (t + 1 < L_) {      // overlap next-step gmem loads with compute
            int row = b * L_ + t + 1;
            size_t qoff = (size_t)row * KD + h * HD;
            pk0 = keS[qoff + tid];
            pk1 = keS[(size_t)BL * KD + qoff + tid];
            pk2 = keS[(size_t)2 * BL * KD + qoff + tid];
            pq  = qn[qoff + tid];
            if (tid < 64) pv = vn[(size_t)row * VD + h * DV + vt * 64 + tid];
        }

        float vv0 = sbuf.v[w * 8 + g * 2];
        float vv1 = sbuf.v[w * 8 + g * 2 + 1];
        float o0 = 0.f, o1 = 0.f;
        #pragma unroll
        for (int e = 0; e < 3; e++) {
            float dec = sdec[t * 3 + e], bb = sbeta[t * 3 + e], wo = wout[e];
            if (bb != 0.f) {
                float2 dec2 = make_float2(dec, dec);
                float2 kS0 = {0,0}, kS1 = {0,0}, qS0 = {0,0}, qS1 = {0,0}, qk2 = {0,0};
                #pragma unroll
                for (int jj = 0; jj < 8; jj++) {
                    float4 k4 = *reinterpret_cast<const float4*>(&sbuf.ke[e][rb + jj * 4]);
                    float4 q4 = *reinterpret_cast<const float4*>(&sbuf.q[rb + jj * 4]);
                    float2 ka = {k4.x, k4.y}, kb = {k4.z, k4.w};
                    float2 qa = {q4.x, q4.y}, qb = {q4.z, q4.w};
                    int jp = jj * 2;
                    float2 s0 = fmul2(dec2, S0[e][jp]), s1 = fmul2(dec2, S1[e][jp]);
                    kS0 = ffma2(ka, s0, kS0); kS1 = ffma2(ka, s1, kS1);
                    qS0 = ffma2(qa, s0, qS0); qS1 = ffma2(qa, s1, qS1);
                    qk2 = ffma2(qa, ka, qk2);
                    S0[e][jp] = s0; S1[e][jp] = s1;
                    float2 t0 = fmul2(dec2, S0[e][jp + 1]), t1 = fmul2(dec2, S1[e][jp + 1]);
                    kS0 = ffma2(kb, t0, kS0); kS1 = ffma2(kb, t1, kS1);
                    qS0 = ffma2(qb, t0, qS0); qS1 = ffma2(qb, t1, qS1);
                    qk2 = ffma2(qb, kb, qk2);
                    S0[e][jp + 1] = t0; S1[e][jp + 1] = t1;
                }
                float kS0s = kS0.x + kS0.y, kS1s = kS1.x + kS1.y;
                float qS0s = qS0.x + qS0.y, qS1s = qS1.x + qS1.y;
                float qks = qk2.x + qk2.y;
                #pragma unroll
                for (int off = 4; off; off >>= 1) {
                    kS0s += __shfl_xor_sync(0xffffffffu, kS0s, off);
                    kS1s += __shfl_xor_sync(0xffffffffu, kS1s, off);
                    qS0s += __shfl_xor_sync(0xffffffffu, qS0s, off);
                    qS1s += __shfl_xor_sync(0xffffffffu, qS1s, off);
                    qks  += __shfl_xor_sync(0xffffffffu, qks,  off);
                }
                float d0 = (vv0 - kS0s) * bb;
                float d1 = (vv1 - kS1s) * bb;
                float2 d0d = make_float2(d0, d0), d1d = make_float2(d1, d1);
                #pragma unroll
                for (int jj = 0; jj < 8; jj++) {
                    float4 k4 = *reinterpret_cast<const float4*>(&sbuf.ke[e][rb + jj * 4]);
                    float2 ka = {k4.x, k4.y}, kb = {k4.z, k4.w};
                    int jp = jj * 2;
                    S0[e][jp] = ffma2(ka, d0d, S0[e][jp]);
                    S1[e][jp] = ffma2(ka, d1d, S1[e][jp]);
                    S0[e][jp + 1] = ffma2(kb, d0d, S0[e][jp + 1]);
                    S1[e][jp + 1] = ffma2(kb, d1d, S1[e][jp + 1]);
                }
                o0 += wo * (qS0s + qks * d0);
                o1 += wo * (qS1s + qks * d1);
            } else {
                float2 qS0 = {0,0}, qS1 = {0,0};
                #pragma unroll
                for (int jj = 0; jj < 8; jj++) {
                    float4 q4 = *reinterpret_cast<const float4*>(&sbuf.q[rb + jj * 4]);
                    float2 qa = {q4.x, q4.y}, qb = {q4.z, q4.w};
                    int jp = jj * 2;
                    qS0 = ffma2(qa, S0[e][jp], qS0); qS1 = ffma2(qa, S1[e][jp], qS1);
                    qS0 = ffma2(qb, S0[e][jp + 1], qS0); qS1 = ffma2(qb, S1[e][jp + 1], qS1);
                }
                float qS0s = qS0.x + qS0.y, qS1s = qS1.x + qS1.y;
                #pragma unroll
                for (int off = 4; off; off >>= 1) {
                    qS0s += __shfl_xor_sync(0xffffffffu, qS0s, off);
                    qS1s += __shfl_xor_sync(0xffffffffu, qS1s, off);
                }
                o0 += wo * qS0s;
                o1 += wo * qS1s;
            }
        }
        if (r == 0) {
            int row = b * L_ + t;
            *reinterpret_cast<float2*>(&oB[(size_t)row * VD + h * DV + colBase]) = make_float2(o0, o1);
        }
    }
}

__global__ __launch_bounds__(256) void normgate_k(const float* __restrict__ oB,
                                                  const float* __restrict__ gateRaw,
                                                  const float* __restrict__ onw,
                                                  float* __restrict__ oF) {
    __shared__ float red[8];
    int row = blockIdx.x >> 3, h = blockIdx.x & 7, tid = threadIdx.x;
    size_t base = (size_t)row * VD + h * DV;
    float x0 = oB[base + tid], x1 = oB[base + tid + 256];
    float tot = blockReduceSum256(x0 * x0 + x1 * x1, red);
    float rn = rsqrtf(tot * (1.f / 512.f) + 1e-5f);
    float g0 = gateRaw[base + tid];
    float g1 = gateRaw[base + tid + 256];
    oF[base + tid]       = x0 * rn * onw[tid]       * (g0 / (1.f + expf(-g0)));
    oF[base + tid + 256] = x1 * rn * onw[tid + 256] * (g1 / (1.f + expf(-g1)));
}

extern "C" void kernel_launch(void* const* d_in, const int* in_sizes, int n_in,
                              void* d_out, int out_size) {
    const float *x, *Wq, *Wk, *Wv, *cq, *ck, *cv, *Wek, *Wb, *Wa, *Alog, *dtb, *ow, *Wg, *onw, *Wo;
    const int* mod;
    if (in_sizes[1] == 2048) {
        x = (const float*)d_in[0];  mod = (const int*)d_in[1];
        Wq = (const float*)d_in[2]; Wk = (const float*)d_in[3];
        Wv = (const float*)d_in[4]; cq = (const float*)d_in[5];
        ck = (const float*)d_in[6]; cv = (const float*)d_in[7];
        Wek = (const float*)d_in[8]; Wb = (const float*)d_in[9];
        Wa = (const float*)d_in[10]; Alog = (const float*)d_in[11];
        dtb = (const float*)d_in[12]; ow = (const float*)d_in[13];
        Wg = (const float*)d_in[14]; onw = (const float*)d_in[15];
        Wo = (const float*)d_in[16];
    } else {
        x = (const float*)d_in[0];  Wq = (const float*)d_in[1];
        Wk = (const float*)d_in[2]; Wv = (const float*)d_in[3];
        cq = (const float*)d_in[4]; ck = (const float*)d_in[5];
        cv = (const float*)d_in[6]; Wek = (const float*)d_in[7];
        Wb = (const float*)d_in[8]; Wa = (const float*)d_in[9];
        Alog = (const float*)d_in[10]; dtb = (const float*)d_in[11];
        ow = (const float*)d_in[12]; Wg = (const float*)d_in[13];
        onw = (const float*)d_in[14]; Wo = (const float*)d_in[15];
        mod = (const int*)d_in[16];
    }

    float *qraw, *kraw, *vraw, *gateraw, *q, *k, *v, *ke, *ba, *o, *of;
    cudaGetSymbolAddress((void**)&qraw, g_qraw);
    cudaGetSymbolAddress((void**)&kraw, g_kraw);
    cudaGetSymbolAddress((void**)&vraw, g_vraw);
    cudaGetSymbolAddress((void**)&gateraw, g_gateraw);
    cudaGetSymbolAddress((void**)&q, g_q);
    cudaGetSymbolAddress((void**)&k, g_k);
    cudaGetSymbolAddress((void**)&v, g_v);
    cudaGetSymbolAddress((void**)&ke, g_ke);
    cudaGetSymbolAddress((void**)&ba, g_ba);
    cudaGetSymbolAddress((void**)&o, g_o);
    cudaGetSymbolAddress((void**)&of, g_of);

    proj_gemm<<<dim3(98, 16), 256>>>(x, Wq, Wk, Wv, Wg, Wb, Wa, qraw, kraw, vraw, gateraw, ba);
    conv_all<<<dim3(BL, NH, 3), 256>>>(qraw, kraw, vraw, cq, ck, cv, q, k, v);
    ke_gemm<<<dim3(2, 16, 24), 256>>>(k, Wek, ke);
    scan_k<<<128, 256>>>(ke, q, v, ba, Alog, dtb, mod, ow, o);   // 4th launch -> profiled
    normgate_k<<<BL * NH, 256>>>(o, gateraw, onw, of);
    gemm_nt<<<dim3(16, 16), 256>>>(of, Wo, (float*)d_out, VD, VD, VD, HS);
}

// round 12
// speedup vs baseline: 1.8163x; 1.1136x over previous
#include <cuda_runtime.h>
#include <cuda_bf16.h>
#include <cstdint>

#define B_ 2
#define L_ 1024
#define BL 2048
#define HS 2048
#define NH 8
#define HD 256
#define DV 512
#define KD 2048
#define VD 4096
#define E_ 3
#define QSCALE 0.0625f

__device__ float g_qraw[BL * KD];
__device__ float g_kraw[BL * KD];
__device__ float g_vraw[BL * VD];
__device__ float g_gateraw[BL * VD];
__device__ float g_q[BL * KD];
__device__ float g_k[BL * KD];
__device__ float g_v[BL * VD];
__device__ float g_ke[E_ * BL * KD];
__device__ float g_ba[BL * 48];
__device__ float g_oE[3 * BL * VD];
__device__ float g_of[BL * VD];

__device__ __forceinline__ float2 ffma2(float2 a, float2 b, float2 c) {
    unsigned long long au = *reinterpret_cast<unsigned long long*>(&a);
    unsigned long long bu = *reinterpret_cast<unsigned long long*>(&b);
    unsigned long long cu = *reinterpret_cast<unsigned long long*>(&c);
    unsigned long long du;
    asm("fma.rn.f32x2 %0, %1, %2, %3;" : "=l"(du) : "l"(au), "l"(bu), "l"(cu));
    return *reinterpret_cast<float2*>(&du);
}
__device__ __forceinline__ float2 fmul2(float2 a, float2 b) {
    unsigned long long au = *reinterpret_cast<unsigned long long*>(&a);
    unsigned long long bu = *reinterpret_cast<unsigned long long*>(&b);
    unsigned long long du;
    asm("mul.rn.f32x2 %0, %1, %2;" : "=l"(du) : "l"(au), "l"(bu));
    return *reinterpret_cast<float2*>(&du);
}

__device__ __forceinline__ float blockReduceSum256(float v, float* red) {
    int tid = threadIdx.x;
    #pragma unroll
    for (int off = 16; off; off >>= 1) v += __shfl_xor_sync(0xffffffffu, v, off);
    if ((tid & 31) == 0) red[tid >> 5] = v;
    __syncthreads();
    return red[0] + red[1] + red[2] + red[3] + red[4] + red[5] + red[6] + red[7];
}

// C[m,n] = A[m,k]*B[n,k], 128x128 tile, K%16==0. Relies on 2 CTA/SM for latency hiding.
__device__ __forceinline__ void gemm128_body(const float* __restrict__ A, int lda,
                                             const float* __restrict__ B, int ldb,
                                             float* __restrict__ C, int ldc, int K,
                                             float (*As)[132], float (*Bs)[132]) {
    int tid = threadIdx.x;
    int w = tid >> 5, lane = tid & 31;
    int tm8 = (((w >> 1) << 2) + (lane >> 3)) << 3;
    int tn8 = (((w & 1) << 3) + (lane & 7)) << 3;
    int r0 = tid >> 2, c4 = (tid & 3) * 4;
    int r1 = r0 + 64;
    float2 acc[8][4];
    #pragma unroll
    for (int i = 0; i < 8; i++)
        #pragma unroll
        for (int j = 0; j < 4; j++) acc[i][j] = make_float2(0.f, 0.f);

    for (int k0 = 0; k0 < K; k0 += 16) {
        if (k0) __syncthreads();
        float4 a0v = *reinterpret_cast<const float4*>(A + (size_t)r0 * lda + k0 + c4);
        float4 b0v = *reinterpret_cast<const float4*>(B + (size_t)r0 * ldb + k0 + c4);
        float4 a1v = *reinterpret_cast<const float4*>(A + (size_t)r1 * lda + k0 + c4);
        float4 b1v = *reinterpret_cast<const float4*>(B + (size_t)r1 * ldb + k0 + c4);
        As[c4][r0] = a0v.x; As[c4 + 1][r0] = a0v.y; As[c4 + 2][r0] = a0v.z; As[c4 + 3][r0] = a0v.w;
        Bs[c4][r0] = b0v.x; Bs[c4 + 1][r0] = b0v.y; Bs[c4 + 2][r0] = b0v.z; Bs[c4 + 3][r0] = b0v.w;
        As[c4][r1] = a1v.x; As[c4 + 1][r1] = a1v.y; As[c4 + 2][r1] = a1v.z; As[c4 + 3][r1] = a1v.w;
        Bs[c4][r1] = b1v.x; Bs[c4 + 1][r1] = b1v.y; Bs[c4 + 2][r1] = b1v.z; Bs[c4 + 3][r1] = b1v.w;
        __syncthreads();
        #pragma unroll
        for (int kk = 0; kk < 16; kk++) {
            float4 a0 = *reinterpret_cast<const float4*>(&As[kk][tm8]);
            float4 a1 = *reinterpret_cast<const float4*>(&As[kk][tm8 + 4]);
            float4 b0 = *reinterpret_cast<const float4*>(&Bs[kk][tn8]);
            float4 b1 = *reinterpret_cast<const float4*>(&Bs[kk][tn8 + 4]);
            float2 bb[4] = { {b0.x,b0.y},{b0.z,b0.w},{b1.x,b1.y},{b1.z,b1.w} };
            float ar[8] = { a0.x,a0.y,a0.z,a0.w,a1.x,a1.y,a1.z,a1.w };
            #pragma unroll
            for (int i = 0; i < 8; i++) {
                float2 ad = make_float2(ar[i], ar[i]);
                #pragma unroll
                for (int j = 0; j < 4; j++) acc[i][j] = ffma2(ad, bb[j], acc[i][j]);
            }
        }
    }
    #pragma unroll
    for (int i = 0; i < 8; i++) {
        float* cp = C + (size_t)(tm8 + i) * ldc + tn8;
        *reinterpret_cast<float4*>(cp)     = make_float4(acc[i][0].x, acc[i][0].y, acc[i][1].x, acc[i][1].y);
        *reinterpret_cast<float4*>(cp + 4) = make_float4(acc[i][2].x, acc[i][2].y, acc[i][3].x, acc[i][3].y);
    }
}

// fused 5-way: nt 0..15 Wq, 16..31 Wk, 32..63 Wv, 64..95 Wg, 96..97 ba tile
__global__ __launch_bounds__(256, 2) void proj_gemm(const float* __restrict__ x,
                                                    const float* __restrict__ Wq,
                                                    const float* __restrict__ Wk,
                                                    const float* __restrict__ Wv,
                                                    const float* __restrict__ Wg,
                                                    const float* __restrict__ Wb,
                                                    const float* __restrict__ Wa,
                                                    float* __restrict__ qraw,
                                                    float* __restrict__ kraw,
                                                    float* __restrict__ vraw,
                                                    float* __restrict__ graw,
                                                    float* __restrict__ ba) {
    __shared__ float smem[5056];
    int nt = blockIdx.x;
    if (nt < 96) {
        float (*As)[132] = reinterpret_cast<float(*)[132]>(smem);
        float (*Bs)[132] = reinterpret_cast<float(*)[132]>(smem + 2112);
        const float* Bm; float* C; int ldc, nl;
        if (nt < 16)      { Bm = Wq; C = qraw; ldc = KD; nl = nt; }
        else if (nt < 32) { Bm = Wk; C = kraw; ldc = KD; nl = nt - 16; }
        else if (nt < 64) { Bm = Wv; C = vraw; ldc = VD; nl = nt - 32; }
        else              { Bm = Wg; C = graw; ldc = VD; nl = nt - 64; }
        gemm128_body(x + (size_t)blockIdx.y * 128 * HS, HS,
                     Bm + (size_t)nl * 128 * HS, HS,
                     C + (size_t)blockIdx.y * 128 * ldc + nl * 128, ldc, HS, As, Bs);
        return;
    }
    float (*xs)[66] = reinterpret_cast<float(*)[66]>(smem);   // 64*66 = 4224
    float* wsf = smem + 4224;                                  // 48*17 = 816 -> 5040
    int tid = threadIdx.x;
    int m0 = blockIdx.y * 128 + (nt - 96) * 64;
    int tm = tid >> 4, tn = tid & 15;
    float acc[4][3] = {};
    for (int k0 = 0; k0 < HS; k0 += 16) {
        if (k0) __syncthreads();
        #pragma unroll
        for (int it = 0; it < 4; it++) {
            int qq = tid + it * 256;
            int r = qq >> 4, c = qq & 15;
            xs[r][c] = x[(size_t)(m0 + r) * HS + k0 + c];
            if (qq < 768) {
                const float* W = (r < 24) ? (Wb + (size_t)r * HS) : (Wa + (size_t)(r - 24) * HS);
                wsf[r * 17 + c] = W[k0 + c];
            }
        }
        __syncthreads();
        #pragma unroll
        for (int kk = 0; kk < 16; kk++) {
            float xv[4], wv[3];
            #pragma unroll
            for (int i = 0; i < 4; i++) xv[i] = xs[tm * 4 + i][kk];
            #pragma unroll
            for (int j = 0; j < 3; j++) wv[j] = wsf[(tn * 3 + j) * 17 + kk];
            #pragma unroll
            for (int i = 0; i < 4; i++)
                #pragma unroll
                for (int j = 0; j < 3; j++) acc[i][j] += xv[i] * wv[j];
        }
    }
    #pragma unroll
    for (int i = 0; i < 4; i++)
        #pragma unroll
        for (int j = 0; j < 3; j++)
            ba[(size_t)(m0 + tm * 4 + i) * 48 + tn * 3 + j] = acc[i][j];
}

__global__ __launch_bounds__(256, 2) void gemm_nt(const float* __restrict__ A,
                                                  const float* __restrict__ B,
                                                  float* __restrict__ C,
                                                  int K, int lda, int ldb, int ldc) {
    __shared__ float As[16][132];
    __shared__ float Bs[16][132];
    gemm128_body(A + (size_t)blockIdx.y * 128 * lda, lda,
                 B + (size_t)blockIdx.x * 128 * ldb, ldb,
                 C + (size_t)blockIdx.y * 128 * ldc + blockIdx.x * 128, ldc, K, As, Bs);
}

__global__ __launch_bounds__(256, 2) void ke_gemm(const float* __restrict__ Kn,
                                                  const float* __restrict__ Wek,
                                                  float* __restrict__ KeOut) {
    __shared__ float As[16][132];
    __shared__ float Bs[16][132];
    int z = blockIdx.z, e = z >> 3, h = z & 7;
    int n0 = blockIdx.x * 128, m0 = blockIdx.y * 128;
    gemm128_body(Kn + (size_t)m0 * KD + h * HD, KD,
                 Wek + (size_t)z * HD * HD + (size_t)n0 * HD, HD,
                 KeOut + (size_t)e * BL * KD + (size_t)m0 * KD + h * HD + n0, KD, HD, As, Bs);
}

// fused conv+silu(+l2norm) : z=0 q, z=1 k (norm), z=2 v
__global__ __launch_bounds__(256) void conv_all(const float* __restrict__ qraw,
                                                const float* __restrict__ kraw,
                                                const float* __restrict__ vraw,
                                                const float* __restrict__ cq,
                                                const float* __restrict__ ck,
                                                const float* __restrict__ cv,
                                                float* __restrict__ qo,
                                                float* __restrict__ ko,
                                                float* __restrict__ vo) {
    __shared__ float red[8];
    int z = blockIdx.z;
    int row = blockIdx.x, h = blockIdx.y, l = row & (L_ - 1);
    if (z == 2) {
        #pragma unroll
        for (int u = 0; u < 2; u++) {
            int c = h * DV + threadIdx.x + u * 256;
            size_t idx = (size_t)row * VD + c;
            const float* w = cv + (size_t)c * 4;
            float y = w[3] * vraw[idx];
            if (l >= 1) y += w[2] * vraw[idx - VD];
            if (l >= 2) y += w[1] * vraw[idx - 2 * VD];
            if (l >= 3) y += w[0] * vraw[idx - 3 * VD];
            vo[idx] = y / (1.f + expf(-y));
        }
        return;
    }
    const float* raw = z ? kraw : qraw;
    const float* cw = z ? ck : cq;
    float* out = z ? ko : qo;
    float scale = z ? 1.0f : QSCALE;
    int cg = h * HD + threadIdx.x;
    const float* w = cw + (size_t)cg * 4;
    float y = w[3] * raw[(size_t)row * KD + cg];
    if (l >= 1) y += w[2] * raw[(size_t)(row - 1) * KD + cg];
    if (l >= 2) y += w[1] * raw[(size_t)(row - 2) * KD + cg];
    if (l >= 3) y += w[0] * raw[(size_t)(row - 3) * KD + cg];
    y = y / (1.f + expf(-y));
    float tot = blockReduceSum256(y * y, red);
    out[(size_t)row * KD + cg] = y * rsqrtf(tot + 1e-6f) * scale;
}

// per-expert scan: 384 CTAs = (e, b, h, vt). One expert's state per CTA -> 64 state regs.
#define PD 288
struct SBufE { float ke[PD]; float q[PD]; float v[64]; };

__global__ __launch_bounds__(256, 2) void scan_k(const float* __restrict__ keS,
                                                 const float* __restrict__ qn,
                                                 const float* __restrict__ vn,
                                                 const float* __restrict__ ba,
                                                 const float* __restrict__ A_log,
                                                 const float* __restrict__ dt_bias,
                                                 const int* __restrict__ modality,
                                                 const float* __restrict__ OW,
                                                 float* __restrict__ oEbuf) {
    __shared__ SBufE sb[2];
    __shared__ float sdec[L_];
    __shared__ float sbeta[L_];
    int bx = blockIdx.x, vt = bx & 7, h = (bx >> 3) & 7, b = (bx >> 6) & 1, e = bx >> 7;
    int tid = threadIdx.x, w = tid >> 5, lane = tid & 31;
    int g = lane >> 3, r = lane & 7;
    int colBase = vt * 64 + w * 8 + g * 2;
    int pdt = ((tid >> 5) * 36) + (tid & 31);
    int rb = r * 36;

    // softmax weight for (e,h) — computed per-thread, no smem needed
    float w0 = OW[h], w1 = OW[8 + h], w2 = OW[16 + h];
    float mx = fmaxf(w0, fmaxf(w1, w2));
    float e0 = expf(w0 - mx), e1 = expf(w1 - mx), e2 = expf(w2 - mx);
    float wo = ((e == 0) ? e0 : (e == 1) ? e1 : e2) / (e0 + e1 + e2);

    // gating table for this (e,b,h)
    int j = e * NH + h;
    float Ae = expf(A_log[j]), dtb_j = dt_bias[j];
    for (int idx = tid; idx < L_; idx += 256) {
        int row = b * L_ + idx;
        float av = ba[row * 48 + 24 + j] + dtb_j;
        float sp = (av > 20.f) ? av : log1pf(expf(av));
        float beta = 1.f / (1.f + expf(-ba[row * 48 + j]));
        int mo = modality[row];
        int m = (e == 0) ? 1 : ((e == 1) ? (mo == 0) : (mo == 1));
        sdec[idx] = m ? expf(-Ae * sp) : 1.f;
        sbeta[idx] = m ? beta : 0.f;
    }

    float2 S0[16], S1[16];
    #pragma unroll
    for (int jj = 0; jj < 16; jj++) { S0[jj] = make_float2(0.f, 0.f); S1[jj] = make_float2(0.f, 0.f); }

    const float* keE = keS + (size_t)e * BL * KD;
    float* oE = oEbuf + (size_t)e * BL * VD;

    // prefetch t=0
    float pk, pq, pv = 0.f;
    {
        size_t qoff = (size_t)(b * L_) * KD + h * HD;
        pk = keE[qoff + tid];
        pq = qn[qoff + tid];
        if (tid < 64) pv = vn[(size_t)(b * L_) * VD + h * DV + vt * 64 + tid];
    }

    for (int t = 0; t < L_; t++) {
        SBufE& sbuf = sb[t & 1];
        sbuf.ke[pdt] = pk;
        sbuf.q[pdt] = pq;
        if (tid < 64) sbuf.v[tid] = pv;
        __syncthreads();
        if (t + 1 < L_) {
            int row = b * L_ + t + 1;
            size_t qoff = (size_t)row * KD + h * HD;
            pk = keE[qoff + tid];
            pq = qn[qoff + tid];
            if (tid < 64) pv = vn[(size_t)row * VD + h * DV + vt * 64 + tid];
        }

        float dec = sdec[t], bb = sbeta[t];
        float o0, o1;
        if (bb != 0.f) {
            float vv0 = sbuf.v[w * 8 + g * 2];
            float vv1 = sbuf.v[w * 8 + g * 2 + 1];
            float2 dec2 = make_float2(dec, dec);
            float2 kS0 = {0,0}, kS1 = {0,0}, qS0 = {0,0}, qS1 = {0,0}, qk2 = {0,0};
            #pragma unroll
            for (int jj = 0; jj < 8; jj++) {
                float4 k4 = *reinterpret_cast<const float4*>(&sbuf.ke[rb + jj * 4]);
                float4 q4 = *reinterpret_cast<const float4*>(&sbuf.q[rb + jj * 4]);
                float2 ka = {k4.x, k4.y}, kb = {k4.z, k4.w};
                float2 qa = {q4.x, q4.y}, qb = {q4.z, q4.w};
                int jp = jj * 2;
                float2 s0 = fmul2(dec2, S0[jp]), s1 = fmul2(dec2, S1[jp]);
                kS0 = ffma2(ka, s0, kS0); kS1 = ffma2(ka, s1, kS1);
                qS0 = ffma2(qa, s0, qS0); qS1 = ffma2(qa, s1, qS1);
                qk2 = ffma2(qa, ka, qk2);
                S0[jp] = s0; S1[jp] = s1;
                float2 t0 = fmul2(dec2, S0[jp + 1]), t1 = fmul2(dec2, S1[jp + 1]);
                kS0 = ffma2(kb, t0, kS0); kS1 = ffma2(kb, t1, kS1);
                qS0 = ffma2(qb, t0, qS0); qS1 = ffma2(qb, t1, qS1);
                qk2 = ffma2(qb, kb, qk2);
                S0[jp + 1] = t0; S1[jp + 1] = t1;
            }
            float kS0s = kS0.x + kS0.y, kS1s = kS1.x + kS1.y;
            float qS0s = qS0.x + qS0.y, qS1s = qS1.x + qS1.y;
            float qks = qk2.x + qk2.y;
            #pragma unroll
            for (int off = 4; off; off >>= 1) {
                kS0s += __shfl_xor_sync(0xffffffffu, kS0s, off);
                kS1s += __shfl_xor_sync(0xffffffffu, kS1s, off);
                qS0s += __shfl_xor_sync(0xffffffffu, qS0s, off);
                qS1s += __shfl_xor_sync(0xffffffffu, qS1s, off);
                qks  += __shfl_xor_sync(0xffffffffu, qks,  off);
            }
            float d0 = (vv0 - kS0s) * bb;
            float d1 = (vv1 - kS1s) * bb;
            float2 d0d = make_float2(d0, d0), d1d = make_float2(d1, d1);
            #pragma unroll
            for (int jj = 0; jj < 8; jj++) {
                float4 k4 = *reinterpret_cast<const float4*>(&sbuf.ke[rb + jj * 4]);
                float2 ka = {k4.x, k4.y}, kb = {k4.z, k4.w};
                int jp = jj * 2;
                S0[jp] = ffma2(ka, d0d, S0[jp]);
                S1[jp] = ffma2(ka, d1d, S1[jp]);
                S0[jp + 1] = ffma2(kb, d0d, S0[jp + 1]);
                S1[jp + 1] = ffma2(kb, d1d, S1[jp + 1]);
            }
            o0 = wo * (qS0s + qks * d0);
            o1 = wo * (qS1s + qks * d1);
        } else {
            float2 qS0 = {0,0}, qS1 = {0,0};
            #pragma unroll
            for (int jj = 0; jj < 8; jj++) {
                float4 q4 = *reinterpret_cast<const float4*>(&sbuf.q[rb + jj * 4]);
                float2 qa = {q4.x, q4.y}, qb = {q4.z, q4.w};
                int jp = jj * 2;
                qS0 = ffma2(qa, S0[jp], qS0); qS1 = ffma2(qa, S1[jp], qS1);
                qS0 = ffma2(qb, S0[jp + 1], qS0); qS1 = ffma2(qb, S1[jp + 1], qS1);
            }
            float qS0s = qS0.x + qS0.y, qS1s = qS1.x + qS1.y;
            #pragma unroll
            for (int off = 4; off; off >>= 1) {
                qS0s += __shfl_xor_sync(0xffffffffu, qS0s, off);
                qS1s += __shfl_xor_sync(0xffffffffu, qS1s, off);
            }
            o0 = wo * qS0s;
            o1 = wo * qS1s;
        }
        if (r == 0) {
            int row = b * L_ + t;
            *reinterpret_cast<float2*>(&oE[(size_t)row * VD + h * DV + colBase]) = make_float2(o0, o1);
        }
    }
}

__global__ __launch_bounds__(256) void normgate_k(const float* __restrict__ oEbuf,
                                                  const float* __restrict__ gateRaw,
                                                  const float* __restrict__ onw,
                                                  float* __restrict__ oF) {
    __shared__ float red[8];
    int row = blockIdx.x >> 3, h = blockIdx.x & 7, tid = threadIdx.x;
    size_t base = (size_t)row * VD + h * DV;
    const float* o0p = oEbuf;
    const float* o1p = oEbuf + (size_t)BL * VD;
    const float* o2p = oEbuf + (size_t)2 * BL * VD;
    float x0 = o0p[base + tid] + o1p[base + tid] + o2p[base + tid];
    float x1 = o0p[base + tid + 256] + o1p[base + tid + 256] + o2p[base + tid + 256];
    float tot = blockReduceSum256(x0 * x0 + x1 * x1, red);
    float rn = rsqrtf(tot * (1.f / 512.f) + 1e-5f);
    float g0 = gateRaw[base + tid];
    float g1 = gateRaw[base + tid + 256];
    oF[base + tid]       = x0 * rn * onw[tid]       * (g0 / (1.f + expf(-g0)));
    oF[base + tid + 256] = x1 * rn * onw[tid + 256] * (g1 / (1.f + expf(-g1)));
}

extern "C" void kernel_launch(void* const* d_in, const int* in_sizes, int n_in,
                              void* d_out, int out_size) {
    const float *x, *Wq, *Wk, *Wv, *cq, *ck, *cv, *Wek, *Wb, *Wa, *Alog, *dtb, *ow, *Wg, *onw, *Wo;
    const int* mod;
    if (in_sizes[1] == 2048) {
        x = (const float*)d_in[0];  mod = (const int*)d_in[1];
        Wq = (const float*)d_in[2]; Wk = (const float*)d_in[3];
        Wv = (const float*)d_in[4]; cq = (const float*)d_in[5];
        ck = (const float*)d_in[6]; cv = (const float*)d_in[7];
        Wek = (const float*)d_in[8]; Wb = (const float*)d_in[9];
        Wa = (const float*)d_in[10]; Alog = (const float*)d_in[11];
        dtb = (const float*)d_in[12]; ow = (const float*)d_in[13];
        Wg = (const float*)d_in[14]; onw = (const float*)d_in[15];
        Wo = (const float*)d_in[16];
    } else {
        x = (const float*)d_in[0];  Wq = (const float*)d_in[1];
        Wk = (const float*)d_in[2]; Wv = (const float*)d_in[3];
        cq = (const float*)d_in[4]; ck = (const float*)d_in[5];
        cv = (const float*)d_in[6]; Wek = (const float*)d_in[7];
        Wb = (const float*)d_in[8]; Wa = (const float*)d_in[9];
        Alog = (const float*)d_in[10]; dtb = (const float*)d_in[11];
        ow = (const float*)d_in[12]; Wg = (const float*)d_in[13];
        onw = (const float*)d_in[14]; Wo = (const float*)d_in[15];
        mod = (const int*)d_in[16];
    }

    float *qraw, *kraw, *vraw, *gateraw, *q, *k, *v, *ke, *ba, *oE, *of;
    cudaGetSymbolAddress((void**)&qraw, g_qraw);
    cudaGetSymbolAddress((void**)&kraw, g_kraw);
    cudaGetSymbolAddress((void**)&vraw, g_vraw);
    cudaGetSymbolAddress((void**)&gateraw, g_gateraw);
    cudaGetSymbolAddress((void**)&q, g_q);
    cudaGetSymbolAddress((void**)&k, g_k);
    cudaGetSymbolAddress((void**)&v, g_v);
    cudaGetSymbolAddress((void**)&ke, g_ke);
    cudaGetSymbolAddress((void**)&ba, g_ba);
    cudaGetSymbolAddress((void**)&oE, g_oE);
    cudaGetSymbolAddress((void**)&of, g_of);

    proj_gemm<<<dim3(98, 16), 256>>>(x, Wq, Wk, Wv, Wg, Wb, Wa, qraw, kraw, vraw, gateraw, ba);
    conv_all<<<dim3(BL, NH, 3), 256>>>(qraw, kraw, vraw, cq, ck, cv, q, k, v);
    ke_gemm<<<dim3(2, 16, 24), 256>>>(k, Wek, ke);
    scan_k<<<384, 256>>>(ke, q, v, ba, Alog, dtb, mod, ow, oE);   // 4th launch -> profiled
    normgate_k<<<BL * NH, 256>>>(oE, gateraw, onw, of);
    gemm_nt<<<dim3(16, 16), 256>>>(of, Wo, (float*)d_out, VD, VD, VD, HS);
}

// round 14
// speedup vs baseline: 2.4790x; 1.3649x over previous
#include <cuda_runtime.h>
#include <cuda_bf16.h>
#include <cstdint>

#define B_ 2
#define L_ 1024
#define BL 2048
#define HS 2048
#define NH 8
#define HD 256
#define DV 512
#define KD 2048
#define VD 4096
#define E_ 3
#define QSCALE 0.0625f

__device__ float g_qraw[BL * KD];
__device__ float g_kraw[BL * KD];
__device__ float g_vraw[BL * VD];
__device__ float g_gateraw[BL * VD];
__device__ float g_q[BL * KD];
__device__ float g_k[BL * KD];
__device__ float g_v[BL * VD];
__device__ float g_ke[E_ * BL * KD];
__device__ float g_ba[BL * 48];
__device__ float g_oE[3 * BL * VD];
__device__ float g_of[BL * VD];

__device__ __forceinline__ float2 ffma2(float2 a, float2 b, float2 c) {
    unsigned long long au = *reinterpret_cast<unsigned long long*>(&a);
    unsigned long long bu = *reinterpret_cast<unsigned long long*>(&b);
    unsigned long long cu = *reinterpret_cast<unsigned long long*>(&c);
    unsigned long long du;
    asm("fma.rn.f32x2 %0, %1, %2, %3;" : "=l"(du) : "l"(au), "l"(bu), "l"(cu));
    return *reinterpret_cast<float2*>(&du);
}
__device__ __forceinline__ float2 fmul2(float2 a, float2 b) {
    unsigned long long au = *reinterpret_cast<unsigned long long*>(&a);
    unsigned long long bu = *reinterpret_cast<unsigned long long*>(&b);
    unsigned long long du;
    asm("mul.rn.f32x2 %0, %1, %2;" : "=l"(du) : "l"(au), "l"(bu));
    return *reinterpret_cast<float2*>(&du);
}

__device__ __forceinline__ float blockReduceSum256(float v, float* red) {
    int tid = threadIdx.x;
    #pragma unroll
    for (int off = 16; off; off >>= 1) v += __shfl_xor_sync(0xffffffffu, v, off);
    if ((tid & 31) == 0) red[tid >> 5] = v;
    __syncthreads();
    return red[0] + red[1] + red[2] + red[3] + red[4] + red[5] + red[6] + red[7];
}

// ---------------- bf16x3 tensor-core GEMM: C[128m x 64n] = A[m,k]*B[n,k] ----------------
#define LDSM4(R0, R1, R2, R3, addr) \
    asm volatile("ldmatrix.sync.aligned.m8n8.x4.shared.b16 {%0,%1,%2,%3}, [%4];" \
                 : "=r"(R0), "=r"(R1), "=r"(R2), "=r"(R3) : "r"(addr))

#define MMA16816(D, A, B) \
    asm volatile("mma.sync.aligned.m16n8k16.row.col.f32.bf16.bf16.f32 " \
                 "{%0,%1,%2,%3}, {%4,%5,%6,%7}, {%8,%9}, {%0,%1,%2,%3};" \
                 : "+f"(D[0]), "+f"(D[1]), "+f"(D[2]), "+f"(D[3]) \
                 : "r"(A[0]), "r"(A[1]), "r"(A[2]), "r"(A[3]), "r"(B[0]), "r"(B[1]))

#define SMEM_BYTES 30720   // sAh 10240 + sAl 10240 + sBh 5120 + sBl 5120

__device__ __forceinline__ void cvt_store2(__nv_bfloat16* sh, __nv_bfloat16* sl,
                                           int off, float f0, float f1) {
    __nv_bfloat16 h0 = __float2bfloat16(f0), h1 = __float2bfloat16(f1);
    __nv_bfloat162 hp; hp.x = h0; hp.y = h1;
    __nv_bfloat162 lp;
    lp.x = __float2bfloat16(f0 - __bfloat162float(h0));
    lp.y = __float2bfloat16(f1 - __bfloat162float(h1));
    *reinterpret_cast<__nv_bfloat162*>(sh + off) = hp;
    *reinterpret_cast<__nv_bfloat162*>(sl + off) = lp;
}

__device__ __forceinline__ void mma_body(const float* __restrict__ A, int lda,
                                         const float* __restrict__ B, int ldb,
                                         float* __restrict__ C, int ldc, int K,
                                         char* smem) {
    __nv_bfloat16* sAh = reinterpret_cast<__nv_bfloat16*>(smem);          // [128][40]
    __nv_bfloat16* sAl = sAh + 128 * 40;
    __nv_bfloat16* sBh = sAl + 128 * 40;                                   // [64][40]
    __nv_bfloat16* sBl = sBh + 64 * 40;
    int tid = threadIdx.x, lane = tid & 31, wid = tid >> 5;
    int wm = wid >> 1, wn = wid & 1;
    int arow = tid >> 1, acol = (tid & 1) * 16;
    int brow = tid >> 2, bcol = (tid & 3) * 8;
    // ldmatrix per-lane row/col within a tile
    int aRow = (lane & 7) + ((lane >> 3) & 1) * 8;
    int aCol = ((lane >> 4) & 1) * 8;
    int bRow = (lane & 7) + ((lane >> 4) & 1) * 8;
    int bCol = ((lane >> 3) & 1) * 8;

    float d[2][4][4];
    #pragma unroll
    for (int i = 0; i < 2; i++)
        #pragma unroll
        for (int j = 0; j < 4; j++)
            #pragma unroll
            for (int q = 0; q < 4; q++) d[i][j][q] = 0.f;

    for (int k0 = 0; k0 < K; k0 += 32) {
        if (k0) __syncthreads();
        #pragma unroll
        for (int i = 0; i < 4; i++) {
            float4 av = *reinterpret_cast<const float4*>(A + (size_t)arow * lda + k0 + acol + i * 4);
            int off = arow * 40 + acol + i * 4;
            cvt_store2(sAh, sAl, off, av.x, av.y);
            cvt_store2(sAh, sAl, off + 2, av.z, av.w);
        }
        #pragma unroll
        for (int i = 0; i < 2; i++) {
            float4 bv = *reinterpret_cast<const float4*>(B + (size_t)brow * ldb + k0 + bcol + i * 4);
            int off = brow * 40 + bcol + i * 4;
            cvt_store2(sBh, sBl, off, bv.x, bv.y);
            cvt_store2(sBh, sBl, off + 2, bv.z, bv.w);
        }
        __syncthreads();
        #pragma unroll
        for (int kk = 0; kk < 32; kk += 16) {
            uint32_t Ah[2][4], Al[2][4], Bh[4][2], Bl[4][2];
            #pragma unroll
            for (int mt = 0; mt < 2; mt++) {
                int idx = (wm * 32 + mt * 16 + aRow) * 40 + kk + aCol;
                uint32_t ah = (uint32_t)__cvta_generic_to_shared(sAh + idx);
                uint32_t al = (uint32_t)__cvta_generic_to_shared(sAl + idx);
                LDSM4(Ah[mt][0], Ah[mt][1], Ah[mt][2], Ah[mt][3], ah);
                LDSM4(Al[mt][0], Al[mt][1], Al[mt][2], Al[mt][3], al);
            }
            #pragma unroll
            for (int bp = 0; bp < 2; bp++) {
                int idx = (wn * 32 + bp * 16 + bRow) * 40 + kk + bCol;
                uint32_t bh = (uint32_t)__cvta_generic_to_shared(sBh + idx);
                uint32_t bl = (uint32_t)__cvta_generic_to_shared(sBl + idx);
                LDSM4(Bh[2 * bp][0], Bh[2 * bp][1], Bh[2 * bp + 1][0], Bh[2 * bp + 1][1], bh);
                LDSM4(Bl[2 * bp][0], Bl[2 * bp][1], Bl[2 * bp + 1][0], Bl[2 * bp + 1][1], bl);
            }
            #pragma unroll
            for (int mt = 0; mt < 2; mt++)
                #pragma unroll
                for (int nt = 0; nt < 4; nt++) {
                    MMA16816(d[mt][nt], Ah[mt], Bh[nt]);
                    MMA16816(d[mt][nt], Al[mt], Bh[nt]);
                    MMA16816(d[mt][nt], Ah[mt], Bl[nt]);
                }
        }
    }
    #pragma unroll
    for (int mt = 0; mt < 2; mt++)
        #pragma unroll
        for (int nt = 0; nt < 4; nt++) {
            int row = wm * 32 + mt * 16 + (lane >> 2);
            int col = wn * 32 + nt * 8 + (lane & 3) * 2;
            *reinterpret_cast<float2*>(C + (size_t)row * ldc + col) =
                make_float2(d[mt][nt][0], d[mt][nt][1]);
            *reinterpret_cast<float2*>(C + (size_t)(row + 8) * ldc + col) =
                make_float2(d[mt][nt][2], d[mt][nt][3]);
        }
}

__global__ __launch_bounds__(256, 2) void mma_gemm_nt(const float* __restrict__ A,
                                                      const float* __restrict__ B,
                                                      float* __restrict__ C,
                                                      int K, int lda, int ldb, int ldc) {
    __shared__ __align__(16) char smem[SMEM_BYTES];
    mma_body(A + (size_t)blockIdx.y * 128 * lda, lda,
             B + (size_t)blockIdx.x * 64 * ldb, ldb,
             C + (size_t)blockIdx.y * 128 * ldc + blockIdx.x * 64, ldc, K, smem);
}

// Wg gemm (nt<64) fused with ba projection tiles (nt 64,65)
__global__ __launch_bounds__(256, 2) void mma_wg_ba(const float* __restrict__ x,
                                                    const float* __restrict__ Wg,
                                                    const float* __restrict__ Wb,
                                                    const float* __restrict__ Wa,
                                                    float* __restrict__ graw,
                                                    float* __restrict__ ba) {
    __shared__ __align__(16) char smem[SMEM_BYTES];
    int nt = blockIdx.x;
    if (nt < 64) {
        mma_body(x + (size_t)blockIdx.y * 128 * HS, HS,
                 Wg + (size_t)nt * 64 * HS, HS,
                 graw + (size_t)blockIdx.y * 128 * VD + nt * 64, VD, HS, smem);
        return;
    }
    float* smemF = reinterpret_cast<float*>(smem);
    float (*xs)[66] = reinterpret_cast<float(*)[66]>(smemF);  // 64*66 = 4224
    float* wsf = smemF + 4224;                                 // 48*17 = 816 -> 5040 floats
    int tid = threadIdx.x;
    int m0 = blockIdx.y * 128 + (nt - 64) * 64;
    int tm = tid >> 4, tn = tid & 15;
    float acc[4][3] = {};
    for (int k0 = 0; k0 < HS; k0 += 16) {
        if (k0) __syncthreads();
        #pragma unroll
        for (int it = 0; it < 4; it++) {
            int qq = tid + it * 256;
            int r = qq >> 4, c = qq & 15;
            xs[r][c] = x[(size_t)(m0 + r) * HS + k0 + c];
            if (qq < 768) {
                const float* W = (r < 24) ? (Wb + (size_t)r * HS) : (Wa + (size_t)(r - 24) * HS);
                wsf[r * 17 + c] = W[k0 + c];
            }
        }
        __syncthreads();
        #pragma unroll
        for (int kk = 0; kk < 16; kk++) {
            float xv[4], wv[3];
            #pragma unroll
            for (int i = 0; i < 4; i++) xv[i] = xs[tm * 4 + i][kk];
            #pragma unroll
            for (int j = 0; j < 3; j++) wv[j] = wsf[(tn * 3 + j) * 17 + kk];
            #pragma unroll
            for (int i = 0; i < 4; i++)
                #pragma unroll
                for (int j = 0; j < 3; j++) acc[i][j] += xv[i] * wv[j];
        }
    }
    #pragma unroll
    for (int i = 0; i < 4; i++)
        #pragma unroll
        for (int j = 0; j < 3; j++)
            ba[(size_t)(m0 + tm * 4 + i) * 48 + tn * 3 + j] = acc[i][j];
}

__global__ __launch_bounds__(256, 2) void mma_ke(const float* __restrict__ Kn,
                                                 const float* __restrict__ Wek,
                                                 float* __restrict__ KeOut) {
    __shared__ __align__(16) char smem[SMEM_BYTES];
    int z = blockIdx.z, e = z >> 3, h = z & 7;
    int n0 = blockIdx.x * 64, m0 = blockIdx.y * 128;
    mma_body(Kn + (size_t)m0 * KD + h * HD, KD,
             Wek + (size_t)z * HD * HD + (size_t)n0 * HD, HD,
             KeOut + (size_t)e * BL * KD + (size_t)m0 * KD + h * HD + n0, KD, HD, smem);
}

// fused conv+silu(+l2norm) : z=0 q, z=1 k (norm), z=2 v
__global__ __launch_bounds__(256) void conv_all(const float* __restrict__ qraw,
                                                const float* __restrict__ kraw,
                                                const float* __restrict__ vraw,
                                                const float* __restrict__ cq,
                                                const float* __restrict__ ck,
                                                const float* __restrict__ cv,
                                                float* __restrict__ qo,
                                                float* __restrict__ ko,
                                                float* __restrict__ vo) {
    __shared__ float red[8];
    int z = blockIdx.z;
    int row = blockIdx.x, h = blockIdx.y, l = row & (L_ - 1);
    if (z == 2) {
        #pragma unroll
        for (int u = 0; u < 2; u++) {
            int c = h * DV + threadIdx.x + u * 256;
            size_t idx = (size_t)row * VD + c;
            const float* w = cv + (size_t)c * 4;
            float y = w[3] * vraw[idx];
            if (l >= 1) y += w[2] * vraw[idx - VD];
            if (l >= 2) y += w[1] * vraw[idx - 2 * VD];
            if (l >= 3) y += w[0] * vraw[idx - 3 * VD];
            vo[idx] = y / (1.f + expf(-y));
        }
        return;
    }
    const float* raw = z ? kraw : qraw;
    const float* cw = z ? ck : cq;
    float* out = z ? ko : qo;
    float scale = z ? 1.0f : QSCALE;
    int cg = h * HD + threadIdx.x;
    const float* w = cw + (size_t)cg * 4;
    float y = w[3] * raw[(size_t)row * KD + cg];
    if (l >= 1) y += w[2] * raw[(size_t)(row - 1) * KD + cg];
    if (l >= 2) y += w[1] * raw[(size_t)(row - 2) * KD + cg];
    if (l >= 3) y += w[0] * raw[(size_t)(row - 3) * KD + cg];
    y = y / (1.f + expf(-y));
    float tot = blockReduceSum256(y * y, red);
    out[(size_t)row * KD + cg] = y * rsqrtf(tot + 1e-6f) * scale;
}

// per-expert scan: 384 CTAs = (e, b, h, vt)
#define PD 288
struct SBufE { float ke[PD]; float q[PD]; float v[64]; };

__global__ __launch_bounds__(256, 2) void scan_k(const float* __restrict__ keS,
                                                 const float* __restrict__ qn,
                                                 const float* __restrict__ vn,
                                                 const float* __restrict__ ba,
                                                 const float* __restrict__ A_log,
                                                 const float* __restrict__ dt_bias,
                                                 const int* __restrict__ modality,
                                                 const float* __restrict__ OW,
                                                 float* __restrict__ oEbuf) {
    __shared__ SBufE sb[2];
    __shared__ float sdec[L_];
    __shared__ float sbeta[L_];
    int bx = blockIdx.x, vt = bx & 7, h = (bx >> 3) & 7, b = (bx >> 6) & 1, e = bx >> 7;
    int tid = threadIdx.x, w = tid >> 5, lane = tid & 31;
    int g = lane >> 3, r = lane & 7;
    int colBase = vt * 64 + w * 8 + g * 2;
    int pdt = ((tid >> 5) * 36) + (tid & 31);
    int rb = r * 36;

    float w0 = OW[h], w1 = OW[8 + h], w2 = OW[16 + h];
    float mx = fmaxf(w0, fmaxf(w1, w2));
    float e0 = expf(w0 - mx), e1 = expf(w1 - mx), e2 = expf(w2 - mx);
    float wo = ((e == 0) ? e0 : (e == 1) ? e1 : e2) / (e0 + e1 + e2);

    int j = e * NH + h;
    float Ae = expf(A_log[j]), dtb_j = dt_bias[j];
    for (int idx = tid; idx < L_; idx += 256) {
        int row = b * L_ + idx;
        float av = ba[row * 48 + 24 + j] + dtb_j;
        float sp = (av > 20.f) ? av : log1pf(expf(av));
        float beta = 1.f / (1.f + expf(-ba[row * 48 + j]));
        int mo = modality[row];
        int m = (e == 0) ? 1 : ((e == 1) ? (mo == 0) : (mo == 1));
        sdec[idx] = m ? expf(-Ae * sp) : 1.f;
        sbeta[idx] = m ? beta : 0.f;
    }

    float2 S0[16], S1[16];
    #pragma unroll
    for (int jj = 0; jj < 16; jj++) { S0[jj] = make_float2(0.f, 0.f); S1[jj] = make_float2(0.f, 0.f); }

    const float* keE = keS + (size_t)e * BL * KD;
    float* oE = oEbuf + (size_t)e * BL * VD;

    float pk, pq, pv = 0.f;
    {
        size_t qoff = (size_t)(b * L_) * KD + h * HD;
        pk = keE[qoff + tid];
        pq = qn[qoff + tid];
        if (tid < 64) pv = vn[(size_t)(b * L_) * VD + h * DV + vt * 64 + tid];
    }

    for (int t = 0; t < L_; t++) {
        SBufE& sbuf = sb[t & 1];
        sbuf.ke[pdt] = pk;
        sbuf.q[pdt] = pq;
        if (tid < 64) sbuf.v[tid] = pv;
        __syncthreads();
        if (t + 1 < L_) {
            int row = b * L_ + t + 1;
            size_t qoff = (size_t)row * KD + h * HD;
            pk = keE[qoff + tid];
            pq = qn[qoff + tid];
            if (tid < 64) pv = vn[(size_t)row * VD + h * DV + vt * 64 + tid];
        }

        float dec = sdec[t], bb = sbeta[t];
        float o0, o1;
        if (bb != 0.f) {
            float vv0 = sbuf.v[w * 8 + g * 2];
            float vv1 = sbuf.v[w * 8 + g * 2 + 1];
            float2 dec2 = make_float2(dec, dec);
            float2 kS0 = {0,0}, kS1 = {0,0}, qS0 = {0,0}, qS1 = {0,0}, qk2 = {0,0};
            #pragma unroll
            for (int jj = 0; jj < 8; jj++) {
                float4 k4 = *reinterpret_cast<const float4*>(&sbuf.ke[rb + jj * 4]);
                float4 q4 = *reinterpret_cast<const float4*>(&sbuf.q[rb + jj * 4]);
                float2 ka = {k4.x, k4.y}, kb = {k4.z, k4.w};
                float2 qa = {q4.x, q4.y}, qb = {q4.z, q4.w};
                int jp = jj * 2;
                float2 s0 = fmul2(dec2, S0[jp]), s1 = fmul2(dec2, S1[jp]);
                kS0 = ffma2(ka, s0, kS0); kS1 = ffma2(ka, s1, kS1);
                qS0 = ffma2(qa, s0, qS0); qS1 = ffma2(qa, s1, qS1);
                qk2 = ffma2(qa, ka, qk2);
                S0[jp] = s0; S1[jp] = s1;
                float2 t0 = fmul2(dec2, S0[jp + 1]), t1 = fmul2(dec2, S1[jp + 1]);
                kS0 = ffma2(kb, t0, kS0); kS1 = ffma2(kb, t1, kS1);
                qS0 = ffma2(qb, t0, qS0); qS1 = ffma2(qb, t1, qS1);
                qk2 = ffma2(qb, kb, qk2);
                S0[jp + 1] = t0; S1[jp + 1] = t1;
            }
            float kS0s = kS0.x + kS0.y, kS1s = kS1.x + kS1.y;
            float qS0s = qS0.x + qS0.y, qS1s = qS1.x + qS1.y;
            float qks = qk2.x + qk2.y;
            #pragma unroll
            for (int off = 4; off; off >>= 1) {
                kS0s += __shfl_xor_sync(0xffffffffu, kS0s, off);
                kS1s += __shfl_xor_sync(0xffffffffu, kS1s, off);
                qS0s += __shfl_xor_sync(0xffffffffu, qS0s, off);
                qS1s += __shfl_xor_sync(0xffffffffu, qS1s, off);
                qks  += __shfl_xor_sync(0xffffffffu, qks,  off);
            }
            float d0 = (vv0 - kS0s) * bb;
            float d1 = (vv1 - kS1s) * bb;
            float2 d0d = make_float2(d0, d0), d1d = make_float2(d1, d1);
            #pragma unroll
            for (int jj = 0; jj < 8; jj++) {
                float4 k4 = *reinterpret_cast<const float4*>(&sbuf.ke[rb + jj * 4]);
                float2 ka = {k4.x, k4.y}, kb = {k4.z, k4.w};
                int jp = jj * 2;
                S0[jp] = ffma2(ka, d0d, S0[jp]);
                S1[jp] = ffma2(ka, d1d, S1[jp]);
                S0[jp + 1] = ffma2(kb, d0d, S0[jp + 1]);
                S1[jp + 1] = ffma2(kb, d1d, S1[jp + 1]);
            }
            o0 = wo * (qS0s + qks * d0);
            o1 = wo * (qS1s + qks * d1);
        } else {
            float2 qS0 = {0,0}, qS1 = {0,0};
            #pragma unroll
            for (int jj = 0; jj < 8; jj++) {
                float4 q4 = *reinterpret_cast<const float4*>(&sbuf.q[rb + jj * 4]);
                float2 qa = {q4.x, q4.y}, qb = {q4.z, q4.w};
                int jp = jj * 2;
                qS0 = ffma2(qa, S0[jp], qS0); qS1 = ffma2(qa, S1[jp], qS1);
                qS0 = ffma2(qb, S0[jp + 1], qS0); qS1 = ffma2(qb, S1[jp + 1], qS1);
            }
            float qS0s = qS0.x + qS0.y, qS1s = qS1.x + qS1.y;
            #pragma unroll
            for (int off = 4; off; off >>= 1) {
                qS0s += __shfl_xor_sync(0xffffffffu, qS0s, off);
                qS1s += __shfl_xor_sync(0xffffffffu, qS1s, off);
            }
            o0 = wo * qS0s;
            o1 = wo * qS1s;
        }
        if (r == 0) {
            int row = b * L_ + t;
            *reinterpret_cast<float2*>(&oE[(size_t)row * VD + h * DV + colBase]) = make_float2(o0, o1);
        }
    }
}

__global__ __launch_bounds__(256) void normgate_k(const float* __restrict__ oEbuf,
                                                  const float* __restrict__ gateRaw,
                                                  const float* __restrict__ onw,
                                                  float* __restrict__ oF) {
    __shared__ float red[8];
    int row = blockIdx.x >> 3, h = blockIdx.x & 7, tid = threadIdx.x;
    size_t base = (size_t)row * VD + h * DV;
    const float* o0p = oEbuf;
    const float* o1p = oEbuf + (size_t)BL * VD;
    const float* o2p = oEbuf + (size_t)2 * BL * VD;
    float x0 = o0p[base + tid] + o1p[base + tid] + o2p[base + tid];
    float x1 = o0p[base + tid + 256] + o1p[base + tid + 256] + o2p[base + tid + 256];
    float tot = blockReduceSum256(x0 * x0 + x1 * x1, red);
    float rn = rsqrtf(tot * (1.f / 512.f) + 1e-5f);
    float g0 = gateRaw[base + tid];
    float g1 = gateRaw[base + tid + 256];
    oF[base + tid]       = x0 * rn * onw[tid]       * (g0 / (1.f + expf(-g0)));
    oF[base + tid + 256] = x1 * rn * onw[tid + 256] * (g1 / (1.f + expf(-g1)));
}

extern "C" void kernel_launch(void* const* d_in, const int* in_sizes, int n_in,
                              void* d_out, int out_size) {
    const float *x, *Wq, *Wk, *Wv, *cq, *ck, *cv, *Wek, *Wb, *Wa, *Alog, *dtb, *ow, *Wg, *onw, *Wo;
    const int* mod;
    if (in_sizes[1] == 2048) {
        x = (const float*)d_in[0];  mod = (const int*)d_in[1];
        Wq = (const float*)d_in[2]; Wk = (const float*)d_in[3];
        Wv = (const float*)d_in[4]; cq = (const float*)d_in[5];
        ck = (const float*)d_in[6]; cv = (const float*)d_in[7];
        Wek = (const float*)d_in[8]; Wb = (const float*)d_in[9];
        Wa = (const float*)d_in[10]; Alog = (const float*)d_in[11];
        dtb = (const float*)d_in[12]; ow = (const float*)d_in[13];
        Wg = (const float*)d_in[14]; onw = (const float*)d_in[15];
        Wo = (const float*)d_in[16];
    } else {
        x = (const float*)d_in[0];  Wq = (const float*)d_in[1];
        Wk = (const float*)d_in[2]; Wv = (const float*)d_in[3];
        cq = (const float*)d_in[4]; ck = (const float*)d_in[5];
        cv = (const float*)d_in[6]; Wek = (const float*)d_in[7];
        Wb = (const float*)d_in[8]; Wa = (const float*)d_in[9];
        Alog = (const float*)d_in[10]; dtb = (const float*)d_in[11];
        ow = (const float*)d_in[12]; Wg = (const float*)d_in[13];
        onw = (const float*)d_in[14]; Wo = (const float*)d_in[15];
        mod = (const int*)d_in[16];
    }

    float *qraw, *kraw, *vraw, *gateraw, *q, *k, *v, *ke, *ba, *oE, *of;
    cudaGetSymbolAddress((void**)&qraw, g_qraw);
    cudaGetSymbolAddress((void**)&kraw, g_kraw);
    cudaGetSymbolAddress((void**)&vraw, g_vraw);
    cudaGetSymbolAddress((void**)&gateraw, g_gateraw);
    cudaGetSymbolAddress((void**)&q, g_q);
    cudaGetSymbolAddress((void**)&k, g_k);
    cudaGetSymbolAddress((void**)&v, g_v);
    cudaGetSymbolAddress((void**)&ke, g_ke);
    cudaGetSymbolAddress((void**)&ba, g_ba);
    cudaGetSymbolAddress((void**)&oE, g_oE);
    cudaGetSymbolAddress((void**)&of, g_of);

    mma_gemm_nt<<<dim3(32, 16), 256>>>(x, Wq, qraw, HS, HS, HS, KD);
    mma_gemm_nt<<<dim3(32, 16), 256>>>(x, Wk, kraw, HS, HS, HS, KD);
    mma_gemm_nt<<<dim3(64, 16), 256>>>(x, Wv, vraw, HS, HS, HS, VD);
    mma_wg_ba<<<dim3(66, 16), 256>>>(x, Wg, Wb, Wa, gateraw, ba);   // slot 3 -> profiled
    conv_all<<<dim3(BL, NH, 3), 256>>>(qraw, kraw, vraw, cq, ck, cv, q, k, v);
    mma_ke<<<dim3(4, 16, 24), 256>>>(k, Wek, ke);
    scan_k<<<384, 256>>>(ke, q, v, ba, Alog, dtb, mod, ow, oE);
    normgate_k<<<BL * NH, 256>>>(oE, gateraw, onw, of);
    mma_gemm_nt<<<dim3(32, 16), 256>>>(of, Wo, (float*)d_out, VD, VD, VD, HS);
}

// round 16
// speedup vs baseline: 2.5432x; 1.0259x over previous
#include <cuda_runtime.h>
#include <cuda_bf16.h>
#include <cstdint>

#define B_ 2
#define L_ 1024
#define BL 2048
#define HS 2048
#define NH 8
#define HD 256
#define DV 512
#define KD 2048
#define VD 4096
#define E_ 3
#define QSCALE 0.0625f

typedef __nv_bfloat16 bf16;
typedef __nv_bfloat162 bf162;

// fp32 scratch
__device__ float g_qraw[BL * KD];
__device__ float g_kraw[BL * KD];
__device__ float g_vraw[BL * VD];
__device__ float g_gateraw[BL * VD];
__device__ float g_q[BL * KD];
__device__ float g_v[BL * VD];
__device__ float g_ke[E_ * BL * KD];
__device__ float g_ba[BL * 48];
__device__ float g_oE[3 * BL * VD];
// bf16 hi/lo operand buffers
__device__ bf16 g_xh[BL * HS],  g_xl[BL * HS];
__device__ bf16 g_Wqh[KD * HS], g_Wql[KD * HS];
__device__ bf16 g_Wkh[KD * HS], g_Wkl[KD * HS];
__device__ bf16 g_Wvh[VD * HS], g_Wvl[VD * HS];
__device__ bf16 g_Wgh[VD * HS], g_Wgl[VD * HS];
__device__ bf16 g_Woh[HS * VD], g_Wol[HS * VD];
__device__ bf16 g_kh[BL * KD],  g_kl[BL * KD];
__device__ bf16 g_Wekh[E_ * NH * HD * HD], g_Wekl[E_ * NH * HD * HD];
__device__ bf16 g_ofh[BL * VD], g_ofl[BL * VD];

__device__ __forceinline__ float2 ffma2(float2 a, float2 b, float2 c) {
    unsigned long long au = *reinterpret_cast<unsigned long long*>(&a);
    unsigned long long bu = *reinterpret_cast<unsigned long long*>(&b);
    unsigned long long cu = *reinterpret_cast<unsigned long long*>(&c);
    unsigned long long du;
    asm("fma.rn.f32x2 %0, %1, %2, %3;" : "=l"(du) : "l"(au), "l"(bu), "l"(cu));
    return *reinterpret_cast<float2*>(&du);
}
__device__ __forceinline__ float2 fmul2(float2 a, float2 b) {
    unsigned long long au = *reinterpret_cast<unsigned long long*>(&a);
    unsigned long long bu = *reinterpret_cast<unsigned long long*>(&b);
    unsigned long long du;
    asm("mul.rn.f32x2 %0, %1, %2;" : "=l"(du) : "l"(au), "l"(bu));
    return *reinterpret_cast<float2*>(&du);
}

__device__ __forceinline__ float blockReduceSum256(float v, float* red) {
    int tid = threadIdx.x;
    #pragma unroll
    for (int off = 16; off; off >>= 1) v += __shfl_xor_sync(0xffffffffu, v, off);
    if ((tid & 31) == 0) red[tid >> 5] = v;
    __syncthreads();
    return red[0] + red[1] + red[2] + red[3] + red[4] + red[5] + red[6] + red[7];
}

// split fp32 -> bf16 hi + lo (residual)
__global__ __launch_bounds__(256) void cvt_split(const float* __restrict__ src,
                                                 bf16* __restrict__ h,
                                                 bf16* __restrict__ l, int n4) {
    int i = blockIdx.x * 256 + threadIdx.x;
    if (i >= n4) return;
    float4 v = reinterpret_cast<const float4*>(src)[i];
    bf162 h0, h1, l0, l1;
    h0.x = __float2bfloat16(v.x); h0.y = __float2bfloat16(v.y);
    h1.x = __float2bfloat16(v.z); h1.y = __float2bfloat16(v.w);
    l0.x = __float2bfloat16(v.x - __bfloat162float(h0.x));
    l0.y = __float2bfloat16(v.y - __bfloat162float(h0.y));
    l1.x = __float2bfloat16(v.z - __bfloat162float(h1.x));
    l1.y = __float2bfloat16(v.w - __bfloat162float(h1.y));
    reinterpret_cast<bf162*>(h)[i * 2] = h0;
    reinterpret_cast<bf162*>(h)[i * 2 + 1] = h1;
    reinterpret_cast<bf162*>(l)[i * 2] = l0;
    reinterpret_cast<bf162*>(l)[i * 2 + 1] = l1;
}

// ---------------- bf16x3 tensor-core GEMM, preconverted operands + cp.async ----------------
#define LDSM4(R0, R1, R2, R3, addr) \
    asm volatile("ldmatrix.sync.aligned.m8n8.x4.shared.b16 {%0,%1,%2,%3}, [%4];" \
                 : "=r"(R0), "=r"(R1), "=r"(R2), "=r"(R3) : "r"(addr))
#define MMA16816(D, A, B) \
    asm volatile("mma.sync.aligned.m16n8k16.row.col.f32.bf16.bf16.f32 " \
                 "{%0,%1,%2,%3}, {%4,%5,%6,%7}, {%8,%9}, {%0,%1,%2,%3};" \
                 : "+f"(D[0]), "+f"(D[1]), "+f"(D[2]), "+f"(D[3]) \
                 : "r"(A[0]), "r"(A[1]), "r"(A[2]), "r"(A[3]), "r"(B[0]), "r"(B[1]))
#define CP16(dst, src) \
    asm volatile("cp.async.cg.shared.global [%0], [%1], 16;" :: "r"(dst), "l"(src))
#define CP_COMMIT_WAIT() \
    asm volatile("cp.async.commit_group;\ncp.async.wait_group 0;" ::: "memory")

#define SMEM_BYTES 30720   // sAh 10240 + sAl 10240 + sBh 5120 + sBl 5120

__device__ __forceinline__ void mma_body2(const bf16* __restrict__ Ah, const bf16* __restrict__ Al, int lda,
                                          const bf16* __restrict__ Bh, const bf16* __restrict__ Bl, int ldb,
                                          float* __restrict__ C, int ldc, int K, char* smem) {
    bf16* sAh = reinterpret_cast<bf16*>(smem);   // [128][40]
    bf16* sAl = sAh + 128 * 40;
    bf16* sBh = sAl + 128 * 40;                  // [64][40]
    bf16* sBl = sBh + 64 * 40;
    int tid = threadIdx.x, lane = tid & 31, wid = tid >> 5;
    int wm = wid >> 1, wn = wid & 1;
    // cp.async assignments: A 512 16B-ops per dtype -> 2/thread; B 256 -> 1/thread
    int ar0 = tid >> 2, ac0 = (tid & 3) * 8;
    int ar1 = (tid + 256) >> 2, ac1 = ((tid + 256) & 3) * 8;
    int br = tid >> 2, bc = (tid & 3) * 8;
    uint32_t dAh0 = (uint32_t)__cvta_generic_to_shared(sAh + ar0 * 40 + ac0);
    uint32_t dAh1 = (uint32_t)__cvta_generic_to_shared(sAh + ar1 * 40 + ac1);
    uint32_t dAl0 = (uint32_t)__cvta_generic_to_shared(sAl + ar0 * 40 + ac0);
    uint32_t dAl1 = (uint32_t)__cvta_generic_to_shared(sAl + ar1 * 40 + ac1);
    uint32_t dBh0 = (uint32_t)__cvta_generic_to_shared(sBh + br * 40 + bc);
    uint32_t dBl0 = (uint32_t)__cvta_generic_to_shared(sBl + br * 40 + bc);
    // ldmatrix lane addressing
    int aRow = (lane & 7) + ((lane >> 3) & 1) * 8;
    int aCol = ((lane >> 4) & 1) * 8;
    int bRow = (lane & 7) + ((lane >> 4) & 1) * 8;
    int bCol = ((lane >> 3) & 1) * 8;

    float d[2][4][4];
    #pragma unroll
    for (int i = 0; i < 2; i++)
        #pragma unroll
        for (int j = 0; j < 4; j++)
            #pragma unroll
            for (int q = 0; q < 4; q++) d[i][j][q] = 0.f;

    for (int k0 = 0; k0 < K; k0 += 32) {
        if (k0) __syncthreads();
        CP16(dAh0, Ah + (size_t)ar0 * lda + k0 + ac0);
        CP16(dAh1, Ah + (size_t)ar1 * lda + k0 + ac1);
        CP16(dAl0, Al + (size_t)ar0 * lda + k0 + ac0);
        CP16(dAl1, Al + (size_t)ar1 * lda + k0 + ac1);
        CP16(dBh0, Bh + (size_t)br * ldb + k0 + bc);
        CP16(dBl0, Bl + (size_t)br * ldb + k0 + bc);
        CP_COMMIT_WAIT();
        __syncthreads();
        #pragma unroll
        for (int kk = 0; kk < 32; kk += 16) {
            uint32_t Am[2][4], Alr[2][4], Bm[4][2], Blr[4][2];
            #pragma unroll
            for (int mt = 0; mt < 2; mt++) {
                int idx = (wm * 32 + mt * 16 + aRow) * 40 + kk + aCol;
                uint32_t ah = (uint32_t)__cvta_generic_to_shared(sAh + idx);
                uint32_t al = (uint32_t)__cvta_generic_to_shared(sAl + idx);
                LDSM4(Am[mt][0], Am[mt][1], Am[mt][2], Am[mt][3], ah);
                LDSM4(Alr[mt][0], Alr[mt][1], Alr[mt][2], Alr[mt][3], al);
            }
            #pragma unroll
            for (int bp = 0; bp < 2; bp++) {
                int idx = (wn * 32 + bp * 16 + bRow) * 40 + kk + bCol;
                uint32_t bh = (uint32_t)__cvta_generic_to_shared(sBh + idx);
                uint32_t bl = (uint32_t)__cvta_generic_to_shared(sBl + idx);
                LDSM4(Bm[2 * bp][0], Bm[2 * bp][1], Bm[2 * bp + 1][0], Bm[2 * bp + 1][1], bh);
                LDSM4(Blr[2 * bp][0], Blr[2 * bp][1], Blr[2 * bp + 1][0], Blr[2 * bp + 1][1], bl);
            }
            #pragma unroll
            for (int mt = 0; mt < 2; mt++)
                #pragma unroll
                for (int nt = 0; nt < 4; nt++) {
                    MMA16816(d[mt][nt], Am[mt], Bm[nt]);
                    MMA16816(d[mt][nt], Alr[mt], Bm[nt]);
                    MMA16816(d[mt][nt], Am[mt], Blr[nt]);
                }
        }
    }
    #pragma unroll
    for (int mt = 0; mt < 2; mt++)
        #pragma unroll
        for (int nt = 0; nt < 4; nt++) {
            int row = wm * 32 + mt * 16 + (lane >> 2);
            int col = wn * 32 + nt * 8 + (lane & 3) * 2;
            *reinterpret_cast<float2*>(C + (size_t)row * ldc + col) =
                make_float2(d[mt][nt][0], d[mt][nt][1]);
            *reinterpret_cast<float2*>(C + (size_t)(row + 8) * ldc + col) =
                make_float2(d[mt][nt][2], d[mt][nt][3]);
        }
}

__global__ __launch_bounds__(256, 2) void mma_gemm_nt(const bf16* __restrict__ Ah, const bf16* __restrict__ Al,
                                                      const bf16* __restrict__ Bh, const bf16* __restrict__ Bl,
                                                      float* __restrict__ C,
                                                      int K, int lda, int ldb, int ldc) {
    __shared__ __align__(16) char smem[SMEM_BYTES];
    mma_body2(Ah + (size_t)blockIdx.y * 128 * lda, Al + (size_t)blockIdx.y * 128 * lda, lda,
              Bh + (size_t)blockIdx.x * 64 * ldb,  Bl + (size_t)blockIdx.x * 64 * ldb, ldb,
              C + (size_t)blockIdx.y * 128 * ldc + blockIdx.x * 64, ldc, K, smem);
}

// Wg gemm (nt<64) fused with ba projection tiles (nt 64,65; fp32 path)
__global__ __launch_bounds__(256, 2) void mma_wg_ba(const bf16* __restrict__ xh, const bf16* __restrict__ xl,
                                                    const bf16* __restrict__ Wgh, const bf16* __restrict__ Wgl,
                                                    const float* __restrict__ x,
                                                    const float* __restrict__ Wb,
                                                    const float* __restrict__ Wa,
                                                    float* __restrict__ graw,
                                                    float* __restrict__ ba) {
    __shared__ __align__(16) char smem[SMEM_BYTES];
    int nt = blockIdx.x;
    if (nt < 64) {
        mma_body2(xh + (size_t)blockIdx.y * 128 * HS, xl + (size_t)blockIdx.y * 128 * HS, HS,
                  Wgh + (size_t)nt * 64 * HS, Wgl + (size_t)nt * 64 * HS, HS,
                  graw + (size_t)blockIdx.y * 128 * VD + nt * 64, VD, HS, smem);
        return;
    }
    float* smemF = reinterpret_cast<float*>(smem);
    float (*xs)[66] = reinterpret_cast<float(*)[66]>(smemF);  // 4224 floats
    float* wsf = smemF + 4224;                                 // 816 -> 5040 floats (20160B < 30720)
    int tid = threadIdx.x;
    int m0 = blockIdx.y * 128 + (nt - 64) * 64;
    int tm = tid >> 4, tn = tid & 15;
    float acc[4][3] = {};
    for (int k0 = 0; k0 < HS; k0 += 16) {
        if (k0) __syncthreads();
        #pragma unroll
        for (int it = 0; it < 4; it++) {
            int qq = tid + it * 256;
            int r = qq >> 4, c = qq & 15;
            xs[r][c] = x[(size_t)(m0 + r) * HS + k0 + c];
            if (qq < 768) {
                const float* W = (r < 24) ? (Wb + (size_t)r * HS) : (Wa + (size_t)(r - 24) * HS);
                wsf[r * 17 + c] = W[k0 + c];
            }
        }
        __syncthreads();
        #pragma unroll
        for (int kk = 0; kk < 16; kk++) {
            float xv[4], wv[3];
            #pragma unroll
            for (int i = 0; i < 4; i++) xv[i] = xs[tm * 4 + i][kk];
            #pragma unroll
            for (int j = 0; j < 3; j++) wv[j] = wsf[(tn * 3 + j) * 17 + kk];
            #pragma unroll
            for (int i = 0; i < 4; i++)
                #pragma unroll
                for (int j = 0; j < 3; j++) acc[i][j] += xv[i] * wv[j];
        }
    }
    #pragma unroll
    for (int i = 0; i < 4; i++)
        #pragma unroll
        for (int j = 0; j < 3; j++)
            ba[(size_t)(m0 + tm * 4 + i) * 48 + tn * 3 + j] = acc[i][j];
}

__global__ __launch_bounds__(256, 2) void mma_ke(const bf16* __restrict__ kh, const bf16* __restrict__ kl,
                                                 const bf16* __restrict__ Wekh, const bf16* __restrict__ Wekl,
                                                 float* __restrict__ KeOut) {
    __shared__ __align__(16) char smem[SMEM_BYTES];
    int z = blockIdx.z, e = z >> 3, h = z & 7;
    int n0 = blockIdx.x * 64, m0 = blockIdx.y * 128;
    size_t aoff = (size_t)m0 * KD + h * HD;
    size_t boff = (size_t)z * HD * HD + (size_t)n0 * HD;
    mma_body2(kh + aoff, kl + aoff, KD,
              Wekh + boff, Wekl + boff, HD,
              KeOut + (size_t)e * BL * KD + (size_t)m0 * KD + h * HD + n0, KD, HD, smem);
}

// fused conv+silu(+l2norm): z=0 q (fp32), z=1 k (bf16 hi/lo), z=2 v (fp32)
__global__ __launch_bounds__(256) void conv_all(const float* __restrict__ qraw,
                                                const float* __restrict__ kraw,
                                                const float* __restrict__ vraw,
                                                const float* __restrict__ cq,
                                                const float* __restrict__ ck,
                                                const float* __restrict__ cv,
                                                float* __restrict__ qo,
                                                bf16* __restrict__ kh,
                                                bf16* __restrict__ kl,
                                                float* __restrict__ vo) {
    __shared__ float red[8];
    int z = blockIdx.z;
    int row = blockIdx.x, h = blockIdx.y, l = row & (L_ - 1);
    if (z == 2) {
        #pragma unroll
        for (int u = 0; u < 2; u++) {
            int c = h * DV + threadIdx.x + u * 256;
            size_t idx = (size_t)row * VD + c;
            const float* w = cv + (size_t)c * 4;
            float y = w[3] * vraw[idx];
            if (l >= 1) y += w[2] * vraw[idx - VD];
            if (l >= 2) y += w[1] * vraw[idx - 2 * VD];
            if (l >= 3) y += w[0] * vraw[idx - 3 * VD];
            vo[idx] = y / (1.f + expf(-y));
        }
        return;
    }
    const float* raw = z ? kraw : qraw;
    const float* cw = z ? ck : cq;
    float scale = z ? 1.0f : QSCALE;
    int cg = h * HD + threadIdx.x;
    const float* w = cw + (size_t)cg * 4;
    float y = w[3] * raw[(size_t)row * KD + cg];
    if (l >= 1) y += w[2] * raw[(size_t)(row - 1) * KD + cg];
    if (l >= 2) y += w[1] * raw[(size_t)(row - 2) * KD + cg];
    if (l >= 3) y += w[0] * raw[(size_t)(row - 3) * KD + cg];
    y = y / (1.f + expf(-y));
    float tot = blockReduceSum256(y * y, red);
    float val = y * rsqrtf(tot + 1e-6f) * scale;
    size_t oidx = (size_t)row * KD + cg;
    if (z == 0) {
        qo[oidx] = val;
    } else {
        bf16 hi = __float2bfloat16(val);
        kh[oidx] = hi;
        kl[oidx] = __float2bfloat16(val - __bfloat162float(hi));
    }
}

// per-expert scan: 384 CTAs = (e, b, h, vt)
#define PD 288
struct SBufE { float ke[PD]; float q[PD]; float v[64]; };

__global__ __launch_bounds__(256, 2) void scan_k(const float* __restrict__ keS,
                                                 const float* __restrict__ qn,
                                                 const float* __restrict__ vn,
                                                 const float* __restrict__ ba,
                                                 const float* __restrict__ A_log,
                                                 const float* __restrict__ dt_bias,
                                                 const int* __restrict__ modality,
                                                 const float* __restrict__ OW,
                                                 float* __restrict__ oEbuf) {
    __shared__ SBufE sb[2];
    __shared__ float sdec[L_];
    __shared__ float sbeta[L_];
    int bx = blockIdx.x, vt = bx & 7, h = (bx >> 3) & 7, b = (bx >> 6) & 1, e = bx >> 7;
    int tid = threadIdx.x, w = tid >> 5, lane = tid & 31;
    int g = lane >> 3, r = lane & 7;
    int colBase = vt * 64 + w * 8 + g * 2;
    int pdt = ((tid >> 5) * 36) + (tid & 31);
    int rb = r * 36;

    float w0 = OW[h], w1 = OW[8 + h], w2 = OW[16 + h];
    float mx = fmaxf(w0, fmaxf(w1, w2));
    float e0 = expf(w0 - mx), e1 = expf(w1 - mx), e2 = expf(w2 - mx);
    float wo = ((e == 0) ? e0 : (e == 1) ? e1 : e2) / (e0 + e1 + e2);

    int j = e * NH + h;
    float Ae = expf(A_log[j]), dtb_j = dt_bias[j];
    for (int idx = tid; idx < L_; idx += 256) {
        int row = b * L_ + idx;
        float av = ba[row * 48 + 24 + j] + dtb_j;
        float sp = (av > 20.f) ? av : log1pf(expf(av));
        float beta = 1.f / (1.f + expf(-ba[row * 48 + j]));
        int mo = modality[row];
        int m = (e == 0) ? 1 : ((e == 1) ? (mo == 0) : (mo == 1));
        sdec[idx] = m ? expf(-Ae * sp) : 1.f;
        sbeta[idx] = m ? beta : 0.f;
    }

    float2 S0[16], S1[16];
    #pragma unroll
    for (int jj = 0; jj < 16; jj++) { S0[jj] = make_float2(0.f, 0.f); S1[jj] = make_float2(0.f, 0.f); }

    const float* keE = keS + (size_t)e * BL * KD;
    float* oE = oEbuf + (size_t)e * BL * VD;

    float pk, pq, pv = 0.f;
    {
        size_t qoff = (size_t)(b * L_) * KD + h * HD;
        pk = keE[qoff + tid];
        pq = qn[qoff + tid];
        if (tid < 64) pv = vn[(size_t)(b * L_) * VD + h * DV + vt * 64 + tid];
    }

    for (int t = 0; t < L_; t++) {
        SBufE& sbuf = sb[t & 1];
        sbuf.ke[pdt] = pk;
        sbuf.q[pdt] = pq;
        if (tid < 64) sbuf.v[tid] = pv;
        __syncthreads();
        if (t + 1 < L_) {
            int row = b * L_ + t + 1;
            size_t qoff = (size_t)row * KD + h * HD;
            pk = keE[qoff + tid];
            pq = qn[qoff + tid];
            if (tid < 64) pv = vn[(size_t)row * VD + h * DV + vt * 64 + tid];
        }

        float dec = sdec[t], bb = sbeta[t];
        float o0, o1;
        if (bb != 0.f) {
            float vv0 = sbuf.v[w * 8 + g * 2];
            float vv1 = sbuf.v[w * 8 + g * 2 + 1];
            float2 dec2 = make_float2(dec, dec);
            float2 kS0 = {0,0}, kS1 = {0,0}, qS0 = {0,0}, qS1 = {0,0}, qk2 = {0,0};
            #pragma unroll
            for (int jj = 0; jj < 8; jj++) {
                float4 k4 = *reinterpret_cast<const float4*>(&sbuf.ke[rb + jj * 4]);
                float4 q4 = *reinterpret_cast<const float4*>(&sbuf.q[rb + jj * 4]);
                float2 ka = {k4.x, k4.y}, kb = {k4.z, k4.w};
                float2 qa = {q4.x, q4.y}, qb = {q4.z, q4.w};
                int jp = jj * 2;
                float2 s0 = fmul2(dec2, S0[jp]), s1 = fmul2(dec2, S1[jp]);
                kS0 = ffma2(ka, s0, kS0); kS1 = ffma2(ka, s1, kS1);
                qS0 = ffma2(qa, s0, qS0); qS1 = ffma2(qa, s1, qS1);
                qk2 = ffma2(qa, ka, qk2);
                S0[jp] = s0; S1[jp] = s1;
                float2 t0 = fmul2(dec2, S0[jp + 1]), t1 = fmul2(dec2, S1[jp + 1]);
                kS0 = ffma2(kb, t0, kS0); kS1 = ffma2(kb, t1, kS1);
                qS0 = ffma2(qb, t0, qS0); qS1 = ffma2(qb, t1, qS1);
                qk2 = ffma2(qb, kb, qk2);
                S0[jp + 1] = t0; S1[jp + 1] = t1;
            }
            float kS0s = kS0.x + kS0.y, kS1s = kS1.x + kS1.y;
            float qS0s = qS0.x + qS0.y, qS1s = qS1.x + qS1.y;
            float qks = qk2.x + qk2.y;
            #pragma unroll
            for (int off = 4; off; off >>= 1) {
                kS0s += __shfl_xor_sync(0xffffffffu, kS0s, off);
                kS1s += __shfl_xor_sync(0xffffffffu, kS1s, off);
                qS0s += __shfl_xor_sync(0xffffffffu, qS0s, off);
                qS1s += __shfl_xor_sync(0xffffffffu, qS1s, off);
                qks  += __shfl_xor_sync(0xffffffffu, qks,  off);
            }
            float d0 = (vv0 - kS0s) * bb;
            float d1 = (vv1 - kS1s) * bb;
            float2 d0d = make_float2(d0, d0), d1d = make_float2(d1, d1);
            #pragma unroll
            for (int jj = 0; jj < 8; jj++) {
                float4 k4 = *reinterpret_cast<const float4*>(&sbuf.ke[rb + jj * 4]);
                float2 ka = {k4.x, k4.y}, kb = {k4.z, k4.w};
                int jp = jj * 2;
                S0[jp] = ffma2(ka, d0d, S0[jp]);
                S1[jp] = ffma2(ka, d1d, S1[jp]);
                S0[jp + 1] = ffma2(kb, d0d, S0[jp + 1]);
                S1[jp + 1] = ffma2(kb, d1d, S1[jp + 1]);
            }
            o0 = wo * (qS0s + qks * d0);
            o1 = wo * (qS1s + qks * d1);
        } else {
            float2 qS0 = {0,0}, qS1 = {0,0};
            #pragma unroll
            for (int jj = 0; jj < 8; jj++) {
                float4 q4 = *reinterpret_cast<const float4*>(&sbuf.q[rb + jj * 4]);
                float2 qa = {q4.x, q4.y}, qb = {q4.z, q4.w};
                int jp = jj * 2;
                qS0 = ffma2(qa, S0[jp], qS0); qS1 = ffma2(qa, S1[jp], qS1);
                qS0 = ffma2(qb, S0[jp + 1], qS0); qS1 = ffma2(qb, S1[jp + 1], qS1);
            }
            float qS0s = qS0.x + qS0.y, qS1s = qS1.x + qS1.y;
            #pragma unroll
            for (int off = 4; off; off >>= 1) {
                qS0s += __shfl_xor_sync(0xffffffffu, qS0s, off);
                qS1s += __shfl_xor_sync(0xffffffffu, qS1s, off);
            }
            o0 = wo * qS0s;
            o1 = wo * qS1s;
        }
        if (r == 0) {
            int row = b * L_ + t;
            *reinterpret_cast<float2*>(&oE[(size_t)row * VD + h * DV + colBase]) = make_float2(o0, o1);
        }
    }
}

__global__ __launch_bounds__(256) void normgate_k(const float* __restrict__ oEbuf,
                                                  const float* __restrict__ gateRaw,
                                                  const float* __restrict__ onw,
                                                  bf16* __restrict__ oFh,
                                                  bf16* __restrict__ oFl) {
    __shared__ float red[8];
    int row = blockIdx.x >> 3, h = blockIdx.x & 7, tid = threadIdx.x;
    size_t base = (size_t)row * VD + h * DV;
    const float* o0p = oEbuf;
    const float* o1p = oEbuf + (size_t)BL * VD;
    const float* o2p = oEbuf + (size_t)2 * BL * VD;
    float x0 = o0p[base + tid] + o1p[base + tid] + o2p[base + tid];
    float x1 = o0p[base + tid + 256] + o1p[base + tid + 256] + o2p[base + tid + 256];
    float tot = blockReduceSum256(x0 * x0 + x1 * x1, red);
    float rn = rsqrtf(tot * (1.f / 512.f) + 1e-5f);
    float g0 = gateRaw[base + tid];
    float g1 = gateRaw[base + tid + 256];
    float v0 = x0 * rn * onw[tid]       * (g0 / (1.f + expf(-g0)));
    float v1 = x1 * rn * onw[tid + 256] * (g1 / (1.f + expf(-g1)));
    bf16 h0 = __float2bfloat16(v0), h1 = __float2bfloat16(v1);
    oFh[base + tid] = h0;
    oFl[base + tid] = __float2bfloat16(v0 - __bfloat162float(h0));
    oFh[base + tid + 256] = h1;
    oFl[base + tid + 256] = __float2bfloat16(v1 - __bfloat162float(h1));
}

extern "C" void kernel_launch(void* const* d_in, const int* in_sizes, int n_in,
                              void* d_out, int out_size) {
    const float *x, *Wq, *Wk, *Wv, *cq, *ck, *cv, *Wek, *Wb, *Wa, *Alog, *dtb, *ow, *Wg, *onw, *Wo;
    const int* mod;
    if (in_sizes[1] == 2048) {
        x = (const float*)d_in[0];  mod = (const int*)d_in[1];
        Wq = (const float*)d_in[2]; Wk = (const float*)d_in[3];
        Wv = (const float*)d_in[4]; cq = (const float*)d_in[5];
        ck = (const float*)d_in[6]; cv = (const float*)d_in[7];
        Wek = (const float*)d_in[8]; Wb = (const float*)d_in[9];
        Wa = (const float*)d_in[10]; Alog = (const float*)d_in[11];
        dtb = (const float*)d_in[12]; ow = (const float*)d_in[13];
        Wg = (const float*)d_in[14]; onw = (const float*)d_in[15];
        Wo = (const float*)d_in[16];
    } else {
        x = (const float*)d_in[0];  Wq = (const float*)d_in[1];
        Wk = (const float*)d_in[2]; Wv = (const float*)d_in[3];
        cq = (const float*)d_in[4]; ck = (const float*)d_in[5];
        cv = (const float*)d_in[6]; Wek = (const float*)d_in[7];
        Wb = (const float*)d_in[8]; Wa = (const float*)d_in[9];
        Alog = (const float*)d_in[10]; dtb = (const float*)d_in[11];
        ow = (const float*)d_in[12]; Wg = (const float*)d_in[13];
        onw = (const float*)d_in[14]; Wo = (const float*)d_in[15];
        mod = (const int*)d_in[16];
    }

    float *qraw, *kraw, *vraw, *gateraw, *q, *v, *ke, *ba, *oE;
    bf16 *xh, *xl, *Wqh, *Wql, *Wkh, *Wkl, *Wvh, *Wvl, *Wgh, *Wgl, *Woh, *Wol;
    bf16 *kh, *kl, *Wekh, *Wekl, *ofh, *ofl;
    cudaGetSymbolAddress((void**)&qraw, g_qraw);
    cudaGetSymbolAddress((void**)&kraw, g_kraw);
    cudaGetSymbolAddress((void**)&vraw, g_vraw);
    cudaGetSymbolAddress((void**)&gateraw, g_gateraw);
    cudaGetSymbolAddress((void**)&q, g_q);
    cudaGetSymbolAddress((void**)&v, g_v);
    cudaGetSymbolAddress((void**)&ke, g_ke);
    cudaGetSymbolAddress((void**)&ba, g_ba);
    cudaGetSymbolAddress((void**)&oE, g_oE);
    cudaGetSymbolAddress((void**)&xh, g_xh);   cudaGetSymbolAddress((void**)&xl, g_xl);
    cudaGetSymbolAddress((void**)&Wqh, g_Wqh); cudaGetSymbolAddress((void**)&Wql, g_Wql);
    cudaGetSymbolAddress((void**)&Wkh, g_Wkh); cudaGetSymbolAddress((void**)&Wkl, g_Wkl);
    cudaGetSymbolAddress((void**)&Wvh, g_Wvh); cudaGetSymbolAddress((void**)&Wvl, g_Wvl);
    cudaGetSymbolAddress((void**)&Wgh, g_Wgh); cudaGetSymbolAddress((void**)&Wgl, g_Wgl);
    cudaGetSymbolAddress((void**)&Woh, g_Woh); cudaGetSymbolAddress((void**)&Wol, g_Wol);
    cudaGetSymbolAddress((void**)&kh, g_kh);   cudaGetSymbolAddress((void**)&kl, g_kl);
    cudaGetSymbolAddress((void**)&Wekh, g_Wekh); cudaGetSymbolAddress((void**)&Wekl, g_Wekl);
    cudaGetSymbolAddress((void**)&ofh, g_ofh); cudaGetSymbolAddress((void**)&ofl, g_ofl);

    cvt_split<<<(BL * HS / 4 + 255) / 256, 256>>>(x, xh, xl, BL * HS / 4);
    cvt_split<<<(KD * HS / 4 + 255) / 256, 256>>>(Wq, Wqh, Wql, KD * HS / 4);
    cvt_split<<<(KD * HS / 4 + 255) / 256, 256>>>(Wk, Wkh, Wkl, KD * HS / 4);
    mma_gemm_nt<<<dim3(32, 16), 256>>>(xh, xl, Wqh, Wql, qraw, HS, HS, HS, KD);  // slot 3 -> profiled
    cvt_split<<<(VD * HS / 4 + 255) / 256, 256>>>(Wv, Wvh, Wvl, VD * HS / 4);
    cvt_split<<<(VD * HS / 4 + 255) / 256, 256>>>(Wg, Wgh, Wgl, VD * HS / 4);
    mma_gemm_nt<<<dim3(32, 16), 256>>>(xh, xl, Wkh, Wkl, kraw, HS, HS, HS, KD);
    mma_gemm_nt<<<dim3(64, 16), 256>>>(xh, xl, Wvh, Wvl, vraw, HS, HS, HS, VD);
    mma_wg_ba<<<dim3(66, 16), 256>>>(xh, xl, Wgh, Wgl, x, Wb, Wa, gateraw, ba);
    conv_all<<<dim3(BL, NH, 3), 256>>>(qraw, kraw, vraw, cq, ck, cv, q, kh, kl, v);
    cvt_split<<<(E_ * NH * HD * HD / 4 + 255) / 256, 256>>>(Wek, Wekh, Wekl, E_ * NH * HD * HD / 4);
    mma_ke<<<dim3(4, 16, 24), 256>>>(kh, kl, Wekh, Wekl, ke);
    scan_k<<<384, 256>>>(ke, q, v, ba, Alog, dtb, mod, ow, oE);
    normgate_k<<<BL * NH, 256>>>(oE, gateraw, onw, ofh, ofl);
    cvt_split<<<(HS * VD / 4 + 255) / 256, 256>>>(Wo, Woh, Wol, HS * VD / 4);
    mma_gemm_nt<<<dim3(32, 16), 256>>>(ofh, ofl, Woh, Wol, (float*)d_out, VD, VD, VD, HS);
}

// round 17
// speedup vs baseline: 2.7314x; 1.0740x over previous
#include <cuda_runtime.h>
#include <cuda_bf16.h>
#include <cstdint>

#define B_ 2
#define L_ 1024
#define BL 2048
#define HS 2048
#define NH 8
#define HD 256
#define DV 512
#define KD 2048
#define VD 4096
#define E_ 3
#define QSCALE 0.0625f

typedef __nv_bfloat16 bf16;
typedef __nv_bfloat162 bf162;

__device__ float g_qraw[BL * KD];
__device__ float g_kraw[BL * KD];
__device__ float g_vraw[BL * VD];
__device__ float g_gateraw[BL * VD];
__device__ float g_q[BL * KD];
__device__ float g_v[BL * VD];
__device__ float g_ke[E_ * BL * KD];
__device__ float g_ba[BL * 48];
__device__ float g_oE[3 * BL * VD];
__device__ bf16 g_xh[BL * HS],  g_xl[BL * HS];
__device__ bf16 g_Wqh[KD * HS], g_Wql[KD * HS];
__device__ bf16 g_Wkh[KD * HS], g_Wkl[KD * HS];
__device__ bf16 g_Wvh[VD * HS], g_Wvl[VD * HS];
__device__ bf16 g_Wgh[VD * HS], g_Wgl[VD * HS];
__device__ bf16 g_Woh[HS * VD], g_Wol[HS * VD];
__device__ bf16 g_kh[BL * KD],  g_kl[BL * KD];
__device__ bf16 g_Wekh[E_ * NH * HD * HD], g_Wekl[E_ * NH * HD * HD];
__device__ bf16 g_ofh[BL * VD], g_ofl[BL * VD];

__device__ __forceinline__ float2 ffma2(float2 a, float2 b, float2 c) {
    unsigned long long au = *reinterpret_cast<unsigned long long*>(&a);
    unsigned long long bu = *reinterpret_cast<unsigned long long*>(&b);
    unsigned long long cu = *reinterpret_cast<unsigned long long*>(&c);
    unsigned long long du;
    asm("fma.rn.f32x2 %0, %1, %2, %3;" : "=l"(du) : "l"(au), "l"(bu), "l"(cu));
    return *reinterpret_cast<float2*>(&du);
}
__device__ __forceinline__ float2 fmul2(float2 a, float2 b) {
    unsigned long long au = *reinterpret_cast<unsigned long long*>(&a);
    unsigned long long bu = *reinterpret_cast<unsigned long long*>(&b);
    unsigned long long du;
    asm("mul.rn.f32x2 %0, %1, %2;" : "=l"(du) : "l"(au), "l"(bu));
    return *reinterpret_cast<float2*>(&du);
}

__device__ __forceinline__ float blockReduceSum256(float v, float* red) {
    int tid = threadIdx.x;
    #pragma unroll
    for (int off = 16; off; off >>= 1) v += __shfl_xor_sync(0xffffffffu, v, off);
    if ((tid & 31) == 0) red[tid >> 5] = v;
    __syncthreads();
    return red[0] + red[1] + red[2] + red[3] + red[4] + red[5] + red[6] + red[7];
}

__global__ __launch_bounds__(256) void cvt_split(const float* __restrict__ src,
                                                 bf16* __restrict__ h,
                                                 bf16* __restrict__ l, int n4) {
    int i = blockIdx.x * 256 + threadIdx.x;
    if (i >= n4) return;
    float4 v = reinterpret_cast<const float4*>(src)[i];
    bf162 h0, h1, l0, l1;
    h0.x = __float2bfloat16(v.x); h0.y = __float2bfloat16(v.y);
    h1.x = __float2bfloat16(v.z); h1.y = __float2bfloat16(v.w);
    l0.x = __float2bfloat16(v.x - __bfloat162float(h0.x));
    l0.y = __float2bfloat16(v.y - __bfloat162float(h0.y));
    l1.x = __float2bfloat16(v.z - __bfloat162float(h1.x));
    l1.y = __float2bfloat16(v.w - __bfloat162float(h1.y));
    reinterpret_cast<bf162*>(h)[i * 2] = h0;
    reinterpret_cast<bf162*>(h)[i * 2 + 1] = h1;
    reinterpret_cast<bf162*>(l)[i * 2] = l0;
    reinterpret_cast<bf162*>(l)[i * 2 + 1] = l1;
}

#define LDSM4(R0, R1, R2, R3, addr) \
    asm volatile("ldmatrix.sync.aligned.m8n8.x4.shared.b16 {%0,%1,%2,%3}, [%4];" \
                 : "=r"(R0), "=r"(R1), "=r"(R2), "=r"(R3) : "r"(addr))
#define MMA16816(D, A, B) \
    asm volatile("mma.sync.aligned.m16n8k16.row.col.f32.bf16.bf16.f32 " \
                 "{%0,%1,%2,%3}, {%4,%5,%6,%7}, {%8,%9}, {%0,%1,%2,%3};" \
                 : "+f"(D[0]), "+f"(D[1]), "+f"(D[2]), "+f"(D[3]) \
                 : "r"(A[0]), "r"(A[1]), "r"(A[2]), "r"(A[3]), "r"(B[0]), "r"(B[1]))
#define CP16(dst, src) \
    asm volatile("cp.async.cg.shared.global [%0], [%1], 16;" :: "r"(dst), "l"(src))

#define STAGE_BYTES 30720   // sAh 10240 + sAl 10240 + sBh 5120 + sBl 5120
#define SMEM_DYN (2 * STAGE_BYTES)

// 2-stage cp.async pipelined bf16x3 GEMM: C[128 x 64] = A*B^T
__device__ __forceinline__ void mma_body3(const bf16* __restrict__ Ah, const bf16* __restrict__ Al, int lda,
                                          const bf16* __restrict__ Bh, const bf16* __restrict__ Bl, int ldb,
                                          float* __restrict__ C, int ldc, int K, char* smem) {
    int tid = threadIdx.x, lane = tid & 31, wid = tid >> 5;
    int wm = wid >> 1, wn = wid & 1;
    int ar0 = tid >> 2, ac0 = (tid & 3) * 8;
    int ar1 = (tid + 256) >> 2, ac1 = ((tid + 256) & 3) * 8;
    int br = tid >> 2, bc = (tid & 3) * 8;
    int aRow = (lane & 7) + ((lane >> 3) & 1) * 8;
    int aCol = ((lane >> 4) & 1) * 8;
    int bRow = (lane & 7) + ((lane >> 4) & 1) * 8;
    int bCol = ((lane >> 3) & 1) * 8;

    uint32_t sbase = (uint32_t)__cvta_generic_to_shared(smem);
    // per-stage offsets (bytes)
    const uint32_t oAh = 0, oAl = 10240, oBh = 20480, oBl = 25600;

    float d[2][4][4];
    #pragma unroll
    for (int i = 0; i < 2; i++)
        #pragma unroll
        for (int j = 0; j < 4; j++)
            #pragma unroll
            for (int q = 0; q < 4; q++) d[i][j][q] = 0.f;

    int T = K >> 5;
    // prologue: stage 0
    {
        uint32_t sb = sbase;
        CP16(sb + oAh + (ar0 * 40 + ac0) * 2, Ah + (size_t)ar0 * lda + ac0);
        CP16(sb + oAh + (ar1 * 40 + ac1) * 2, Ah + (size_t)ar1 * lda + ac1);
        CP16(sb + oAl + (ar0 * 40 + ac0) * 2, Al + (size_t)ar0 * lda + ac0);
        CP16(sb + oAl + (ar1 * 40 + ac1) * 2, Al + (size_t)ar1 * lda + ac1);
        CP16(sb + oBh + (br * 40 + bc) * 2,  Bh + (size_t)br * ldb + bc);
        CP16(sb + oBl + (br * 40 + bc) * 2,  Bl + (size_t)br * ldb + bc);
        asm volatile("cp.async.commit_group;" ::: "memory");
    }
    for (int i = 0; i < T; i++) {
        if (i + 1 < T) {
            int k0 = (i + 1) << 5;
            uint32_t sb = sbase + ((i + 1) & 1) * STAGE_BYTES;
            CP16(sb + oAh + (ar0 * 40 + ac0) * 2, Ah + (size_t)ar0 * lda + k0 + ac0);
            CP16(sb + oAh + (ar1 * 40 + ac1) * 2, Ah + (size_t)ar1 * lda + k0 + ac1);
            CP16(sb + oAl + (ar0 * 40 + ac0) * 2, Al + (size_t)ar0 * lda + k0 + ac0);
            CP16(sb + oAl + (ar1 * 40 + ac1) * 2, Al + (size_t)ar1 * lda + k0 + ac1);
            CP16(sb + oBh + (br * 40 + bc) * 2,  Bh + (size_t)br * ldb + k0 + bc);
            CP16(sb + oBl + (br * 40 + bc) * 2,  Bl + (size_t)br * ldb + k0 + bc);
            asm volatile("cp.async.commit_group;" ::: "memory");
            asm volatile("cp.async.wait_group 1;" ::: "memory");
        } else {
            asm volatile("cp.async.wait_group 0;" ::: "memory");
        }
        __syncthreads();
        uint32_t sb = sbase + (i & 1) * STAGE_BYTES;
        #pragma unroll
        for (int kk = 0; kk < 32; kk += 16) {
            uint32_t Am[2][4], Alr[2][4], Bm[4][2], Blr[4][2];
            #pragma unroll
            for (int mt = 0; mt < 2; mt++) {
                uint32_t idx = ((wm * 32 + mt * 16 + aRow) * 40 + kk + aCol) * 2;
                LDSM4(Am[mt][0], Am[mt][1], Am[mt][2], Am[mt][3], sb + oAh + idx);
                LDSM4(Alr[mt][0], Alr[mt][1], Alr[mt][2], Alr[mt][3], sb + oAl + idx);
            }
            #pragma unroll
            for (int bp = 0; bp < 2; bp++) {
                uint32_t idx = ((wn * 32 + bp * 16 + bRow) * 40 + kk + bCol) * 2;
                LDSM4(Bm[2 * bp][0], Bm[2 * bp][1], Bm[2 * bp + 1][0], Bm[2 * bp + 1][1], sb + oBh + idx);
                LDSM4(Blr[2 * bp][0], Blr[2 * bp][1], Blr[2 * bp + 1][0], Blr[2 * bp + 1][1], sb + oBl + idx);
            }
            #pragma unroll
            for (int mt = 0; mt < 2; mt++)
                #pragma unroll
                for (int nt = 0; nt < 4; nt++) {
                    MMA16816(d[mt][nt], Am[mt], Bm[nt]);
                    MMA16816(d[mt][nt], Alr[mt], Bm[nt]);
                    MMA16816(d[mt][nt], Am[mt], Blr[nt]);
                }
        }
        __syncthreads();
    }
    #pragma unroll
    for (int mt = 0; mt < 2; mt++)
        #pragma unroll
        for (int nt = 0; nt < 4; nt++) {
            int row = wm * 32 + mt * 16 + (lane >> 2);
            int col = wn * 32 + nt * 8 + (lane & 3) * 2;
            *reinterpret_cast<float2*>(C + (size_t)row * ldc + col) =
                make_float2(d[mt][nt][0], d[mt][nt][1]);
            *reinterpret_cast<float2*>(C + (size_t)(row + 8) * ldc + col) =
                make_float2(d[mt][nt][2], d[mt][nt][3]);
        }
}

__global__ __launch_bounds__(256, 2) void mma_gemm_nt(const bf16* __restrict__ Ah, const bf16* __restrict__ Al,
                                                      const bf16* __restrict__ Bh, const bf16* __restrict__ Bl,
                                                      float* __restrict__ C,
                                                      int K, int lda, int ldb, int ldc) {
    extern __shared__ __align__(16) char smem[];
    mma_body3(Ah + (size_t)blockIdx.y * 128 * lda, Al + (size_t)blockIdx.y * 128 * lda, lda,
              Bh + (size_t)blockIdx.x * 64 * ldb,  Bl + (size_t)blockIdx.x * 64 * ldb, ldb,
              C + (size_t)blockIdx.y * 128 * ldc + blockIdx.x * 64, ldc, K, smem);
}

__global__ __launch_bounds__(256, 2) void mma_wg_ba(const bf16* __restrict__ xh, const bf16* __restrict__ xl,
                                                    const bf16* __restrict__ Wgh, const bf16* __restrict__ Wgl,
                                                    const float* __restrict__ x,
                                                    const float* __restrict__ Wb,
                                                    const float* __restrict__ Wa,
                                                    float* __restrict__ graw,
                                                    float* __restrict__ ba) {
    extern __shared__ __align__(16) char smem[];
    int nt = blockIdx.x;
    if (nt < 64) {
        mma_body3(xh + (size_t)blockIdx.y * 128 * HS, xl + (size_t)blockIdx.y * 128 * HS, HS,
                  Wgh + (size_t)nt * 64 * HS, Wgl + (size_t)nt * 64 * HS, HS,
                  graw + (size_t)blockIdx.y * 128 * VD + nt * 64, VD, HS, smem);
        return;
    }
    float* smemF = reinterpret_cast<float*>(smem);
    float (*xs)[66] = reinterpret_cast<float(*)[66]>(smemF);
    float* wsf = smemF + 4224;
    int tid = threadIdx.x;
    int m0 = blockIdx.y * 128 + (nt - 64) * 64;
    int tm = tid >> 4, tn = tid & 15;
    float acc[4][3] = {};
    for (int k0 = 0; k0 < HS; k0 += 16) {
        if (k0) __syncthreads();
        #pragma unroll
        for (int it = 0; it < 4; it++) {
            int qq = tid + it * 256;
            int r = qq >> 4, c = qq & 15;
            xs[r][c] = x[(size_t)(m0 + r) * HS + k0 + c];
            if (qq < 768) {
                const float* W = (r < 24) ? (Wb + (size_t)r * HS) : (Wa + (size_t)(r - 24) * HS);
                wsf[r * 17 + c] = W[k0 + c];
            }
        }
        __syncthreads();
        #pragma unroll
        for (int kk = 0; kk < 16; kk++) {
            float xv[4], wv[3];
            #pragma unroll
            for (int i = 0; i < 4; i++) xv[i] = xs[tm * 4 + i][kk];
            #pragma unroll
            for (int j = 0; j < 3; j++) wv[j] = wsf[(tn * 3 + j) * 17 + kk];
            #pragma unroll
            for (int i = 0; i < 4; i++)
                #pragma unroll
                for (int j = 0; j < 3; j++) acc[i][j] += xv[i] * wv[j];
        }
    }
    #pragma unroll
    for (int i = 0; i < 4; i++)
        #pragma unroll
        for (int j = 0; j < 3; j++)
            ba[(size_t)(m0 + tm * 4 + i) * 48 + tn * 3 + j] = acc[i][j];
}

__global__ __launch_bounds__(256, 2) void mma_ke(const bf16* __restrict__ kh, const bf16* __restrict__ kl,
                                                 const bf16* __restrict__ Wekh, const bf16* __restrict__ Wekl,
                                                 float* __restrict__ KeOut) {
    extern __shared__ __align__(16) char smem[];
    int z = blockIdx.z, e = z >> 3, h = z & 7;
    int n0 = blockIdx.x * 64, m0 = blockIdx.y * 128;
    size_t aoff = (size_t)m0 * KD + h * HD;
    size_t boff = (size_t)z * HD * HD + (size_t)n0 * HD;
    mma_body3(kh + aoff, kl + aoff, KD,
              Wekh + boff, Wekl + boff, HD,
              KeOut + (size_t)e * BL * KD + (size_t)m0 * KD + h * HD + n0, KD, HD, smem);
}

__global__ __launch_bounds__(256) void conv_all(const float* __restrict__ qraw,
                                                const float* __restrict__ kraw,
                                                const float* __restrict__ vraw,
                                                const float* __restrict__ cq,
                                                const float* __restrict__ ck,
                                                const float* __restrict__ cv,
                                                float* __restrict__ qo,
                                                bf16* __restrict__ kh,
                                                bf16* __restrict__ kl,
                                                float* __restrict__ vo) {
    __shared__ float red[8];
    int z = blockIdx.z;
    int row = blockIdx.x, h = blockIdx.y, l = row & (L_ - 1);
    if (z == 2) {
        #pragma unroll
        for (int u = 0; u < 2; u++) {
            int c = h * DV + threadIdx.x + u * 256;
            size_t idx = (size_t)row * VD + c;
            const float* w = cv + (size_t)c * 4;
            float y = w[3] * vraw[idx];
            if (l >= 1) y += w[2] * vraw[idx - VD];
            if (l >= 2) y += w[1] * vraw[idx - 2 * VD];
            if (l >= 3) y += w[0] * vraw[idx - 3 * VD];
            vo[idx] = y / (1.f + expf(-y));
        }
        return;
    }
    const float* raw = z ? kraw : qraw;
    const float* cw = z ? ck : cq;
    float scale = z ? 1.0f : QSCALE;
    int cg = h * HD + threadIdx.x;
    const float* w = cw + (size_t)cg * 4;
    float y = w[3] * raw[(size_t)row * KD + cg];
    if (l >= 1) y += w[2] * raw[(size_t)(row - 1) * KD + cg];
    if (l >= 2) y += w[1] * raw[(size_t)(row - 2) * KD + cg];
    if (l >= 3) y += w[0] * raw[(size_t)(row - 3) * KD + cg];
    y = y / (1.f + expf(-y));
    float tot = blockReduceSum256(y * y, red);
    float val = y * rsqrtf(tot + 1e-6f) * scale;
    size_t oidx = (size_t)row * KD + cg;
    if (z == 0) {
        qo[oidx] = val;
    } else {
        bf16 hi = __float2bfloat16(val);
        kh[oidx] = hi;
        kl[oidx] = __float2bfloat16(val - __bfloat162float(hi));
    }
}

#define PD 288
struct SBufE { float ke[PD]; float q[PD]; float v[64]; };

__global__ __launch_bounds__(256, 2) void scan_k(const float* __restrict__ keS,
                                                 const float* __restrict__ qn,
                                                 const float* __restrict__ vn,
                                                 const float* __restrict__ ba,
                                                 const float* __restrict__ A_log,
                                                 const float* __restrict__ dt_bias,
                                                 const int* __restrict__ modality,
                                                 const float* __restrict__ OW,
                                                 float* __restrict__ oEbuf) {
    __shared__ SBufE sb[2];
    __shared__ float sdec[L_];
    __shared__ float sbeta[L_];
    int bx = blockIdx.x, vt = bx & 7, h = (bx >> 3) & 7, b = (bx >> 6) & 1, e = bx >> 7;
    int tid = threadIdx.x, w = tid >> 5, lane = tid & 31;
    int g = lane >> 3, r = lane & 7;
    int colBase = vt * 64 + w * 8 + g * 2;
    int pdt = ((tid >> 5) * 36) + (tid & 31);
    int rb = r * 36;

    float w0 = OW[h], w1 = OW[8 + h], w2 = OW[16 + h];
    float mx = fmaxf(w0, fmaxf(w1, w2));
    float e0 = expf(w0 - mx), e1 = expf(w1 - mx), e2 = expf(w2 - mx);
    float wo = ((e == 0) ? e0 : (e == 1) ? e1 : e2) / (e0 + e1 + e2);

    int j = e * NH + h;
    float Ae = expf(A_log[j]), dtb_j = dt_bias[j];
    for (int idx = tid; idx < L_; idx += 256) {
        int row = b * L_ + idx;
        float av = ba[row * 48 + 24 + j] + dtb_j;
        float sp = (av > 20.f) ? av : log1pf(expf(av));
        float beta = 1.f / (1.f + expf(-ba[row * 48 + j]));
        int mo = modality[row];
        int m = (e == 0) ? 1 : ((e == 1) ? (mo == 0) : (mo == 1));
        sdec[idx] = m ? expf(-Ae * sp) : 1.f;
        sbeta[idx] = m ? beta : 0.f;
    }

    float2 S0[16], S1[16];
    #pragma unroll
    for (int jj = 0; jj < 16; jj++) { S0[jj] = make_float2(0.f, 0.f); S1[jj] = make_float2(0.f, 0.f); }

    const float* keE = keS + (size_t)e * BL * KD;
    float* oE = oEbuf + (size_t)e * BL * VD;

    float pk, pq, pv = 0.f;
    {
        size_t qoff = (size_t)(b * L_) * KD + h * HD;
        pk = keE[qoff + tid];
        pq = qn[qoff + tid];
        if (tid < 64) pv = vn[(size_t)(b * L_) * VD + h * DV + vt * 64 + tid];
    }

    for (int t = 0; t < L_; t++) {
        SBufE& sbuf = sb[t & 1];
        sbuf.ke[pdt] = pk;
        sbuf.q[pdt] = pq;
        if (tid < 64) sbuf.v[tid] = pv;
        __syncthreads();
        if (t + 1 < L_) {
            int row = b * L_ + t + 1;
            size_t qoff = (size_t)row * KD + h * HD;
            pk = keE[qoff + tid];
            pq = qn[qoff + tid];
            if (tid < 64) pv = vn[(size_t)row * VD + h * DV + vt * 64 + tid];
        }

        float dec = sdec[t], bb = sbeta[t];
        float o0, o1;
        if (bb != 0.f) {
            float vv0 = sbuf.v[w * 8 + g * 2];
            float vv1 = sbuf.v[w * 8 + g * 2 + 1];
            float2 dec2 = make_float2(dec, dec);
            float2 kS0 = {0,0}, kS1 = {0,0}, qS0 = {0,0}, qS1 = {0,0}, qk2 = {0,0};
            #pragma unroll
            for (int jj = 0; jj < 8; jj++) {
                float4 k4 = *reinterpret_cast<const float4*>(&sbuf.ke[rb + jj * 4]);
                float4 q4 = *reinterpret_cast<const float4*>(&sbuf.q[rb + jj * 4]);
                float2 ka = {k4.x, k4.y}, kb = {k4.z, k4.w};
                float2 qa = {q4.x, q4.y}, qb = {q4.z, q4.w};
                int jp = jj * 2;
                float2 s0 = fmul2(dec2, S0[jp]), s1 = fmul2(dec2, S1[jp]);
                kS0 = ffma2(ka, s0, kS0); kS1 = ffma2(ka, s1, kS1);
                qS0 = ffma2(qa, s0, qS0); qS1 = ffma2(qa, s1, qS1);
                qk2 = ffma2(qa, ka, qk2);
                S0[jp] = s0; S1[jp] = s1;
                float2 t0 = fmul2(dec2, S0[jp + 1]), t1 = fmul2(dec2, S1[jp + 1]);
                kS0 = ffma2(kb, t0, kS0); kS1 = ffma2(kb, t1, kS1);
                qS0 = ffma2(qb, t0, qS0); qS1 = ffma2(qb, t1, qS1);
                qk2 = ffma2(qb, kb, qk2);
                S0[jp + 1] = t0; S1[jp + 1] = t1;
            }
            float kS0s = kS0.x + kS0.y, kS1s = kS1.x + kS1.y;
            float qS0s = qS0.x + qS0.y, qS1s = qS1.x + qS1.y;
            float qks = qk2.x + qk2.y;
            #pragma unroll
            for (int off = 4; off; off >>= 1) {
                kS0s += __shfl_xor_sync(0xffffffffu, kS0s, off);
                kS1s += __shfl_xor_sync(0xffffffffu, kS1s, off);
                qS0s += __shfl_xor_sync(0xffffffffu, qS0s, off);
                qS1s += __shfl_xor_sync(0xffffffffu, qS1s, off);
                qks  += __shfl_xor_sync(0xffffffffu, qks,  off);
            }
            float d0 = (vv0 - kS0s) * bb;
            float d1 = (vv1 - kS1s) * bb;
            float2 d0d = make_float2(d0, d0), d1d = make_float2(d1, d1);
            #pragma unroll
            for (int jj = 0; jj < 8; jj++) {
                float4 k4 = *reinterpret_cast<const float4*>(&sbuf.ke[rb + jj * 4]);
                float2 ka = {k4.x, k4.y}, kb = {k4.z, k4.w};
                int jp = jj * 2;
                S0[jp] = ffma2(ka, d0d, S0[jp]);
                S1[jp] = ffma2(ka, d1d, S1[jp]);
                S0[jp + 1] = ffma2(kb, d0d, S0[jp + 1]);
                S1[jp + 1] = ffma2(kb, d1d, S1[jp + 1]);
            }
            o0 = wo * (qS0s + qks * d0);
            o1 = wo * (qS1s + qks * d1);
        } else {
            float2 qS0 = {0,0}, qS1 = {0,0};
            #pragma unroll
            for (int jj = 0; jj < 8; jj++) {
                float4 q4 = *reinterpret_cast<const float4*>(&sbuf.q[rb + jj * 4]);
                float2 qa = {q4.x, q4.y}, qb = {q4.z, q4.w};
                int jp = jj * 2;
                qS0 = ffma2(qa, S0[jp], qS0); qS1 = ffma2(qa, S1[jp], qS1);
                qS0 = ffma2(qb, S0[jp + 1], qS0); qS1 = ffma2(qb, S1[jp + 1], qS1);
            }
            float qS0s = qS0.x + qS0.y, qS1s = qS1.x + qS1.y;
            #pragma unroll
            for (int off = 4; off; off >>= 1) {
                qS0s += __shfl_xor_sync(0xffffffffu, qS0s, off);
                qS1s += __shfl_xor_sync(0xffffffffu, qS1s, off);
            }
            o0 = wo * qS0s;
            o1 = wo * qS1s;
        }
        if (r == 0) {
            int row = b * L_ + t;
            *reinterpret_cast<float2*>(&oE[(size_t)row * VD + h * DV + colBase]) = make_float2(o0, o1);
        }
    }
}

__global__ __launch_bounds__(256) void normgate_k(const float* __restrict__ oEbuf,
                                                  const float* __restrict__ gateRaw,
                                                  const float* __restrict__ onw,
                                                  bf16* __restrict__ oFh,
                                                  bf16* __restrict__ oFl) {
    __shared__ float red[8];
    int row = blockIdx.x >> 3, h = blockIdx.x & 7, tid = threadIdx.x;
    size_t base = (size_t)row * VD + h * DV;
    const float* o0p = oEbuf;
    const float* o1p = oEbuf + (size_t)BL * VD;
    const float* o2p = oEbuf + (size_t)2 * BL * VD;
    float x0 = o0p[base + tid] + o1p[base + tid] + o2p[base + tid];
    float x1 = o0p[base + tid + 256] + o1p[base + tid + 256] + o2p[base + tid + 256];
    float tot = blockReduceSum256(x0 * x0 + x1 * x1, red);
    float rn = rsqrtf(tot * (1.f / 512.f) + 1e-5f);
    float g0 = gateRaw[base + tid];
    float g1 = gateRaw[base + tid + 256];
    float v0 = x0 * rn * onw[tid]       * (g0 / (1.f + expf(-g0)));
    float v1 = x1 * rn * onw[tid + 256] * (g1 / (1.f + expf(-g1)));
    bf16 h0 = __float2bfloat16(v0), h1 = __float2bfloat16(v1);
    oFh[base + tid] = h0;
    oFl[base + tid] = __float2bfloat16(v0 - __bfloat162float(h0));
    oFh[base + tid + 256] = h1;
    oFl[base + tid + 256] = __float2bfloat16(v1 - __bfloat162float(h1));
}

extern "C" void kernel_launch(void* const* d_in, const int* in_sizes, int n_in,
                              void* d_out, int out_size) {
    const float *x, *Wq, *Wk, *Wv, *cq, *ck, *cv, *Wek, *Wb, *Wa, *Alog, *dtb, *ow, *Wg, *onw, *Wo;
    const int* mod;
    if (in_sizes[1] == 2048) {
        x = (const float*)d_in[0];  mod = (const int*)d_in[1];
        Wq = (const float*)d_in[2]; Wk = (const float*)d_in[3];
        Wv = (const float*)d_in[4]; cq = (const float*)d_in[5];
        ck = (const float*)d_in[6]; cv = (const float*)d_in[7];
        Wek = (const float*)d_in[8]; Wb = (const float*)d_in[9];
        Wa = (const float*)d_in[10]; Alog = (const float*)d_in[11];
        dtb = (const float*)d_in[12]; ow = (const float*)d_in[13];
        Wg = (const float*)d_in[14]; onw = (const float*)d_in[15];
        Wo = (const float*)d_in[16];
    } else {
        x = (const float*)d_in[0];  Wq = (const float*)d_in[1];
        Wk = (const float*)d_in[2]; Wv = (const float*)d_in[3];
        cq = (const float*)d_in[4]; ck = (const float*)d_in[5];
        cv = (const float*)d_in[6]; Wek = (const float*)d_in[7];
        Wb = (const float*)d_in[8]; Wa = (const float*)d_in[9];
        Alog = (const float*)d_in[10]; dtb = (const float*)d_in[11];
        ow = (const float*)d_in[12]; Wg = (const float*)d_in[13];
        onw = (const float*)d_in[14]; Wo = (const float*)d_in[15];
        mod = (const int*)d_in[16];
    }

    float *qraw, *kraw, *vraw, *gateraw, *q, *v, *ke, *ba, *oE;
    bf16 *xh, *xl, *Wqh, *Wql, *Wkh, *Wkl, *Wvh, *Wvl, *Wgh, *Wgl, *Woh, *Wol;
    bf16 *kh, *kl, *Wekh, *Wekl, *ofh, *ofl;
    cudaGetSymbolAddress((void**)&qraw, g_qraw);
    cudaGetSymbolAddress((void**)&kraw, g_kraw);
    cudaGetSymbolAddress((void**)&vraw, g_vraw);
    cudaGetSymbolAddress((void**)&gateraw, g_gateraw);
    cudaGetSymbolAddress((void**)&q, g_q);
    cudaGetSymbolAddress((void**)&v, g_v);
    cudaGetSymbolAddress((void**)&ke, g_ke);
    cudaGetSymbolAddress((void**)&ba, g_ba);
    cudaGetSymbolAddress((void**)&oE, g_oE);
    cudaGetSymbolAddress((void**)&xh, g_xh);   cudaGetSymbolAddress((void**)&xl, g_xl);
    cudaGetSymbolAddress((void**)&Wqh, g_Wqh); cudaGetSymbolAddress((void**)&Wql, g_Wql);
    cudaGetSymbolAddress((void**)&Wkh, g_Wkh); cudaGetSymbolAddress((void**)&Wkl, g_Wkl);
    cudaGetSymbolAddress((void**)&Wvh, g_Wvh); cudaGetSymbolAddress((void**)&Wvl, g_Wvl);
    cudaGetSymbolAddress((void**)&Wgh, g_Wgh); cudaGetSymbolAddress((void**)&Wgl, g_Wgl);
    cudaGetSymbolAddress((void**)&Woh, g_Woh); cudaGetSymbolAddress((void**)&Wol, g_Wol);
    cudaGetSymbolAddress((void**)&kh, g_kh);   cudaGetSymbolAddress((void**)&kl, g_kl);
    cudaGetSymbolAddress((void**)&Wekh, g_Wekh); cudaGetSymbolAddress((void**)&Wekl, g_Wekl);
    cudaGetSymbolAddress((void**)&ofh, g_ofh); cudaGetSymbolAddress((void**)&ofl, g_ofl);

    cudaFuncSetAttribute(mma_gemm_nt, cudaFuncAttributeMaxDynamicSharedMemorySize, SMEM_DYN);
    cudaFuncSetAttribute(mma_wg_ba,  cudaFuncAttributeMaxDynamicSharedMemorySize, SMEM_DYN);
    cudaFuncSetAttribute(mma_ke,     cudaFuncAttributeMaxDynamicSharedMemorySize, SMEM_DYN);

    cvt_split<<<(BL * HS / 4 + 255) / 256, 256>>>(x, xh, xl, BL * HS / 4);
    cvt_split<<<(KD * HS / 4 + 255) / 256, 256>>>(Wq, Wqh, Wql, KD * HS / 4);
    cvt_split<<<(KD * HS / 4 + 255) / 256, 256>>>(Wk, Wkh, Wkl, KD * HS / 4);
    mma_gemm_nt<<<dim3(32, 16), 256, SMEM_DYN>>>(xh, xl, Wqh, Wql, qraw, HS, HS, HS, KD);  // slot 3 -> profiled
    cvt_split<<<(VD * HS / 4 + 255) / 256, 256>>>(Wv, Wvh, Wvl, VD * HS / 4);
    cvt_split<<<(VD * HS / 4 + 255) / 256, 256>>>(Wg, Wgh, Wgl, VD * HS / 4);
    mma_gemm_nt<<<dim3(32, 16), 256, SMEM_DYN>>>(xh, xl, Wkh, Wkl, kraw, HS, HS, HS, KD);
    mma_gemm_nt<<<dim3(64, 16), 256, SMEM_DYN>>>(xh, xl, Wvh, Wvl, vraw, HS, HS, HS, VD);
    mma_wg_ba<<<dim3(66, 16), 256, SMEM_DYN>>>(xh, xl, Wgh, Wgl, x, Wb, Wa, gateraw, ba);
    conv_all<<<dim3(BL, NH, 3), 256>>>(qraw, kraw, vraw, cq, ck, cv, q, kh, kl, v);
    cvt_split<<<(E_ * NH * HD * HD / 4 + 255) / 256, 256>>>(Wek, Wekh, Wekl, E_ * NH * HD * HD / 4);
    mma_ke<<<dim3(4, 16, 24), 256, SMEM_DYN>>>(kh, kl, Wekh, Wekl, ke);
    scan_k<<<384, 256>>>(ke, q, v, ba, Alog, dtb, mod, ow, oE);
    normgate_k<<<BL * NH, 256>>>(oE, gateraw, onw, ofh, ofl);
    cvt_split<<<(HS * VD / 4 + 255) / 256, 256>>>(Wo, Woh, Wol, HS * VD / 4);
    mma_gemm_nt<<<dim3(32, 16), 256, SMEM_DYN>>>(ofh, ofl, Woh, Wol, (float*)d_out, VD, VD, VD, HS);
}